// round 4
// baseline (speedup 1.0000x reference)
#include <cuda_runtime.h>
#include <math.h>

#define D     128
#define Mn    128
#define KTAB  64
#define KSEL  32
#define Bq    2048
#define FEW   5
#define DM    256
#define HID   512
#define GATES 2048
#define NTASK (2 * Bq + 2 * FEW)   // 4106
#define TPAD  4160                 // padded task rows for GEMM

typedef unsigned long long ull;

// ---------------- scratch (device globals; no allocation) ----------------
__device__ __align__(128) float g_hs[TPAD * DM];     // [rel_avg | ent_avg]
__device__ __align__(128) float g_hk[TPAD * D];      // knn ent avg
__device__ __align__(128) float g_c1[TPAD * D];      // struct pre-activation
__device__ __align__(128) float g_c2[TPAD * D];      // knn pre-activation
__device__ __align__(128) float g_qn[Bq * DM];
__device__ __align__(128) float g_sn[FEW * DM];
__device__ __align__(128) float g_sh[FEW * HID];
__device__ __align__(128) float g_sz[FEW * DM];
__device__ __align__(128) float g_act[Bq * HID];
__device__ __align__(128) float g_qg[Bq * DM];
__device__ __align__(128) float g_sg[DM];
__device__ __align__(128) float g_sgn[DM];
__device__ __align__(128) float g_vr[GATES];
__device__ __align__(128) float g_qp[(size_t)Bq * GATES];
__device__ __align__(128) float g_cst[Bq * HID];
__device__ __align__(128) float g_ha[Bq * DM];
__device__ __align__(128) float g_hb[Bq * DM];

__device__ __forceinline__ float wred(float v) {
#pragma unroll
    for (int o = 16; o; o >>= 1) v += __shfl_xor_sync(0xffffffffu, v, o);
    return v;
}
__device__ __forceinline__ float sigmf(float x) { return 1.f / (1.f + expf(-x)); }

__device__ __forceinline__ ull pack2(float x) {
    ull r;
    asm("mov.b64 %0, {%1, %1};" : "=l"(r) : "r"(__float_as_uint(x)));
    return r;
}
__device__ __forceinline__ void dfma(ull& d, ull a, ull b) {
    asm("fma.rn.f32x2 %0, %1, %2, %0;" : "+l"(d) : "l"(a), "l"(b));
}
__device__ __forceinline__ float2 unpack2(ull v) {
    unsigned lo, hi;
    asm("mov.b64 {%0, %1}, %2;" : "=r"(lo), "=r"(hi) : "l"(v));
    float2 f; f.x = __uint_as_float(lo); f.y = __uint_as_float(hi);
    return f;
}
__device__ __forceinline__ int permg(int n) { return (n & 3) * 512 + (n >> 2); }

// ---------------- neighbor gather: sims + topk + selected means ----------------
__global__ __launch_bounds__(256) void neigh_gather(
    const int* __restrict__ query, const int* __restrict__ support,
    const int* __restrict__ qlc, const int* __restrict__ qrc,
    const int* __restrict__ slc, const int* __restrict__ src_,
    const int* __restrict__ knn, const float* __restrict__ emb)
{
    __shared__ float s_center[D];
    __shared__ int   s_rid[Mn], s_eid[Mn];
    __shared__ float s_sim[Mn];
    __shared__ int   s_kid[KTAB];
    __shared__ float s_ksim[KTAB];
    __shared__ int   s_selr[KSEL], s_sele[KSEL], s_kselv[KSEL];
    __shared__ int   s_cnt, s_kcnt;
    __shared__ float s_cn;

    int task = blockIdx.x;
    const int* conn; int id;
    if (task < 2 * Bq) {
        int row = task & (Bq - 1);
        int br  = task >> 11;
        conn = (br ? qrc : qlc) + (size_t)row * Mn * 2;
        id   = query[row * 2 + br];
    } else {
        int t = task - 2 * Bq;
        int br = t / FEW, row = t % FEW;
        conn = (br ? src_ : slc) + (size_t)row * Mn * 2;
        id   = support[row * 2 + br];
    }
    int tid = threadIdx.x, lane = tid & 31, wid = tid >> 5;
    if (tid == 0) { s_cnt = 0; s_kcnt = 0; }
    if (tid < D)  s_center[tid] = emb[(size_t)id * D + tid];
    if (tid < Mn) { s_rid[tid] = conn[tid * 2]; s_eid[tid] = conn[tid * 2 + 1]; }
    if (tid >= 192) s_kid[tid - 192] = knn[(size_t)id * KTAB + (tid - 192)];
    __syncthreads();

    if (wid == 0) {
        float c0 = s_center[lane], c1 = s_center[lane + 32],
              c2 = s_center[lane + 64], c3 = s_center[lane + 96];
        float s = wred(c0 * c0 + c1 * c1 + c2 * c2 + c3 * c3);
        if (lane == 0) s_cn = sqrtf(s);
    }
    __syncthreads();
    float cn = s_cn;
    float4 cv = ((const float4*)s_center)[lane];

    // ent sims: warp handles 16 m, groups of 4 with interleaved reductions
#pragma unroll
    for (int g = 0; g < 4; g++) {
        int m = wid * 16 + g * 4;
        float dt[4], nn[4];
#pragma unroll
        for (int t = 0; t < 4; t++) {
            float4 ev = ((const float4*)(emb + (size_t)s_eid[m + t] * D))[lane];
            dt[t] = ev.x * cv.x + ev.y * cv.y + ev.z * cv.z + ev.w * cv.w;
            nn[t] = ev.x * ev.x + ev.y * ev.y + ev.z * ev.z + ev.w * ev.w;
        }
#pragma unroll
        for (int o = 16; o; o >>= 1) {
#pragma unroll
            for (int t = 0; t < 4; t++) {
                dt[t] += __shfl_xor_sync(0xffffffffu, dt[t], o);
                nn[t] += __shfl_xor_sync(0xffffffffu, nn[t], o);
            }
        }
        if (lane == 0) {
#pragma unroll
            for (int t = 0; t < 4; t++)
                s_sim[m + t] = dt[t] / fmaxf(cn * sqrtf(nn[t]), 1e-8f);
        }
    }
    // knn sims: warp handles 8
#pragma unroll
    for (int g = 0; g < 2; g++) {
        int m = wid * 8 + g * 4;
        float dt[4], nn[4];
#pragma unroll
        for (int t = 0; t < 4; t++) {
            float4 ev = ((const float4*)(emb + (size_t)s_kid[m + t] * D))[lane];
            dt[t] = ev.x * cv.x + ev.y * cv.y + ev.z * cv.z + ev.w * cv.w;
            nn[t] = ev.x * ev.x + ev.y * ev.y + ev.z * ev.z + ev.w * ev.w;
        }
#pragma unroll
        for (int o = 16; o; o >>= 1) {
#pragma unroll
            for (int t = 0; t < 4; t++) {
                dt[t] += __shfl_xor_sync(0xffffffffu, dt[t], o);
                nn[t] += __shfl_xor_sync(0xffffffffu, nn[t], o);
            }
        }
        if (lane == 0) {
#pragma unroll
            for (int t = 0; t < 4; t++)
                s_ksim[m + t] = dt[t] / fmaxf(cn * sqrtf(nn[t]), 1e-8f);
        }
    }
    __syncthreads();

    // exact top-K sets (jax tie semantics: lower index wins) + compaction
    if (tid < Mn) {
        float v = s_sim[tid]; int r = 0;
        for (int j = 0; j < Mn; j++) {
            float u = s_sim[j];
            r += (u > v) || (u == v && j < tid);
        }
        if (r < KSEL) {
            int p = atomicAdd(&s_cnt, 1);
            s_selr[p] = s_rid[tid];
            s_sele[p] = s_eid[tid];
        }
    } else if (tid < Mn + KTAB) {
        int m = tid - Mn;
        float v = s_ksim[m]; int r = 0;
        for (int j = 0; j < KTAB; j++) {
            float u = s_ksim[j];
            r += (u > v) || (u == v && j < m);
        }
        if (r < KSEL) {
            int p = atomicAdd(&s_kcnt, 1);
            s_kselv[p] = s_kid[m];
        }
    }
    __syncthreads();

    // means of selected rows (unrolled, full MLP)
    int d = tid & (D - 1);
    float acc = 0.f;
    if (tid < D) {
#pragma unroll 8
        for (int i = 0; i < KSEL; i++) acc += emb[(size_t)s_selr[i] * D + d];
        g_hs[(size_t)task * DM + d] = acc * (1.f / KSEL);
        float ak = 0.f;
#pragma unroll 8
        for (int i = 0; i < KSEL; i++) ak += emb[(size_t)s_kselv[i] * D + d];
        g_hk[(size_t)task * D + d] = ak * (1.f / KSEL);
    } else {
#pragma unroll 8
        for (int i = 0; i < KSEL; i++) acc += emb[(size_t)s_sele[i] * D + d];
        g_hs[(size_t)task * DM + D + d] = acc * (1.f / KSEL);
    }
}

// ---------------- combine: tanh + gate + scatter to qn/sn ----------------
__global__ __launch_bounds__(256) void combine_kernel(
    const float* __restrict__ gcn_w_b, const float* __restrict__ gcn_b,
    const float* __restrict__ gate_w, const float* __restrict__ gate_b)
{
    int lane = threadIdx.x & 31, wid = threadIdx.x >> 5;
    int t = blockIdx.x * 8 + wid;
    if (t >= NTASK) return;
    int c = lane * 4;
    float4 c1 = *(const float4*)(g_c1 + (size_t)t * D + c);
    float4 c2 = *(const float4*)(g_c2 + (size_t)t * D + c);
    float4 wb = *(const float4*)(gcn_w_b + c);
    float4 gb = *(const float4*)(gcn_b + c);
    float s0 = tanhf(c1.x + wb.x + gb.x), s1 = tanhf(c1.y + wb.y + gb.y);
    float s2 = tanhf(c1.z + wb.z + gb.z), s3 = tanhf(c1.w + wb.w + gb.w);
    float k0 = tanhf(c2.x + wb.x + gb.x), k1 = tanhf(c2.y + wb.y + gb.y);
    float k2 = tanhf(c2.z + wb.z + gb.z), k3 = tanhf(c2.w + wb.w + gb.w);
    float4 gws = *(const float4*)(gate_w + c);
    float4 gwk = *(const float4*)(gate_w + D + c);
    float a = gws.x * s0 + gws.y * s1 + gws.z * s2 + gws.w * s3
            + gwk.x * k0 + gwk.y * k1 + gwk.z * k2 + gwk.w * k3;
    a = wred(a);
    float al = sigmf(a + gate_b[0]);
    float4 o;
    o.x = (1.f - al) * s0 + al * k0;
    o.y = (1.f - al) * s1 + al * k1;
    o.z = (1.f - al) * s2 + al * k2;
    o.w = (1.f - al) * s3 + al * k3;
    float* dst;
    if (t < Bq)            dst = g_qn + (size_t)t * DM + c;
    else if (t < 2 * Bq)   dst = g_qn + (size_t)(t - Bq) * DM + D + c;
    else if (t < 2 * Bq + FEW) dst = g_sn + (size_t)(t - 2 * Bq) * DM + c;
    else                   dst = g_sn + (size_t)(t - 2 * Bq - FEW) * DM + D + c;
    *(float4*)dst = o;
}

// ---------------- templated FFMA2 SGEMM: C[M,N] = A[M,K] · B[N,K]ᵀ ----------------
template<int BM, int MODE>
__global__ __launch_bounds__(256) void sgemm(
    const float* __restrict__ A, int lda,
    const float* __restrict__ B, int ldb,
    float* __restrict__ C, int N, int K,
    const float* __restrict__ bias0,
    const float* __restrict__ addmat,
    float* __restrict__ qp, const float* __restrict__ vr,
    const float* __restrict__ bih, const float* __restrict__ bhh,
    float* __restrict__ cst, const float* __restrict__ qg,
    float* __restrict__ hout,
    const float* __restrict__ A2, int lda2,
    const float* __restrict__ B2, int K2, float* __restrict__ C2)
{
    if (MODE == 4 && blockIdx.z == 1) { A = A2; lda = lda2; B = B2; K = K2; C = C2; }
    constexpr int TM = BM / 16;
    __shared__ float As[16][BM + 4];
    __shared__ float Bs[16][132];
    int tid = threadIdx.x;
    int bm = blockIdx.y * BM, bn = blockIdx.x * 128;
    int tm = (tid >> 4) * TM, tn = (tid & 15) * 8;
    int ar = tid >> 2, ac = (tid & 3) * 4;

    int br0 = bn + ar, br1 = bn + ar + 64;
    if (MODE == 2 || MODE == 3) { br0 = permg(br0); br1 = permg(br1); }
    const float* Ap  = A + (size_t)(bm + ar) * lda + ac;
    const float* Bp0 = B + (size_t)br0 * ldb + ac;
    const float* Bp1 = B + (size_t)br1 * ldb + ac;

    ull acc2[TM][4];
#pragma unroll
    for (int i = 0; i < TM; i++)
#pragma unroll
        for (int j = 0; j < 4; j++) acc2[i][j] = 0ULL;

    for (int k0 = 0; k0 < K; k0 += 16) {
        float4 a0 = *(const float4*)(Ap + k0);
        float4 a1;
        if (BM == 128) a1 = *(const float4*)(Ap + (size_t)64 * lda + k0);
        float4 b0 = *(const float4*)(Bp0 + k0);
        float4 b1 = *(const float4*)(Bp1 + k0);
        __syncthreads();
        As[ac + 0][ar] = a0.x; As[ac + 1][ar] = a0.y; As[ac + 2][ar] = a0.z; As[ac + 3][ar] = a0.w;
        if (BM == 128) {
            As[ac + 0][ar + 64] = a1.x; As[ac + 1][ar + 64] = a1.y;
            As[ac + 2][ar + 64] = a1.z; As[ac + 3][ar + 64] = a1.w;
        }
        Bs[ac + 0][ar] = b0.x; Bs[ac + 1][ar] = b0.y; Bs[ac + 2][ar] = b0.z; Bs[ac + 3][ar] = b0.w;
        Bs[ac + 0][ar + 64] = b1.x; Bs[ac + 1][ar + 64] = b1.y;
        Bs[ac + 2][ar + 64] = b1.z; Bs[ac + 3][ar + 64] = b1.w;
        __syncthreads();
#pragma unroll
        for (int kk = 0; kk < 16; kk++) {
            float av[TM];
            *(float4*)av = *(const float4*)&As[kk][tm];
            if (TM == 8) *(float4*)(av + 4) = *(const float4*)&As[kk][tm + 4];
            ulonglong2 p01 = *(const ulonglong2*)&Bs[kk][tn];
            ulonglong2 p23 = *(const ulonglong2*)&Bs[kk][tn + 4];
            ull bd0 = p01.x, bd1 = p01.y, bd2 = p23.x, bd3 = p23.y;
#pragma unroll
            for (int i = 0; i < TM; i++) {
                ull ap = pack2(av[i]);
                dfma(acc2[i][0], ap, bd0);
                dfma(acc2[i][1], ap, bd1);
                dfma(acc2[i][2], ap, bd2);
                dfma(acc2[i][3], ap, bd3);
            }
        }
    }

    int nb = bn + tn;
    float colA[8];
    if (MODE == 0 || MODE == 1) {
#pragma unroll
        for (int j = 0; j < 8; j++) colA[j] = bias0[nb + j];
    } else if (MODE == 2) {
#pragma unroll
        for (int j = 0; j < 8; j++) { int p = permg(nb + j); colA[j] = bih[p] + bhh[p]; }
    } else if (MODE == 3) {
#pragma unroll
        for (int j = 0; j < 8; j++) colA[j] = vr[nb + j];
    }

#pragma unroll
    for (int i = 0; i < TM; i++) {
        size_t m = (size_t)(bm + tm + i);
        float v[8];
#pragma unroll
        for (int jp = 0; jp < 4; jp++) {
            float2 f = unpack2(acc2[i][jp]);
            v[2 * jp] = f.x; v[2 * jp + 1] = f.y;
        }
        if (MODE == 0) {
#pragma unroll
            for (int j = 0; j < 8; j++) v[j] = fmaxf(v[j] + colA[j], 0.f);
            float4* cp = (float4*)(C + m * N + nb);
            cp[0] = make_float4(v[0], v[1], v[2], v[3]);
            cp[1] = make_float4(v[4], v[5], v[6], v[7]);
        } else if (MODE == 1) {
            const float4* am = (const float4*)(addmat + m * N + nb);
            float4 m0 = am[0], m1 = am[1];
            v[0] += colA[0] + m0.x; v[1] += colA[1] + m0.y;
            v[2] += colA[2] + m0.z; v[3] += colA[3] + m0.w;
            v[4] += colA[4] + m1.x; v[5] += colA[5] + m1.y;
            v[6] += colA[6] + m1.z; v[7] += colA[7] + m1.w;
            float4* cp = (float4*)(C + m * N + nb);
            cp[0] = make_float4(v[0], v[1], v[2], v[3]);
            cp[1] = make_float4(v[4], v[5], v[6], v[7]);
        } else if (MODE == 4) {
            float4* cp = (float4*)(C + m * N + nb);
            cp[0] = make_float4(v[0], v[1], v[2], v[3]);
            cp[1] = make_float4(v[4], v[5], v[6], v[7]);
        } else if (MODE == 2) {
#pragma unroll
            for (int j = 0; j < 8; j++) { v[j] += colA[j]; qp[m * GATES + nb + j] = v[j]; }
#pragma unroll
            for (int h = 0; h < 2; h++) {
                int u = (nb >> 2) + h;
                const float* vv = v + h * 4;
                float cc = sigmf(vv[0]) * tanhf(vv[2]);
                cst[m * HID + u] = cc;
                if (nb < 1024)
                    hout[m * DM + u] = qg[m * DM + u] + sigmf(vv[3]) * tanhf(cc);
            }
        } else if (MODE == 3) {
            const float4* qm = (const float4*)(qp + m * GATES + nb);
            float4 q0 = qm[0], q1 = qm[1];
            v[0] += colA[0] + q0.x; v[1] += colA[1] + q0.y;
            v[2] += colA[2] + q0.z; v[3] += colA[3] + q0.w;
            v[4] += colA[4] + q1.x; v[5] += colA[5] + q1.y;
            v[6] += colA[6] + q1.z; v[7] += colA[7] + q1.w;
#pragma unroll
            for (int h = 0; h < 2; h++) {
                int u = (nb >> 2) + h;
                const float* vv = v + h * 4;
                float co = cst[m * HID + u];
                float cc = sigmf(vv[1]) * co + sigmf(vv[0]) * tanhf(vv[2]);
                cst[m * HID + u] = cc;
                if (nb < 1024)
                    hout[m * DM + u] = qg[m * DM + u] + sigmf(vv[3]) * tanhf(cc);
            }
        }
    }
}

// ---------------- support encoder, parallel ----------------
// p1: 2560 warp-dots (5 rows × 512 units)
__global__ __launch_bounds__(256) void sup1_kernel(
    const float* __restrict__ p1_w, const float* __restrict__ p1_b)
{
    int lane = threadIdx.x & 31, wid = threadIdx.x >> 5;
    int w = blockIdx.x * 8 + wid;
    int r = w >> 9, u = w & (HID - 1);
    const float* wp = p1_w + (size_t)u * DM;
    const float* xp = g_sn + r * DM;
    float a = 0.f;
#pragma unroll
    for (int s = 0; s < 8; s++) a += wp[lane + 32 * s] * xp[lane + 32 * s];
    a = wred(a);
    if (lane == 0) g_sh[r * HID + u] = fmaxf(a + p1_b[u], 0.f);
}

// p2: 1280 warp-dots (5 rows × 256 units), + bias + residual
__global__ __launch_bounds__(256) void sup2_kernel(
    const float* __restrict__ p2_w, const float* __restrict__ p2_b)
{
    int lane = threadIdx.x & 31, wid = threadIdx.x >> 5;
    int w = blockIdx.x * 8 + wid;
    int r = w >> 8, u = w & (DM - 1);
    const float* wp = p2_w + (size_t)u * HID;
    const float* xp = g_sh + r * HID;
    float a = 0.f;
#pragma unroll
    for (int s = 0; s < 16; s++) a += wp[lane + 32 * s] * xp[lane + 32 * s];
    a = wred(a);
    if (lane == 0) g_sz[r * DM + u] = a + p2_b[u] + g_sn[r * DM + u];
}

// LN over 5 rows + mean + normalize (tiny)
__global__ __launch_bounds__(256) void sup3_kernel(
    const float* __restrict__ ln_g, const float* __restrict__ ln_b)
{
    __shared__ float red[8];
    int tid = threadIdx.x, lane = tid & 31, wid = tid >> 5;
    float accg = 0.f;
    for (int r = 0; r < FEW; r++) {
        float z = g_sz[r * DM + tid];
        float s1 = wred(z);
        if (lane == 0) red[wid] = s1;
        __syncthreads();
        float mu = (red[0] + red[1] + red[2] + red[3] + red[4] + red[5] + red[6] + red[7]) * (1.f / DM);
        __syncthreads();
        float dz = z - mu;
        float s2 = wred(dz * dz);
        if (lane == 0) red[wid] = s2;
        __syncthreads();
        float sig = sqrtf((red[0] + red[1] + red[2] + red[3] + red[4] + red[5] + red[6] + red[7]) * (1.f / (DM - 1)));
        accg += dz / (sig + 1e-3f) * ln_g[tid] + ln_b[tid];
        __syncthreads();
    }
    float sg = accg * (1.f / FEW);
    g_sg[tid] = sg;
    float s3 = wred(sg * sg);
    if (lane == 0) red[wid] = s3;
    __syncthreads();
    float nrm = sqrtf(red[0] + red[1] + red[2] + red[3] + red[4] + red[5] + red[6] + red[7]);
    g_sgn[tid] = sg / fmaxf(nrm, 1e-12f);
}

// v_r permuted: g_vr[n] = support_g · w_hh[perm(n), 256:512]
__global__ __launch_bounds__(256) void vr_kernel(const float* __restrict__ w_hh) {
    int lane = threadIdx.x & 31, wid = threadIdx.x >> 5;
    int g = blockIdx.x * 8 + wid;
    int p = permg(g);
    const float* w = w_hh + (size_t)p * HID + DM;
    float a = 0.f;
#pragma unroll
    for (int s = 0; s < 8; s++) a += w[lane + 32 * s] * g_sg[lane + 32 * s];
    a = wred(a);
    if (lane == 0) g_vr[g] = a;
}

// layernorm over g_qg rows, in place
__global__ __launch_bounds__(256) void ln_kernel(const float* __restrict__ ln_g,
                                                 const float* __restrict__ ln_b) {
    __shared__ float red[8];
    int row = blockIdx.x, tid = threadIdx.x, lane = tid & 31, wid = tid >> 5;
    float z = g_qg[(size_t)row * DM + tid];
    float s1 = wred(z);
    if (lane == 0) red[wid] = s1;
    __syncthreads();
    float mu = (red[0] + red[1] + red[2] + red[3] + red[4] + red[5] + red[6] + red[7]) * (1.f / DM);
    __syncthreads();
    float dz = z - mu;
    float s2 = wred(dz * dz);
    if (lane == 0) red[wid] = s2;
    __syncthreads();
    float sig = sqrtf((red[0] + red[1] + red[2] + red[3] + red[4] + red[5] + red[6] + red[7]) * (1.f / (DM - 1)));
    g_qg[(size_t)row * DM + tid] = dz / (sig + 1e-3f) * ln_g[tid] + ln_b[tid];
}

// out[row] = (h / max(||h||,1e-12)) · sg_normalized
__global__ __launch_bounds__(256) void final_kernel(float* __restrict__ out) {
    int lane = threadIdx.x & 31, wid = threadIdx.x >> 5;
    int row = blockIdx.x * 8 + wid;
    const float* h = g_hb + (size_t)row * DM;
    float ss = 0.f, dt = 0.f;
#pragma unroll
    for (int s = 0; s < 8; s++) {
        float v = h[lane + 32 * s];
        ss += v * v;
        dt += v * g_sgn[lane + 32 * s];
    }
    ss = wred(ss); dt = wred(dt);
    if (lane == 0) out[row] = dt / fmaxf(sqrtf(ss), 1e-12f);
}

// ---------------- host ----------------
extern "C" void kernel_launch(void* const* d_in, const int* in_sizes, int n_in,
                              void* d_out, int out_size) {
    const int*   query   = (const int*)d_in[0];
    const int*   support = (const int*)d_in[1];
    const int*   qlc     = (const int*)d_in[2];
    const int*   qrc     = (const int*)d_in[4];
    const int*   slc     = (const int*)d_in[6];
    const int*   src_    = (const int*)d_in[8];
    const int*   knn     = (const int*)d_in[10];
    const float* emb     = (const float*)d_in[11];
    const float* gcn_w   = (const float*)d_in[12];
    const float* gcn_w_b = (const float*)d_in[13];
    const float* gcn_b   = (const float*)d_in[14];
    const float* gate_w  = (const float*)d_in[15];
    const float* gate_b  = (const float*)d_in[16];
    const float* p1_w    = (const float*)d_in[17];
    const float* p1_b    = (const float*)d_in[18];
    const float* p2_w    = (const float*)d_in[19];
    const float* p2_b    = (const float*)d_in[20];
    const float* ln_g    = (const float*)d_in[21];
    const float* ln_b    = (const float*)d_in[22];
    const float* w_ih    = (const float*)d_in[23];
    const float* w_hh    = (const float*)d_in[24];
    const float* b_ih    = (const float*)d_in[25];
    const float* b_hh    = (const float*)d_in[26];
    float* out = (float*)d_out;

    float *hs, *hk, *c1, *c2, *qn, *act, *qg, *vr, *qp, *cst, *ha, *hb;
    cudaGetSymbolAddress((void**)&hs, g_hs);
    cudaGetSymbolAddress((void**)&hk, g_hk);
    cudaGetSymbolAddress((void**)&c1, g_c1);
    cudaGetSymbolAddress((void**)&c2, g_c2);
    cudaGetSymbolAddress((void**)&qn, g_qn);
    cudaGetSymbolAddress((void**)&act, g_act);
    cudaGetSymbolAddress((void**)&qg, g_qg);
    cudaGetSymbolAddress((void**)&vr, g_vr);
    cudaGetSymbolAddress((void**)&qp, g_qp);
    cudaGetSymbolAddress((void**)&cst, g_cst);
    cudaGetSymbolAddress((void**)&ha, g_ha);
    cudaGetSymbolAddress((void**)&hb, g_hb);

    // 1) gather + topk means
    neigh_gather<<<NTASK, 256>>>(query, support, qlc, qrc, slc, src_, knn, emb);
    // 2) dual GCN GEMM: c1 = hs @ gcn_wᵀ ; c2 = hk @ gcn_w[:,128:]ᵀ
    sgemm<64, 4><<<dim3(1, TPAD / 64, 2), 256>>>(
        hs, DM, gcn_w, DM, c1, D, DM,
        nullptr, nullptr, nullptr, nullptr, nullptr, nullptr, nullptr, nullptr, nullptr,
        hk, D, gcn_w + D, D, c2);
    // 3) tanh + gate + scatter
    combine_kernel<<<(NTASK + 7) / 8, 256>>>(gcn_w_b, gcn_b, gate_w, gate_b);
    // 4) support path (parallel)
    sup1_kernel<<<FEW * HID / 8, 256>>>(p1_w, p1_b);
    sup2_kernel<<<FEW * DM / 8, 256>>>(p2_w, p2_b);
    sup3_kernel<<<1, 256>>>(ln_g, ln_b);
    vr_kernel<<<GATES / 8, 256>>>(w_hh);
    // 5) query support-encoder
    sgemm<64, 0><<<dim3(HID / 128, Bq / 64), 256>>>(
        qn, DM, p1_w, DM, act, HID, DM, p1_b,
        nullptr, nullptr, nullptr, nullptr, nullptr, nullptr, nullptr, nullptr,
        nullptr, 0, nullptr, 0, nullptr);
    sgemm<64, 1><<<dim3(DM / 128, Bq / 64), 256>>>(
        act, HID, p2_w, HID, qg, DM, HID, p2_b,
        qn, nullptr, nullptr, nullptr, nullptr, nullptr, nullptr, nullptr,
        nullptr, 0, nullptr, 0, nullptr);
    ln_kernel<<<Bq, 256>>>(ln_g, ln_b);
    // 6) LSTM: fused first step, then 3 fused recurrent steps (ping-pong h)
    sgemm<128, 2><<<dim3(GATES / 128, Bq / 128), 256>>>(
        qg, DM, w_ih, DM, nullptr, GATES, DM, nullptr, nullptr,
        qp, nullptr, b_ih, b_hh, cst, qg, ha,
        nullptr, 0, nullptr, 0, nullptr);
    sgemm<128, 3><<<dim3(GATES / 128, Bq / 128), 256>>>(
        ha, DM, w_hh, HID, nullptr, GATES, DM, nullptr, nullptr,
        qp, vr, nullptr, nullptr, cst, qg, hb,
        nullptr, 0, nullptr, 0, nullptr);
    sgemm<128, 3><<<dim3(GATES / 128, Bq / 128), 256>>>(
        hb, DM, w_hh, HID, nullptr, GATES, DM, nullptr, nullptr,
        qp, vr, nullptr, nullptr, cst, qg, ha,
        nullptr, 0, nullptr, 0, nullptr);
    sgemm<128, 3><<<dim3(GATES / 128, Bq / 128), 256>>>(
        ha, DM, w_hh, HID, nullptr, GATES, DM, nullptr, nullptr,
        qp, vr, nullptr, nullptr, cst, qg, hb,
        nullptr, 0, nullptr, 0, nullptr);
    // 7) normalized dot
    final_kernel<<<Bq / 8, 256>>>(out);
}

// round 6
// speedup vs baseline: 1.1686x; 1.1686x over previous
#include <cuda_runtime.h>
#include <cuda_bf16.h>
#include <math.h>
#include <cstdint>

#define D     128
#define Mn    128
#define KTAB  64
#define KSEL  32
#define Bq    2048
#define FEW   5
#define DM    256
#define HID   512
#define GATES 2048
#define NTASK (2 * Bq + 2 * FEW)
#define TPAD  4160

typedef unsigned long long ull;
typedef unsigned int u32;

// ================= scratch =================
__device__ __align__(128) float g_hs[TPAD * DM];
__device__ __align__(128) float g_hk[TPAD * D];
__device__ __align__(128) float g_c1[TPAD * D];
__device__ __align__(128) float g_c2[TPAD * D];
__device__ __align__(128) float g_qn[Bq * DM];
__device__ __align__(128) float g_sn[FEW * DM];
__device__ __align__(128) float g_shd[FEW * HID];
__device__ __align__(128) float g_sz[FEW * DM];
__device__ __align__(128) float g_act[Bq * HID];
__device__ __align__(128) float g_qg[Bq * DM];
__device__ __align__(128) float g_sg[DM];
__device__ __align__(128) float g_sgn[DM];
__device__ __align__(128) float g_vr[GATES];
__device__ __align__(128) float g_pb[GATES];
__device__ __align__(128) float g_qp[(size_t)Bq * GATES];
__device__ __align__(128) float g_cst[Bq * HID];
__device__ __align__(128) float g_hb[Bq * DM];
__device__ __align__(128) u32 g_qghi[Bq * 128];
__device__ __align__(128) u32 g_qglo[Bq * 128];
__device__ __align__(128) u32 g_hahi[Bq * 128];
__device__ __align__(128) u32 g_halo[Bq * 128];
__device__ __align__(128) u32 g_hbhi[Bq * 128];
__device__ __align__(128) u32 g_hblo[Bq * 128];
__device__ __align__(128) u32 g_wihh[GATES * 128];
__device__ __align__(128) u32 g_wihl[GATES * 128];
__device__ __align__(128) u32 g_whhh[GATES * 128];
__device__ __align__(128) u32 g_whhl[GATES * 128];

__device__ __forceinline__ float wred(float v) {
#pragma unroll
    for (int o = 16; o; o >>= 1) v += __shfl_xor_sync(0xffffffffu, v, o);
    return v;
}
__device__ __forceinline__ float sigmf(float x) { return 1.f / (1.f + expf(-x)); }
__device__ __forceinline__ ull pack2(float x) {
    ull r; asm("mov.b64 %0, {%1, %1};" : "=l"(r) : "r"(__float_as_uint(x))); return r;
}
__device__ __forceinline__ void dfma(ull& d, ull a, ull b) {
    asm("fma.rn.f32x2 %0, %1, %2, %0;" : "+l"(d) : "l"(a), "l"(b));
}
__device__ __forceinline__ float2 unpack2(ull v) {
    unsigned lo, hi;
    asm("mov.b64 {%0, %1}, %2;" : "=r"(lo), "=r"(hi) : "l"(v));
    float2 f; f.x = __uint_as_float(lo); f.y = __uint_as_float(hi); return f;
}
__device__ __forceinline__ void splitpack(float a, float b, u32& hi, u32& lo) {
    __nv_bfloat16 ha = __float2bfloat16(a), hb2 = __float2bfloat16(b);
    __nv_bfloat16 la = __float2bfloat16(a - __bfloat162float(ha));
    __nv_bfloat16 lb = __float2bfloat16(b - __bfloat162float(hb2));
    __nv_bfloat162 H; H.x = ha; H.y = hb2;
    __nv_bfloat162 L; L.x = la; L.y = lb;
    hi = *(u32*)&H; lo = *(u32*)&L;
}
// gate-column permutation: block b=n>>4 holds units b*4+v; within block
// i@2v, f@2v+1, g@2v+8, o@2v+9. Source row in torch layout = gate*512 + unit.
__device__ __forceinline__ int nperm_src(int n) {
    int b = n >> 4, r = n & 15;
    int v = (r & 7) >> 1;
    int g = (r >> 3) * 2 + (r & 1);
    return g * 512 + b * 4 + v;
}
__device__ __forceinline__ u32 smem_u32(const void* p) {
    u32 a;
    asm("{ .reg .u64 t; cvta.to.shared.u64 t, %1; cvt.u32.u64 %0, t; }" : "=r"(a) : "l"(p));
    return a;
}
__device__ __forceinline__ void ldm4(u32* r, u32 addr) {
    asm volatile("ldmatrix.sync.aligned.m8n8.x4.shared.b16 {%0,%1,%2,%3}, [%4];"
                 : "=r"(r[0]), "=r"(r[1]), "=r"(r[2]), "=r"(r[3]) : "r"(addr));
}
__device__ __forceinline__ void mma16816(float* d, const u32* a, const u32* b) {
    asm volatile("mma.sync.aligned.m16n8k16.row.col.f32.bf16.bf16.f32 "
                 "{%0,%1,%2,%3},{%4,%5,%6,%7},{%8,%9},{%0,%1,%2,%3};"
                 : "+f"(d[0]), "+f"(d[1]), "+f"(d[2]), "+f"(d[3])
                 : "r"(a[0]), "r"(a[1]), "r"(a[2]), "r"(a[3]), "r"(b[0]), "r"(b[1]));
}

// ================= neighbor gather =================
__global__ __launch_bounds__(256) void neigh_gather(
    const int* __restrict__ query, const int* __restrict__ support,
    const int* __restrict__ qlc, const int* __restrict__ qrc,
    const int* __restrict__ slc, const int* __restrict__ src_,
    const int* __restrict__ knn, const float* __restrict__ emb)
{
    __shared__ float s_center[D];
    __shared__ int   s_rid[Mn], s_eid[Mn];
    __shared__ float s_sim[Mn];
    __shared__ int   s_kid[KTAB];
    __shared__ float s_ksim[KTAB];
    __shared__ int   s_selr[KSEL], s_sele[KSEL], s_kselv[KSEL];
    __shared__ int   s_cnt, s_kcnt;
    __shared__ float s_cn;

    int task = blockIdx.x;
    const int* conn; int id;
    if (task < 2 * Bq) {
        int row = task & (Bq - 1);
        int br  = task >> 11;
        conn = (br ? qrc : qlc) + (size_t)row * Mn * 2;
        id   = query[row * 2 + br];
    } else {
        int t = task - 2 * Bq;
        int br = t / FEW, row = t % FEW;
        conn = (br ? src_ : slc) + (size_t)row * Mn * 2;
        id   = support[row * 2 + br];
    }
    int tid = threadIdx.x, lane = tid & 31, wid = tid >> 5;
    if (tid == 0) { s_cnt = 0; s_kcnt = 0; }
    if (tid < D)  s_center[tid] = emb[(size_t)id * D + tid];
    if (tid < Mn) { s_rid[tid] = conn[tid * 2]; s_eid[tid] = conn[tid * 2 + 1]; }
    if (tid >= 192) s_kid[tid - 192] = knn[(size_t)id * KTAB + (tid - 192)];
    __syncthreads();

    if (wid == 0) {
        float c0 = s_center[lane], c1 = s_center[lane + 32],
              c2 = s_center[lane + 64], c3 = s_center[lane + 96];
        float s = wred(c0 * c0 + c1 * c1 + c2 * c2 + c3 * c3);
        if (lane == 0) s_cn = sqrtf(s);
    }
    __syncthreads();
    float cn = s_cn;
    float4 cv = ((const float4*)s_center)[lane];

#pragma unroll
    for (int g = 0; g < 4; g++) {
        int m = wid * 16 + g * 4;
        float dt[4], nn[4];
#pragma unroll
        for (int t = 0; t < 4; t++) {
            float4 ev = ((const float4*)(emb + (size_t)s_eid[m + t] * D))[lane];
            dt[t] = ev.x * cv.x + ev.y * cv.y + ev.z * cv.z + ev.w * cv.w;
            nn[t] = ev.x * ev.x + ev.y * ev.y + ev.z * ev.z + ev.w * ev.w;
        }
#pragma unroll
        for (int o = 16; o; o >>= 1) {
#pragma unroll
            for (int t = 0; t < 4; t++) {
                dt[t] += __shfl_xor_sync(0xffffffffu, dt[t], o);
                nn[t] += __shfl_xor_sync(0xffffffffu, nn[t], o);
            }
        }
        if (lane == 0) {
#pragma unroll
            for (int t = 0; t < 4; t++)
                s_sim[m + t] = dt[t] / fmaxf(cn * sqrtf(nn[t]), 1e-8f);
        }
    }
#pragma unroll
    for (int g = 0; g < 2; g++) {
        int m = wid * 8 + g * 4;
        float dt[4], nn[4];
#pragma unroll
        for (int t = 0; t < 4; t++) {
            float4 ev = ((const float4*)(emb + (size_t)s_kid[m + t] * D))[lane];
            dt[t] = ev.x * cv.x + ev.y * cv.y + ev.z * cv.z + ev.w * cv.w;
            nn[t] = ev.x * ev.x + ev.y * ev.y + ev.z * ev.z + ev.w * ev.w;
        }
#pragma unroll
        for (int o = 16; o; o >>= 1) {
#pragma unroll
            for (int t = 0; t < 4; t++) {
                dt[t] += __shfl_xor_sync(0xffffffffu, dt[t], o);
                nn[t] += __shfl_xor_sync(0xffffffffu, nn[t], o);
            }
        }
        if (lane == 0) {
#pragma unroll
            for (int t = 0; t < 4; t++)
                s_ksim[m + t] = dt[t] / fmaxf(cn * sqrtf(nn[t]), 1e-8f);
        }
    }
    __syncthreads();

    if (tid < Mn) {
        float v = s_sim[tid]; int r = 0;
        for (int j = 0; j < Mn; j++) {
            float u = s_sim[j];
            r += (u > v) || (u == v && j < tid);
        }
        if (r < KSEL) {
            int p = atomicAdd(&s_cnt, 1);
            s_selr[p] = s_rid[tid];
            s_sele[p] = s_eid[tid];
        }
    } else if (tid < Mn + KTAB) {
        int m = tid - Mn;
        float v = s_ksim[m]; int r = 0;
        for (int j = 0; j < KTAB; j++) {
            float u = s_ksim[j];
            r += (u > v) || (u == v && j < m);
        }
        if (r < KSEL) {
            int p = atomicAdd(&s_kcnt, 1);
            s_kselv[p] = s_kid[m];
        }
    }
    __syncthreads();

    int d = tid & (D - 1);
    float acc = 0.f;
    if (tid < D) {
#pragma unroll 8
        for (int i = 0; i < KSEL; i++) acc += emb[(size_t)s_selr[i] * D + d];
        g_hs[(size_t)task * DM + d] = acc * (1.f / KSEL);
        float ak = 0.f;
#pragma unroll 8
        for (int i = 0; i < KSEL; i++) ak += emb[(size_t)s_kselv[i] * D + d];
        g_hk[(size_t)task * D + d] = ak * (1.f / KSEL);
    } else {
#pragma unroll 8
        for (int i = 0; i < KSEL; i++) acc += emb[(size_t)s_sele[i] * D + d];
        g_hs[(size_t)task * DM + D + d] = acc * (1.f / KSEL);
    }
}

// ================= combine =================
__global__ __launch_bounds__(256) void combine_kernel(
    const float* __restrict__ gcn_w_b, const float* __restrict__ gcn_b,
    const float* __restrict__ gate_w, const float* __restrict__ gate_b)
{
    int lane = threadIdx.x & 31, wid = threadIdx.x >> 5;
    int t = blockIdx.x * 8 + wid;
    if (t >= NTASK) return;
    int c = lane * 4;
    float4 c1 = *(const float4*)(g_c1 + (size_t)t * D + c);
    float4 c2 = *(const float4*)(g_c2 + (size_t)t * D + c);
    float4 wb = *(const float4*)(gcn_w_b + c);
    float4 gb = *(const float4*)(gcn_b + c);
    float s0 = tanhf(c1.x + wb.x + gb.x), s1 = tanhf(c1.y + wb.y + gb.y);
    float s2 = tanhf(c1.z + wb.z + gb.z), s3 = tanhf(c1.w + wb.w + gb.w);
    float k0 = tanhf(c2.x + wb.x + gb.x), k1 = tanhf(c2.y + wb.y + gb.y);
    float k2 = tanhf(c2.z + wb.z + gb.z), k3 = tanhf(c2.w + wb.w + gb.w);
    float4 gws = *(const float4*)(gate_w + c);
    float4 gwk = *(const float4*)(gate_w + D + c);
    float a = gws.x * s0 + gws.y * s1 + gws.z * s2 + gws.w * s3
            + gwk.x * k0 + gwk.y * k1 + gwk.z * k2 + gwk.w * k3;
    a = wred(a);
    float al = sigmf(a + gate_b[0]);
    float4 o;
    o.x = (1.f - al) * s0 + al * k0;
    o.y = (1.f - al) * s1 + al * k1;
    o.z = (1.f - al) * s2 + al * k2;
    o.w = (1.f - al) * s3 + al * k3;
    float* dst;
    if (t < Bq)            dst = g_qn + (size_t)t * DM + c;
    else if (t < 2 * Bq)   dst = g_qn + (size_t)(t - Bq) * DM + D + c;
    else if (t < 2 * Bq + FEW) dst = g_sn + (size_t)(t - 2 * Bq) * DM + c;
    else                   dst = g_sn + (size_t)(t - 2 * Bq - FEW) * DM + D + c;
    *(float4*)dst = o;
}

// ================= FFMA2 SGEMM (0=relu+bias, 1=bias+addmat, 4=dual plain) =================
template<int BM, int MODE>
__global__ __launch_bounds__(256) void sgemm(
    const float* __restrict__ A, int lda,
    const float* __restrict__ B, int ldb,
    float* __restrict__ C, int N, int K,
    const float* __restrict__ bias0, const float* __restrict__ addmat,
    const float* __restrict__ A2, int lda2,
    const float* __restrict__ B2, int K2, float* __restrict__ C2)
{
    if (MODE == 4 && blockIdx.z == 1) { A = A2; lda = lda2; B = B2; K = K2; C = C2; }
    constexpr int TM = BM / 16;
    __shared__ float As[16][BM + 4];
    __shared__ float Bs[16][132];
    int tid = threadIdx.x;
    int bm = blockIdx.y * BM, bn = blockIdx.x * 128;
    int tm = (tid >> 4) * TM, tn = (tid & 15) * 8;
    int ar = tid >> 2, ac = (tid & 3) * 4;

    const float* Ap  = A + (size_t)(bm + ar) * lda + ac;
    const float* Bp0 = B + (size_t)(bn + ar) * ldb + ac;
    const float* Bp1 = B + (size_t)(bn + ar + 64) * ldb + ac;

    ull acc2[TM][4];
#pragma unroll
    for (int i = 0; i < TM; i++)
#pragma unroll
        for (int j = 0; j < 4; j++) acc2[i][j] = 0ULL;

    for (int k0 = 0; k0 < K; k0 += 16) {
        float4 a0 = *(const float4*)(Ap + k0);
        float4 a1;
        if (BM == 128) a1 = *(const float4*)(Ap + (size_t)64 * lda + k0);
        float4 b0 = *(const float4*)(Bp0 + k0);
        float4 b1 = *(const float4*)(Bp1 + k0);
        __syncthreads();
        As[ac + 0][ar] = a0.x; As[ac + 1][ar] = a0.y; As[ac + 2][ar] = a0.z; As[ac + 3][ar] = a0.w;
        if (BM == 128) {
            As[ac + 0][ar + 64] = a1.x; As[ac + 1][ar + 64] = a1.y;
            As[ac + 2][ar + 64] = a1.z; As[ac + 3][ar + 64] = a1.w;
        }
        Bs[ac + 0][ar] = b0.x; Bs[ac + 1][ar] = b0.y; Bs[ac + 2][ar] = b0.z; Bs[ac + 3][ar] = b0.w;
        Bs[ac + 0][ar + 64] = b1.x; Bs[ac + 1][ar + 64] = b1.y;
        Bs[ac + 2][ar + 64] = b1.z; Bs[ac + 3][ar + 64] = b1.w;
        __syncthreads();
#pragma unroll
        for (int kk = 0; kk < 16; kk++) {
            float av[TM];
            *(float4*)av = *(const float4*)&As[kk][tm];
            if (TM == 8) *(float4*)(av + 4) = *(const float4*)&As[kk][tm + 4];
            ulonglong2 p01 = *(const ulonglong2*)&Bs[kk][tn];
            ulonglong2 p23 = *(const ulonglong2*)&Bs[kk][tn + 4];
#pragma unroll
            for (int i = 0; i < TM; i++) {
                ull ap = pack2(av[i]);
                dfma(acc2[i][0], ap, p01.x);
                dfma(acc2[i][1], ap, p01.y);
                dfma(acc2[i][2], ap, p23.x);
                dfma(acc2[i][3], ap, p23.y);
            }
        }
    }

    int nb = bn + tn;
#pragma unroll
    for (int i = 0; i < TM; i++) {
        size_t m = (size_t)(bm + tm + i);
        float v[8];
#pragma unroll
        for (int jp = 0; jp < 4; jp++) {
            float2 f = unpack2(acc2[i][jp]);
            v[2 * jp] = f.x; v[2 * jp + 1] = f.y;
        }
        if (MODE == 0) {
#pragma unroll
            for (int j = 0; j < 8; j++) v[j] = fmaxf(v[j] + bias0[nb + j], 0.f);
        } else if (MODE == 1) {
            const float4* am = (const float4*)(addmat + m * N + nb);
            float4 m0 = am[0], m1 = am[1];
            v[0] += bias0[nb + 0] + m0.x; v[1] += bias0[nb + 1] + m0.y;
            v[2] += bias0[nb + 2] + m0.z; v[3] += bias0[nb + 3] + m0.w;
            v[4] += bias0[nb + 4] + m1.x; v[5] += bias0[nb + 5] + m1.y;
            v[6] += bias0[nb + 6] + m1.z; v[7] += bias0[nb + 7] + m1.w;
        }
        float4* cp = (float4*)(C + m * N + nb);
        cp[0] = make_float4(v[0], v[1], v[2], v[3]);
        cp[1] = make_float4(v[4], v[5], v[6], v[7]);
    }
}

// ================= weight prep: planar bf16 hi/lo in permuted gate layout =================
__global__ __launch_bounds__(256) void prep_wmma(
    const float* __restrict__ w, int ldw, u32* __restrict__ hi, u32* __restrict__ lo)
{
    int idx = blockIdx.x * 256 + threadIdx.x;      // over 2048*128
    int n = idx >> 7, kp = idx & 127;
    int srow = nperm_src(n);
    float v0 = w[(size_t)srow * ldw + 2 * kp];
    float v1 = w[(size_t)srow * ldw + 2 * kp + 1];
    u32 h, l;
    splitpack(v0, v1, h, l);
    hi[idx] = h; lo[idx] = l;
}

// ================= LSTM step: bf16-split mma.sync + fused gates =================
// C[128m x 128n] per CTA; A[2048,256] split bf16; W planar split bf16 (permuted cols).
template<int FIRST, int LAST>
__global__ __launch_bounds__(256) void lstm_mma(
    const u32* __restrict__ ahi, const u32* __restrict__ alo,
    const u32* __restrict__ whi, const u32* __restrict__ wlo,
    float* __restrict__ qp, const float* __restrict__ pbias, const float* __restrict__ vr,
    float* __restrict__ cst, const float* __restrict__ qg,
    u32* __restrict__ ohi, u32* __restrict__ olo, float* __restrict__ of32)
{
    __shared__ __align__(16) __nv_bfloat16 sAh[128][24], sAl[128][24], sWh[128][24], sWl[128][24];
    int tid = threadIdx.x, lane = tid & 31, w = tid >> 5;
    int bm = blockIdx.y * 128, bn = blockIdx.x * 128;
    int wm = (w >> 1) * 32, wn = (w & 1) * 64;

    float acc[2][8][4];
#pragma unroll
    for (int i = 0; i < 2; i++)
#pragma unroll
        for (int j = 0; j < 8; j++)
#pragma unroll
            for (int c = 0; c < 4; c++) acc[i][j][c] = 0.f;

    int lrow = tid >> 1, lseg = tid & 1;
    const uint4* gAh = (const uint4*)(ahi + (size_t)(bm + lrow) * 128) + lseg;
    const uint4* gAl = (const uint4*)(alo + (size_t)(bm + lrow) * 128) + lseg;
    const uint4* gWh = (const uint4*)(whi + (size_t)(bn + lrow) * 128) + lseg;
    const uint4* gWl = (const uint4*)(wlo + (size_t)(bn + lrow) * 128) + lseg;
    // smem store slot (same each chunk): row lrow, bf16 col lseg*8
    u32 soff = (u32)(lrow * 24 + lseg * 8) * 2;
    u32 bAh = smem_u32(sAh), bAl = smem_u32(sAl), bWh = smem_u32(sWh), bWl = smem_u32(sWl);

    // ldmatrix offsets
    u32 aoff[2];
#pragma unroll
    for (int mf = 0; mf < 2; mf++) {
        int row = wm + mf * 16 + (lane & 15);
        int col = (lane >> 4) * 8;
        aoff[mf] = (u32)(row * 24 + col) * 2;
    }
    u32 boff[4];
#pragma unroll
    for (int nf = 0; nf < 4; nf++) {
        int g = lane >> 3;
        int row = wn + nf * 16 + (lane & 7) + (g >> 1) * 8;
        int col = (g & 1) * 8;
        boff[nf] = (u32)(row * 24 + col) * 2;
    }

    for (int kc = 0; kc < 16; kc++) {
        uint4 vah = gAh[kc * 2], val = gAl[kc * 2], vwh = gWh[kc * 2], vwl = gWl[kc * 2];
        __syncthreads();
        *(uint4*)((char*)sAh + soff) = vah;
        *(uint4*)((char*)sAl + soff) = val;
        *(uint4*)((char*)sWh + soff) = vwh;
        *(uint4*)((char*)sWl + soff) = vwl;
        __syncthreads();

        u32 ah[2][4], al[2][4], wf[4][4];
        ldm4(ah[0], bAh + aoff[0]); ldm4(ah[1], bAh + aoff[1]);
        ldm4(al[0], bAl + aoff[0]); ldm4(al[1], bAl + aoff[1]);
#pragma unroll
        for (int nf = 0; nf < 4; nf++) ldm4(wf[nf], bWh + boff[nf]);
#pragma unroll
        for (int mf = 0; mf < 2; mf++)
#pragma unroll
            for (int nf = 0; nf < 4; nf++) {
                mma16816(acc[mf][nf * 2],     ah[mf], wf[nf]);
                mma16816(acc[mf][nf * 2 + 1], ah[mf], wf[nf] + 2);
                mma16816(acc[mf][nf * 2],     al[mf], wf[nf]);
                mma16816(acc[mf][nf * 2 + 1], al[mf], wf[nf] + 2);
            }
#pragma unroll
        for (int nf = 0; nf < 4; nf++) ldm4(wf[nf], bWl + boff[nf]);
#pragma unroll
        for (int mf = 0; mf < 2; mf++)
#pragma unroll
            for (int nf = 0; nf < 4; nf++) {
                mma16816(acc[mf][nf * 2],     ah[mf], wf[nf]);
                mma16816(acc[mf][nf * 2 + 1], ah[mf], wf[nf] + 2);
            }
    }

    // epilogue: gates + state update
    int q = lane & 3, r4 = lane >> 2;
#pragma unroll
    for (int mf = 0; mf < 2; mf++) {
#pragma unroll
        for (int p = 0; p < 4; p++) {
            int nblk = bn + wn + p * 16;
            int u = (nblk >> 4) * 4 + q;
            int n0 = nblk + 2 * q;
            float* A0 = acc[mf][2 * p];
            float* A1 = acc[mf][2 * p + 1];
#pragma unroll
            for (int rh = 0; rh < 2; rh++) {
                size_t m = (size_t)(bm + wm + mf * 16 + r4 + rh * 8);
                float iv = A0[rh * 2], fv = A0[rh * 2 + 1];
                float gv = A1[rh * 2], ov = A1[rh * 2 + 1];
                if (FIRST) {
                    iv += pbias[n0];     fv += pbias[n0 + 1];
                    gv += pbias[n0 + 8]; ov += pbias[n0 + 9];
                    *(float2*)(qp + m * GATES + n0)     = make_float2(iv, fv);
                    *(float2*)(qp + m * GATES + n0 + 8) = make_float2(gv, ov);
                } else {
                    float2 q1 = *(const float2*)(qp + m * GATES + n0);
                    float2 q2 = *(const float2*)(qp + m * GATES + n0 + 8);
                    iv += q1.x + vr[n0];     fv += q1.y + vr[n0 + 1];
                    gv += q2.x + vr[n0 + 8]; ov += q2.y + vr[n0 + 9];
                }
                float cc;
                if (FIRST) cc = sigmf(iv) * tanhf(gv);
                else       cc = sigmf(fv) * cst[m * HID + u] + sigmf(iv) * tanhf(gv);
                cst[m * HID + u] = cc;
                if (u < DM) {
                    float h = qg[m * DM + u] + sigmf(ov) * tanhf(cc);
                    if (LAST) {
                        of32[m * DM + u] = h;
                    } else {
                        __nv_bfloat16 hh = __float2bfloat16(h);
                        __nv_bfloat16 hl = __float2bfloat16(h - __bfloat162float(hh));
                        ((__nv_bfloat16*)ohi)[m * DM + u] = hh;
                        ((__nv_bfloat16*)olo)[m * DM + u] = hl;
                    }
                }
            }
        }
    }
}

// ================= support path =================
__global__ __launch_bounds__(256) void sup1_kernel(
    const float* __restrict__ p1_w, const float* __restrict__ p1_b)
{
    int lane = threadIdx.x & 31, wid = threadIdx.x >> 5;
    int w = blockIdx.x * 8 + wid;
    int r = w >> 9, u = w & (HID - 1);
    const float* wp = p1_w + (size_t)u * DM;
    const float* xp = g_sn + r * DM;
    float a = 0.f;
#pragma unroll
    for (int s = 0; s < 8; s++) a += wp[lane + 32 * s] * xp[lane + 32 * s];
    a = wred(a);
    if (lane == 0) g_shd[r * HID + u] = fmaxf(a + p1_b[u], 0.f);
}

__global__ __launch_bounds__(256) void sup2_kernel(
    const float* __restrict__ p2_w, const float* __restrict__ p2_b)
{
    int lane = threadIdx.x & 31, wid = threadIdx.x >> 5;
    int w = blockIdx.x * 8 + wid;
    int r = w >> 8, u = w & (DM - 1);
    const float* wp = p2_w + (size_t)u * HID;
    const float* xp = g_shd + r * HID;
    float a = 0.f;
#pragma unroll
    for (int s = 0; s < 16; s++) a += wp[lane + 32 * s] * xp[lane + 32 * s];
    a = wred(a);
    if (lane == 0) g_sz[r * DM + u] = a + p2_b[u] + g_sn[r * DM + u];
}

__global__ __launch_bounds__(256) void sup3_kernel(
    const float* __restrict__ ln_g, const float* __restrict__ ln_b)
{
    __shared__ float red[8];
    int tid = threadIdx.x, lane = tid & 31, wid = tid >> 5;
    float accg = 0.f;
    for (int r = 0; r < FEW; r++) {
        float z = g_sz[r * DM + tid];
        float s1 = wred(z);
        if (lane == 0) red[wid] = s1;
        __syncthreads();
        float mu = (red[0] + red[1] + red[2] + red[3] + red[4] + red[5] + red[6] + red[7]) * (1.f / DM);
        __syncthreads();
        float dz = z - mu;
        float s2 = wred(dz * dz);
        if (lane == 0) red[wid] = s2;
        __syncthreads();
        float sig = sqrtf((red[0] + red[1] + red[2] + red[3] + red[4] + red[5] + red[6] + red[7]) * (1.f / (DM - 1)));
        accg += dz / (sig + 1e-3f) * ln_g[tid] + ln_b[tid];
        __syncthreads();
    }
    float sg = accg * (1.f / FEW);
    g_sg[tid] = sg;
    float s3 = wred(sg * sg);
    if (lane == 0) red[wid] = s3;
    __syncthreads();
    float nrm = sqrtf(red[0] + red[1] + red[2] + red[3] + red[4] + red[5] + red[6] + red[7]);
    g_sgn[tid] = sg / fmaxf(nrm, 1e-12f);
}

// vr + bias in permuted layout
__global__ __launch_bounds__(256) void vr_kernel(
    const float* __restrict__ w_hh,
    const float* __restrict__ b_ih, const float* __restrict__ b_hh)
{
    int lane = threadIdx.x & 31, wid = threadIdx.x >> 5;
    int n = blockIdx.x * 8 + wid;
    int p = nperm_src(n);
    const float* w = w_hh + (size_t)p * HID + DM;
    float a = 0.f;
#pragma unroll
    for (int s = 0; s < 8; s++) a += w[lane + 32 * s] * g_sg[lane + 32 * s];
    a = wred(a);
    if (lane == 0) {
        g_vr[n] = a;
        g_pb[n] = b_ih[p] + b_hh[p];
    }
}

__global__ __launch_bounds__(256) void ln_kernel(const float* __restrict__ ln_g,
                                                 const float* __restrict__ ln_b) {
    __shared__ float red[8];
    __shared__ float srow[DM];
    int row = blockIdx.x, tid = threadIdx.x, lane = tid & 31, wid = tid >> 5;
    float z = g_qg[(size_t)row * DM + tid];
    float s1 = wred(z);
    if (lane == 0) red[wid] = s1;
    __syncthreads();
    float mu = (red[0] + red[1] + red[2] + red[3] + red[4] + red[5] + red[6] + red[7]) * (1.f / DM);
    __syncthreads();
    float dz = z - mu;
    float s2 = wred(dz * dz);
    if (lane == 0) red[wid] = s2;
    __syncthreads();
    float sig = sqrtf((red[0] + red[1] + red[2] + red[3] + red[4] + red[5] + red[6] + red[7]) * (1.f / (DM - 1)));
    float o = dz / (sig + 1e-3f) * ln_g[tid] + ln_b[tid];
    g_qg[(size_t)row * DM + tid] = o;
    srow[tid] = o;
    __syncthreads();
    if (tid < 128) {
        u32 hi, lo;
        splitpack(srow[2 * tid], srow[2 * tid + 1], hi, lo);
        g_qghi[(size_t)row * 128 + tid] = hi;
        g_qglo[(size_t)row * 128 + tid] = lo;
    }
}

__global__ __launch_bounds__(256) void final_kernel(float* __restrict__ out) {
    int lane = threadIdx.x & 31, wid = threadIdx.x >> 5;
    int row = blockIdx.x * 8 + wid;
    const float* h = g_hb + (size_t)row * DM;
    float ss = 0.f, dt = 0.f;
#pragma unroll
    for (int s = 0; s < 8; s++) {
        float v = h[lane + 32 * s];
        ss += v * v;
        dt += v * g_sgn[lane + 32 * s];
    }
    ss = wred(ss); dt = wred(dt);
    if (lane == 0) out[row] = dt / fmaxf(sqrtf(ss), 1e-12f);
}

// ================= host =================
extern "C" void kernel_launch(void* const* d_in, const int* in_sizes, int n_in,
                              void* d_out, int out_size) {
    const int*   query   = (const int*)d_in[0];
    const int*   support = (const int*)d_in[1];
    const int*   qlc     = (const int*)d_in[2];
    const int*   qrc     = (const int*)d_in[4];
    const int*   slc     = (const int*)d_in[6];
    const int*   src_    = (const int*)d_in[8];
    const int*   knn     = (const int*)d_in[10];
    const float* emb     = (const float*)d_in[11];
    const float* gcn_w   = (const float*)d_in[12];
    const float* gcn_w_b = (const float*)d_in[13];
    const float* gcn_b   = (const float*)d_in[14];
    const float* gate_w  = (const float*)d_in[15];
    const float* gate_b  = (const float*)d_in[16];
    const float* p1_w    = (const float*)d_in[17];
    const float* p1_b    = (const float*)d_in[18];
    const float* p2_w    = (const float*)d_in[19];
    const float* p2_b    = (const float*)d_in[20];
    const float* ln_g    = (const float*)d_in[21];
    const float* ln_b    = (const float*)d_in[22];
    const float* w_ih    = (const float*)d_in[23];
    const float* w_hh    = (const float*)d_in[24];
    const float* b_ih    = (const float*)d_in[25];
    const float* b_hh    = (const float*)d_in[26];
    float* out = (float*)d_out;

    float *hs, *hk, *c1, *c2, *qn, *act, *qg, *vr, *pb, *qp, *cst, *hb;
    u32 *wihh, *wihl, *whhh, *whhl, *qghi, *qglo, *hahi, *halo, *hbhi, *hblo;
    cudaGetSymbolAddress((void**)&hs, g_hs);
    cudaGetSymbolAddress((void**)&hk, g_hk);
    cudaGetSymbolAddress((void**)&c1, g_c1);
    cudaGetSymbolAddress((void**)&c2, g_c2);
    cudaGetSymbolAddress((void**)&qn, g_qn);
    cudaGetSymbolAddress((void**)&act, g_act);
    cudaGetSymbolAddress((void**)&qg, g_qg);
    cudaGetSymbolAddress((void**)&vr, g_vr);
    cudaGetSymbolAddress((void**)&pb, g_pb);
    cudaGetSymbolAddress((void**)&qp, g_qp);
    cudaGetSymbolAddress((void**)&cst, g_cst);
    cudaGetSymbolAddress((void**)&hb, g_hb);
    cudaGetSymbolAddress((void**)&wihh, g_wihh);
    cudaGetSymbolAddress((void**)&wihl, g_wihl);
    cudaGetSymbolAddress((void**)&whhh, g_whhh);
    cudaGetSymbolAddress((void**)&whhl, g_whhl);
    cudaGetSymbolAddress((void**)&qghi, g_qghi);
    cudaGetSymbolAddress((void**)&qglo, g_qglo);
    cudaGetSymbolAddress((void**)&hahi, g_hahi);
    cudaGetSymbolAddress((void**)&halo, g_halo);
    cudaGetSymbolAddress((void**)&hbhi, g_hbhi);
    cudaGetSymbolAddress((void**)&hblo, g_hblo);

    dim3 lgrid(16, 16);

    prep_wmma<<<GATES * 128 / 256, 256>>>(w_ih, DM, wihh, wihl);
    prep_wmma<<<GATES * 128 / 256, 256>>>(w_hh, HID, whhh, whhl);
    neigh_gather<<<NTASK, 256>>>(query, support, qlc, qrc, slc, src_, knn, emb);
    sgemm<64, 4><<<dim3(1, TPAD / 64, 2), 256>>>(
        hs, DM, gcn_w, DM, c1, D, DM, nullptr, nullptr,
        hk, D, gcn_w + D, D, c2);
    combine_kernel<<<(NTASK + 7) / 8, 256>>>(gcn_w_b, gcn_b, gate_w, gate_b);
    sup1_kernel<<<FEW * HID / 8, 256>>>(p1_w, p1_b);
    sup2_kernel<<<FEW * DM / 8, 256>>>(p2_w, p2_b);
    sup3_kernel<<<1, 256>>>(ln_g, ln_b);
    vr_kernel<<<GATES / 8, 256>>>(w_hh, b_ih, b_hh);
    sgemm<64, 0><<<dim3(HID / 128, Bq / 64), 256>>>(
        qn, DM, p1_w, DM, act, HID, DM, p1_b, nullptr,
        nullptr, 0, nullptr, 0, nullptr);
    sgemm<64, 1><<<dim3(DM / 128, Bq / 64), 256>>>(
        act, HID, p2_w, HID, qg, DM, HID, p2_b, qn,
        nullptr, 0, nullptr, 0, nullptr);
    ln_kernel<<<Bq, 256>>>(ln_g, ln_b);
    lstm_mma<1, 0><<<lgrid, 256>>>(qghi, qglo, wihh, wihl, qp, pb, vr, cst, qg,
                                   hahi, halo, nullptr);
    lstm_mma<0, 0><<<lgrid, 256>>>(hahi, halo, whhh, whhl, qp, pb, vr, cst, qg,
                                   hbhi, hblo, nullptr);
    lstm_mma<0, 0><<<lgrid, 256>>>(hbhi, hblo, whhh, whhl, qp, pb, vr, cst, qg,
                                   hahi, halo, nullptr);
    lstm_mma<0, 1><<<lgrid, 256>>>(hahi, halo, whhh, whhl, qp, pb, vr, cst, qg,
                                   nullptr, nullptr, hb);
    final_kernel<<<Bq / 8, 256>>>(out);
}

// round 7
// speedup vs baseline: 1.2524x; 1.0717x over previous
#include <cuda_runtime.h>
#include <cuda_bf16.h>
#include <math.h>
#include <cstdint>

#define D     128
#define Mn    128
#define KTAB  64
#define KSEL  32
#define Bq    2048
#define FEW   5
#define DM    256
#define HID   512
#define GATES 2048
#define NTASK (2 * Bq + 2 * FEW)
#define TPAD  4224

typedef unsigned long long ull;
typedef unsigned int u32;

// ================= scratch =================
__device__ __align__(128) float g_c1[TPAD * D];
__device__ __align__(128) float g_c2[TPAD * D];
__device__ __align__(128) float g_qn[Bq * DM];
__device__ __align__(128) float g_sn[FEW * DM];
__device__ __align__(128) float g_shd[FEW * HID];
__device__ __align__(128) float g_sz[FEW * DM];
__device__ __align__(128) float g_qg[Bq * DM];
__device__ __align__(128) float g_sg[DM];
__device__ __align__(128) float g_sgn[DM];
__device__ __align__(128) float g_vr[GATES];
__device__ __align__(128) float g_pb[GATES];
__device__ __align__(128) float g_qp[(size_t)Bq * GATES];
__device__ __align__(128) float g_cst[Bq * HID];
__device__ __align__(128) float g_hb[Bq * DM];
// packed bf16 splits
__device__ __align__(128) u32 g_hshi[TPAD * 128];
__device__ __align__(128) u32 g_hslo[TPAD * 128];
__device__ __align__(128) u32 g_hkhi[TPAD * 64];
__device__ __align__(128) u32 g_hklo[TPAD * 64];
__device__ __align__(128) u32 g_qnhi[Bq * 128];
__device__ __align__(128) u32 g_qnlo[Bq * 128];
__device__ __align__(128) u32 g_acthi[Bq * 256];
__device__ __align__(128) u32 g_actlo[Bq * 256];
__device__ __align__(128) u32 g_qghi[Bq * 128];
__device__ __align__(128) u32 g_qglo[Bq * 128];
__device__ __align__(128) u32 g_hahi[Bq * 128];
__device__ __align__(128) u32 g_halo[Bq * 128];
__device__ __align__(128) u32 g_hbhi[Bq * 128];
__device__ __align__(128) u32 g_hblo[Bq * 128];
__device__ __align__(128) u32 g_wihh[GATES * 128];
__device__ __align__(128) u32 g_wihl[GATES * 128];
__device__ __align__(128) u32 g_whhh[GATES * 128];
__device__ __align__(128) u32 g_whhl[GATES * 128];
__device__ __align__(128) u32 g_gwh[128 * 128];
__device__ __align__(128) u32 g_gwl[128 * 128];
__device__ __align__(128) u32 g_gkh[128 * 64];
__device__ __align__(128) u32 g_gkl[128 * 64];
__device__ __align__(128) u32 g_p1h[512 * 128];
__device__ __align__(128) u32 g_p1l[512 * 128];
__device__ __align__(128) u32 g_p2h[256 * 256];
__device__ __align__(128) u32 g_p2l[256 * 256];

__device__ __forceinline__ float wred(float v) {
#pragma unroll
    for (int o = 16; o; o >>= 1) v += __shfl_xor_sync(0xffffffffu, v, o);
    return v;
}
__device__ __forceinline__ float sigmf(float x) { return 1.f / (1.f + expf(-x)); }
__device__ __forceinline__ void splitpack(float a, float b, u32& hi, u32& lo) {
    __nv_bfloat16 ha = __float2bfloat16(a), hb2 = __float2bfloat16(b);
    __nv_bfloat16 la = __float2bfloat16(a - __bfloat162float(ha));
    __nv_bfloat16 lb = __float2bfloat16(b - __bfloat162float(hb2));
    __nv_bfloat162 H; H.x = ha; H.y = hb2;
    __nv_bfloat162 L; L.x = la; L.y = lb;
    hi = *(u32*)&H; lo = *(u32*)&L;
}
__device__ __forceinline__ int nperm_src(int n) {
    int b = n >> 4, r = n & 15;
    int v = (r & 7) >> 1;
    int g = (r >> 3) * 2 + (r & 1);
    return g * 512 + b * 4 + v;
}
__device__ __forceinline__ u32 smem_u32(const void* p) {
    u32 a;
    asm("{ .reg .u64 t; cvta.to.shared.u64 t, %1; cvt.u32.u64 %0, t; }" : "=r"(a) : "l"(p));
    return a;
}
__device__ __forceinline__ void ldm4(u32* r, u32 addr) {
    asm volatile("ldmatrix.sync.aligned.m8n8.x4.shared.b16 {%0,%1,%2,%3}, [%4];"
                 : "=r"(r[0]), "=r"(r[1]), "=r"(r[2]), "=r"(r[3]) : "r"(addr));
}
__device__ __forceinline__ void mma16816(float* d, const u32* a, const u32* b) {
    asm volatile("mma.sync.aligned.m16n8k16.row.col.f32.bf16.bf16.f32 "
                 "{%0,%1,%2,%3},{%4,%5,%6,%7},{%8,%9},{%0,%1,%2,%3};"
                 : "+f"(d[0]), "+f"(d[1]), "+f"(d[2]), "+f"(d[3])
                 : "r"(a[0]), "r"(a[1]), "r"(a[2]), "r"(a[3]), "r"(b[0]), "r"(b[1]));
}

// ================= neighbor gather (emits pre-split hs/hk) =================
__global__ __launch_bounds__(256) void neigh_gather(
    const int* __restrict__ query, const int* __restrict__ support,
    const int* __restrict__ qlc, const int* __restrict__ qrc,
    const int* __restrict__ slc, const int* __restrict__ src_,
    const int* __restrict__ knn, const float* __restrict__ emb)
{
    __shared__ float s_center[D];
    __shared__ int   s_rid[Mn], s_eid[Mn];
    __shared__ float s_sim[Mn];
    __shared__ int   s_kid[KTAB];
    __shared__ float s_ksim[KTAB];
    __shared__ int   s_selr[KSEL], s_sele[KSEL], s_kselv[KSEL];
    __shared__ int   s_cnt, s_kcnt;
    __shared__ float s_cn;
    __shared__ float e_hs[DM];
    __shared__ float e_hk[D];

    int task = blockIdx.x;
    const int* conn; int id;
    if (task < 2 * Bq) {
        int row = task & (Bq - 1);
        int br  = task >> 11;
        conn = (br ? qrc : qlc) + (size_t)row * Mn * 2;
        id   = query[row * 2 + br];
    } else {
        int t = task - 2 * Bq;
        int br = t / FEW, row = t % FEW;
        conn = (br ? src_ : slc) + (size_t)row * Mn * 2;
        id   = support[row * 2 + br];
    }
    int tid = threadIdx.x, lane = tid & 31, wid = tid >> 5;
    if (tid == 0) { s_cnt = 0; s_kcnt = 0; }
    if (tid < D)  s_center[tid] = emb[(size_t)id * D + tid];
    if (tid < Mn) { s_rid[tid] = conn[tid * 2]; s_eid[tid] = conn[tid * 2 + 1]; }
    if (tid >= 192) s_kid[tid - 192] = knn[(size_t)id * KTAB + (tid - 192)];
    __syncthreads();

    if (wid == 0) {
        float c0 = s_center[lane], c1 = s_center[lane + 32],
              c2 = s_center[lane + 64], c3 = s_center[lane + 96];
        float s = wred(c0 * c0 + c1 * c1 + c2 * c2 + c3 * c3);
        if (lane == 0) s_cn = sqrtf(s);
    }
    __syncthreads();
    float cn = s_cn;
    float4 cv = ((const float4*)s_center)[lane];

#pragma unroll
    for (int g = 0; g < 4; g++) {
        int m = wid * 16 + g * 4;
        float dt[4], nn[4];
#pragma unroll
        for (int t = 0; t < 4; t++) {
            float4 ev = ((const float4*)(emb + (size_t)s_eid[m + t] * D))[lane];
            dt[t] = ev.x * cv.x + ev.y * cv.y + ev.z * cv.z + ev.w * cv.w;
            nn[t] = ev.x * ev.x + ev.y * ev.y + ev.z * ev.z + ev.w * ev.w;
        }
#pragma unroll
        for (int o = 16; o; o >>= 1) {
#pragma unroll
            for (int t = 0; t < 4; t++) {
                dt[t] += __shfl_xor_sync(0xffffffffu, dt[t], o);
                nn[t] += __shfl_xor_sync(0xffffffffu, nn[t], o);
            }
        }
        if (lane == 0) {
#pragma unroll
            for (int t = 0; t < 4; t++)
                s_sim[m + t] = dt[t] / fmaxf(cn * sqrtf(nn[t]), 1e-8f);
        }
    }
#pragma unroll
    for (int g = 0; g < 2; g++) {
        int m = wid * 8 + g * 4;
        float dt[4], nn[4];
#pragma unroll
        for (int t = 0; t < 4; t++) {
            float4 ev = ((const float4*)(emb + (size_t)s_kid[m + t] * D))[lane];
            dt[t] = ev.x * cv.x + ev.y * cv.y + ev.z * cv.z + ev.w * cv.w;
            nn[t] = ev.x * ev.x + ev.y * ev.y + ev.z * ev.z + ev.w * ev.w;
        }
#pragma unroll
        for (int o = 16; o; o >>= 1) {
#pragma unroll
            for (int t = 0; t < 4; t++) {
                dt[t] += __shfl_xor_sync(0xffffffffu, dt[t], o);
                nn[t] += __shfl_xor_sync(0xffffffffu, nn[t], o);
            }
        }
        if (lane == 0) {
#pragma unroll
            for (int t = 0; t < 4; t++)
                s_ksim[m + t] = dt[t] / fmaxf(cn * sqrtf(nn[t]), 1e-8f);
        }
    }
    __syncthreads();

    if (tid < Mn) {
        float v = s_sim[tid]; int r = 0;
        for (int j = 0; j < Mn; j++) {
            float u = s_sim[j];
            r += (u > v) || (u == v && j < tid);
        }
        if (r < KSEL) {
            int p = atomicAdd(&s_cnt, 1);
            s_selr[p] = s_rid[tid];
            s_sele[p] = s_eid[tid];
        }
    } else if (tid < Mn + KTAB) {
        int m = tid - Mn;
        float v = s_ksim[m]; int r = 0;
        for (int j = 0; j < KTAB; j++) {
            float u = s_ksim[j];
            r += (u > v) || (u == v && j < m);
        }
        if (r < KSEL) {
            int p = atomicAdd(&s_kcnt, 1);
            s_kselv[p] = s_kid[m];
        }
    }
    __syncthreads();

    int d = tid & (D - 1);
    float acc = 0.f;
    if (tid < D) {
#pragma unroll 8
        for (int i = 0; i < KSEL; i++) acc += emb[(size_t)s_selr[i] * D + d];
        e_hs[d] = acc * (1.f / KSEL);
        float ak = 0.f;
#pragma unroll 8
        for (int i = 0; i < KSEL; i++) ak += emb[(size_t)s_kselv[i] * D + d];
        e_hk[d] = ak * (1.f / KSEL);
    } else {
#pragma unroll 8
        for (int i = 0; i < KSEL; i++) acc += emb[(size_t)s_sele[i] * D + d];
        e_hs[D + d] = acc * (1.f / KSEL);
    }
    __syncthreads();
    if (tid < 128) {
        u32 hi, lo;
        splitpack(e_hs[2 * tid], e_hs[2 * tid + 1], hi, lo);
        g_hshi[(size_t)task * 128 + tid] = hi;
        g_hslo[(size_t)task * 128 + tid] = lo;
    } else if (tid < 192) {
        int t2 = tid - 128;
        u32 hi, lo;
        splitpack(e_hk[2 * t2], e_hk[2 * t2 + 1], hi, lo);
        g_hkhi[(size_t)task * 64 + t2] = hi;
        g_hklo[(size_t)task * 64 + t2] = lo;
    }
}

// ================= combine (emits qn f32 + split) =================
__global__ __launch_bounds__(256) void combine_kernel(
    const float* __restrict__ gcn_w_b, const float* __restrict__ gcn_b,
    const float* __restrict__ gate_w, const float* __restrict__ gate_b)
{
    int lane = threadIdx.x & 31, wid = threadIdx.x >> 5;
    int t = blockIdx.x * 8 + wid;
    if (t >= NTASK) return;
    int c = lane * 4;
    float4 c1 = *(const float4*)(g_c1 + (size_t)t * D + c);
    float4 c2 = *(const float4*)(g_c2 + (size_t)t * D + c);
    float4 wb = *(const float4*)(gcn_w_b + c);
    float4 gb = *(const float4*)(gcn_b + c);
    float s0 = tanhf(c1.x + wb.x + gb.x), s1 = tanhf(c1.y + wb.y + gb.y);
    float s2 = tanhf(c1.z + wb.z + gb.z), s3 = tanhf(c1.w + wb.w + gb.w);
    float k0 = tanhf(c2.x + wb.x + gb.x), k1 = tanhf(c2.y + wb.y + gb.y);
    float k2 = tanhf(c2.z + wb.z + gb.z), k3 = tanhf(c2.w + wb.w + gb.w);
    float4 gws = *(const float4*)(gate_w + c);
    float4 gwk = *(const float4*)(gate_w + D + c);
    float a = gws.x * s0 + gws.y * s1 + gws.z * s2 + gws.w * s3
            + gwk.x * k0 + gwk.y * k1 + gwk.z * k2 + gwk.w * k3;
    a = wred(a);
    float al = sigmf(a + gate_b[0]);
    float4 o;
    o.x = (1.f - al) * s0 + al * k0;
    o.y = (1.f - al) * s1 + al * k1;
    o.z = (1.f - al) * s2 + al * k2;
    o.w = (1.f - al) * s3 + al * k3;
    if (t < 2 * Bq) {
        int row = t & (Bq - 1);
        int half = t >> 11;
        *(float4*)(g_qn + (size_t)row * DM + half * D + c) = o;
        u32 h0, l0, h1, l1;
        splitpack(o.x, o.y, h0, l0);
        splitpack(o.z, o.w, h1, l1);
        int colu = (half * 128 + c) >> 1;
        g_qnhi[(size_t)row * 128 + colu]     = h0;
        g_qnhi[(size_t)row * 128 + colu + 1] = h1;
        g_qnlo[(size_t)row * 128 + colu]     = l0;
        g_qnlo[(size_t)row * 128 + colu + 1] = l1;
    } else {
        int t2 = t - 2 * Bq;
        int half = t2 / FEW, row = t2 % FEW;
        *(float4*)(g_sn + (size_t)row * DM + half * D + c) = o;
    }
}

// ================= weight preps =================
__global__ __launch_bounds__(256) void prep_wmma(
    const float* __restrict__ w, int ldw, u32* __restrict__ hi, u32* __restrict__ lo)
{
    int idx = blockIdx.x * 256 + threadIdx.x;
    int n = idx >> 7, kp = idx & 127;
    int srow = nperm_src(n);
    float v0 = w[(size_t)srow * ldw + 2 * kp];
    float v1 = w[(size_t)srow * ldw + 2 * kp + 1];
    u32 h, l;
    splitpack(v0, v1, h, l);
    hi[idx] = h; lo[idx] = l;
}

__global__ __launch_bounds__(256) void split_w(
    const float* __restrict__ w, int ldw, int off, int khalf,
    u32* __restrict__ hi, u32* __restrict__ lo)
{
    int idx = blockIdx.x * 256 + threadIdx.x;
    int n = idx / khalf, kp = idx % khalf;
    float v0 = w[(size_t)n * ldw + off + 2 * kp];
    float v1 = w[(size_t)n * ldw + off + 2 * kp + 1];
    u32 h, l;
    splitpack(v0, v1, h, l);
    hi[idx] = h; lo[idx] = l;
}

// ================= generic bf16-split mma GEMM =================
// MODE 0: dual (z selects set), f32 store, N=128
// MODE 1: relu(x+bias) -> split store (Chi/Clo), N=512
// MODE 2: x+bias+resid -> f32 store, N=256
template<int MODE>
__global__ __launch_bounds__(256) void mma_gemm(
    const u32* __restrict__ ahi, const u32* __restrict__ alo,
    const u32* __restrict__ whi, const u32* __restrict__ wlo,
    int K, int N,
    float* __restrict__ Cf, u32* __restrict__ Chi, u32* __restrict__ Clo,
    const float* __restrict__ bias, const float* __restrict__ resid,
    const u32* a2hi, const u32* a2lo, const u32* w2hi, const u32* w2lo,
    int K2, float* C2f)
{
    if (MODE == 0 && blockIdx.z == 1) {
        ahi = a2hi; alo = a2lo; whi = w2hi; wlo = w2lo; K = K2; Cf = C2f;
    }
    int khalf = K >> 1;
    int nchunks = K >> 4;
    __shared__ __align__(16) __nv_bfloat16 sAh[128][24], sAl[128][24], sWh[128][24], sWl[128][24];
    int tid = threadIdx.x, lane = tid & 31, w = tid >> 5;
    int bm = blockIdx.y * 128, bn = blockIdx.x * 128;
    int wm = (w >> 1) * 32, wn = (w & 1) * 64;

    float acc[2][8][4];
#pragma unroll
    for (int i = 0; i < 2; i++)
#pragma unroll
        for (int j = 0; j < 8; j++)
#pragma unroll
            for (int c = 0; c < 4; c++) acc[i][j][c] = 0.f;

    int lrow = tid >> 1, lseg = tid & 1;
    const uint4* gAh = (const uint4*)(ahi + (size_t)(bm + lrow) * khalf) + lseg;
    const uint4* gAl = (const uint4*)(alo + (size_t)(bm + lrow) * khalf) + lseg;
    const uint4* gWh = (const uint4*)(whi + (size_t)(bn + lrow) * khalf) + lseg;
    const uint4* gWl = (const uint4*)(wlo + (size_t)(bn + lrow) * khalf) + lseg;
    u32 soff = (u32)(lrow * 24 + lseg * 8) * 2;
    u32 bAh = smem_u32(sAh), bAl = smem_u32(sAl), bWh = smem_u32(sWh), bWl = smem_u32(sWl);

    u32 aoff[2];
#pragma unroll
    for (int mf = 0; mf < 2; mf++) {
        int row = wm + mf * 16 + (lane & 15);
        int col = (lane >> 4) * 8;
        aoff[mf] = (u32)(row * 24 + col) * 2;
    }
    u32 boff[4];
#pragma unroll
    for (int nf = 0; nf < 4; nf++) {
        int g = lane >> 3;
        int row = wn + nf * 16 + (lane & 7) + (g >> 1) * 8;
        int col = (g & 1) * 8;
        boff[nf] = (u32)(row * 24 + col) * 2;
    }

    for (int kc = 0; kc < nchunks; kc++) {
        uint4 vah = gAh[kc * 2], val = gAl[kc * 2], vwh = gWh[kc * 2], vwl = gWl[kc * 2];
        __syncthreads();
        *(uint4*)((char*)sAh + soff) = vah;
        *(uint4*)((char*)sAl + soff) = val;
        *(uint4*)((char*)sWh + soff) = vwh;
        *(uint4*)((char*)sWl + soff) = vwl;
        __syncthreads();

        u32 ah[2][4], al[2][4], wf[4][4];
        ldm4(ah[0], bAh + aoff[0]); ldm4(ah[1], bAh + aoff[1]);
        ldm4(al[0], bAl + aoff[0]); ldm4(al[1], bAl + aoff[1]);
#pragma unroll
        for (int nf = 0; nf < 4; nf++) ldm4(wf[nf], bWh + boff[nf]);
#pragma unroll
        for (int mf = 0; mf < 2; mf++)
#pragma unroll
            for (int nf = 0; nf < 4; nf++) {
                mma16816(acc[mf][nf * 2],     ah[mf], wf[nf]);
                mma16816(acc[mf][nf * 2 + 1], ah[mf], wf[nf] + 2);
                mma16816(acc[mf][nf * 2],     al[mf], wf[nf]);
                mma16816(acc[mf][nf * 2 + 1], al[mf], wf[nf] + 2);
            }
#pragma unroll
        for (int nf = 0; nf < 4; nf++) ldm4(wf[nf], bWl + boff[nf]);
#pragma unroll
        for (int mf = 0; mf < 2; mf++)
#pragma unroll
            for (int nf = 0; nf < 4; nf++) {
                mma16816(acc[mf][nf * 2],     ah[mf], wf[nf]);
                mma16816(acc[mf][nf * 2 + 1], ah[mf], wf[nf] + 2);
            }
    }

    int q = lane & 3, r4 = lane >> 2;
#pragma unroll
    for (int mf = 0; mf < 2; mf++)
#pragma unroll
        for (int p = 0; p < 4; p++)
#pragma unroll
            for (int s = 0; s < 2; s++) {
                int cb = bn + wn + p * 16 + s * 8 + 2 * q;
                float* A = acc[mf][2 * p + s];
#pragma unroll
                for (int rh = 0; rh < 2; rh++) {
                    size_t m = (size_t)(bm + wm + mf * 16 + r4 + rh * 8);
                    float v0 = A[rh * 2], v1 = A[rh * 2 + 1];
                    if (MODE == 0) {
                        *(float2*)(Cf + m * 128 + cb) = make_float2(v0, v1);
                    } else if (MODE == 1) {
                        v0 = fmaxf(v0 + bias[cb], 0.f);
                        v1 = fmaxf(v1 + bias[cb + 1], 0.f);
                        u32 h, l;
                        splitpack(v0, v1, h, l);
                        Chi[m * (N >> 1) + (cb >> 1)] = h;
                        Clo[m * (N >> 1) + (cb >> 1)] = l;
                    } else {
                        float2 r = *(const float2*)(resid + m * N + cb);
                        v0 += bias[cb] + r.x;
                        v1 += bias[cb + 1] + r.y;
                        *(float2*)(Cf + m * N + cb) = make_float2(v0, v1);
                    }
                }
            }
}

// ================= LSTM step: bf16-split mma.sync + fused gates =================
template<int FIRST, int LAST>
__global__ __launch_bounds__(256) void lstm_mma(
    const u32* __restrict__ ahi, const u32* __restrict__ alo,
    const u32* __restrict__ whi, const u32* __restrict__ wlo,
    float* __restrict__ qp, const float* __restrict__ pbias, const float* __restrict__ vr,
    float* __restrict__ cst, const float* __restrict__ qg,
    u32* __restrict__ ohi, u32* __restrict__ olo, float* __restrict__ of32)
{
    __shared__ __align__(16) __nv_bfloat16 sAh[128][24], sAl[128][24], sWh[128][24], sWl[128][24];
    int tid = threadIdx.x, lane = tid & 31, w = tid >> 5;
    int bm = blockIdx.y * 128, bn = blockIdx.x * 128;
    int wm = (w >> 1) * 32, wn = (w & 1) * 64;

    float acc[2][8][4];
#pragma unroll
    for (int i = 0; i < 2; i++)
#pragma unroll
        for (int j = 0; j < 8; j++)
#pragma unroll
            for (int c = 0; c < 4; c++) acc[i][j][c] = 0.f;

    int lrow = tid >> 1, lseg = tid & 1;
    const uint4* gAh = (const uint4*)(ahi + (size_t)(bm + lrow) * 128) + lseg;
    const uint4* gAl = (const uint4*)(alo + (size_t)(bm + lrow) * 128) + lseg;
    const uint4* gWh = (const uint4*)(whi + (size_t)(bn + lrow) * 128) + lseg;
    const uint4* gWl = (const uint4*)(wlo + (size_t)(bn + lrow) * 128) + lseg;
    u32 soff = (u32)(lrow * 24 + lseg * 8) * 2;
    u32 bAh = smem_u32(sAh), bAl = smem_u32(sAl), bWh = smem_u32(sWh), bWl = smem_u32(sWl);

    u32 aoff[2];
#pragma unroll
    for (int mf = 0; mf < 2; mf++) {
        int row = wm + mf * 16 + (lane & 15);
        int col = (lane >> 4) * 8;
        aoff[mf] = (u32)(row * 24 + col) * 2;
    }
    u32 boff[4];
#pragma unroll
    for (int nf = 0; nf < 4; nf++) {
        int g = lane >> 3;
        int row = wn + nf * 16 + (lane & 7) + (g >> 1) * 8;
        int col = (g & 1) * 8;
        boff[nf] = (u32)(row * 24 + col) * 2;
    }

    for (int kc = 0; kc < 16; kc++) {
        uint4 vah = gAh[kc * 2], val = gAl[kc * 2], vwh = gWh[kc * 2], vwl = gWl[kc * 2];
        __syncthreads();
        *(uint4*)((char*)sAh + soff) = vah;
        *(uint4*)((char*)sAl + soff) = val;
        *(uint4*)((char*)sWh + soff) = vwh;
        *(uint4*)((char*)sWl + soff) = vwl;
        __syncthreads();

        u32 ah[2][4], al[2][4], wf[4][4];
        ldm4(ah[0], bAh + aoff[0]); ldm4(ah[1], bAh + aoff[1]);
        ldm4(al[0], bAl + aoff[0]); ldm4(al[1], bAl + aoff[1]);
#pragma unroll
        for (int nf = 0; nf < 4; nf++) ldm4(wf[nf], bWh + boff[nf]);
#pragma unroll
        for (int mf = 0; mf < 2; mf++)
#pragma unroll
            for (int nf = 0; nf < 4; nf++) {
                mma16816(acc[mf][nf * 2],     ah[mf], wf[nf]);
                mma16816(acc[mf][nf * 2 + 1], ah[mf], wf[nf] + 2);
                mma16816(acc[mf][nf * 2],     al[mf], wf[nf]);
                mma16816(acc[mf][nf * 2 + 1], al[mf], wf[nf] + 2);
            }
#pragma unroll
        for (int nf = 0; nf < 4; nf++) ldm4(wf[nf], bWl + boff[nf]);
#pragma unroll
        for (int mf = 0; mf < 2; mf++)
#pragma unroll
            for (int nf = 0; nf < 4; nf++) {
                mma16816(acc[mf][nf * 2],     ah[mf], wf[nf]);
                mma16816(acc[mf][nf * 2 + 1], ah[mf], wf[nf] + 2);
            }
    }

    int q = lane & 3, r4 = lane >> 2;
#pragma unroll
    for (int mf = 0; mf < 2; mf++) {
#pragma unroll
        for (int p = 0; p < 4; p++) {
            int nblk = bn + wn + p * 16;
            int u = (nblk >> 4) * 4 + q;
            int n0 = nblk + 2 * q;
            float* A0 = acc[mf][2 * p];
            float* A1 = acc[mf][2 * p + 1];
#pragma unroll
            for (int rh = 0; rh < 2; rh++) {
                size_t m = (size_t)(bm + wm + mf * 16 + r4 + rh * 8);
                float iv = A0[rh * 2], fv = A0[rh * 2 + 1];
                float gv = A1[rh * 2], ov = A1[rh * 2 + 1];
                if (FIRST) {
                    iv += pbias[n0];     fv += pbias[n0 + 1];
                    gv += pbias[n0 + 8]; ov += pbias[n0 + 9];
                    *(float2*)(qp + m * GATES + n0)     = make_float2(iv, fv);
                    *(float2*)(qp + m * GATES + n0 + 8) = make_float2(gv, ov);
                } else {
                    float2 q1 = *(const float2*)(qp + m * GATES + n0);
                    float2 q2 = *(const float2*)(qp + m * GATES + n0 + 8);
                    iv += q1.x + vr[n0];     fv += q1.y + vr[n0 + 1];
                    gv += q2.x + vr[n0 + 8]; ov += q2.y + vr[n0 + 9];
                }
                float cc;
                if (FIRST) cc = sigmf(iv) * tanhf(gv);
                else       cc = sigmf(fv) * cst[m * HID + u] + sigmf(iv) * tanhf(gv);
                cst[m * HID + u] = cc;
                if (u < DM) {
                    float h = qg[m * DM + u] + sigmf(ov) * tanhf(cc);
                    if (LAST) {
                        of32[m * DM + u] = h;
                    } else {
                        __nv_bfloat16 hh = __float2bfloat16(h);
                        __nv_bfloat16 hl = __float2bfloat16(h - __bfloat162float(hh));
                        ((__nv_bfloat16*)ohi)[m * DM + u] = hh;
                        ((__nv_bfloat16*)olo)[m * DM + u] = hl;
                    }
                }
            }
        }
    }
}

// ================= support path =================
__global__ __launch_bounds__(256) void sup1_kernel(
    const float* __restrict__ p1_w, const float* __restrict__ p1_b)
{
    int lane = threadIdx.x & 31, wid = threadIdx.x >> 5;
    int w = blockIdx.x * 8 + wid;
    int r = w >> 9, u = w & (HID - 1);
    const float* wp = p1_w + (size_t)u * DM;
    const float* xp = g_sn + r * DM;
    float a = 0.f;
#pragma unroll
    for (int s = 0; s < 8; s++) a += wp[lane + 32 * s] * xp[lane + 32 * s];
    a = wred(a);
    if (lane == 0) g_shd[r * HID + u] = fmaxf(a + p1_b[u], 0.f);
}

__global__ __launch_bounds__(256) void sup2_kernel(
    const float* __restrict__ p2_w, const float* __restrict__ p2_b)
{
    int lane = threadIdx.x & 31, wid = threadIdx.x >> 5;
    int w = blockIdx.x * 8 + wid;
    int r = w >> 8, u = w & (DM - 1);
    const float* wp = p2_w + (size_t)u * HID;
    const float* xp = g_shd + r * HID;
    float a = 0.f;
#pragma unroll
    for (int s = 0; s < 16; s++) a += wp[lane + 32 * s] * xp[lane + 32 * s];
    a = wred(a);
    if (lane == 0) g_sz[r * DM + u] = a + p2_b[u] + g_sn[r * DM + u];
}

__global__ __launch_bounds__(256) void sup3_kernel(
    const float* __restrict__ ln_g, const float* __restrict__ ln_b)
{
    __shared__ float red[8];
    int tid = threadIdx.x, lane = tid & 31, wid = tid >> 5;
    float accg = 0.f;
    for (int r = 0; r < FEW; r++) {
        float z = g_sz[r * DM + tid];
        float s1 = wred(z);
        if (lane == 0) red[wid] = s1;
        __syncthreads();
        float mu = (red[0] + red[1] + red[2] + red[3] + red[4] + red[5] + red[6] + red[7]) * (1.f / DM);
        __syncthreads();
        float dz = z - mu;
        float s2 = wred(dz * dz);
        if (lane == 0) red[wid] = s2;
        __syncthreads();
        float sig = sqrtf((red[0] + red[1] + red[2] + red[3] + red[4] + red[5] + red[6] + red[7]) * (1.f / (DM - 1)));
        accg += dz / (sig + 1e-3f) * ln_g[tid] + ln_b[tid];
        __syncthreads();
    }
    float sg = accg * (1.f / FEW);
    g_sg[tid] = sg;
    float s3 = wred(sg * sg);
    if (lane == 0) red[wid] = s3;
    __syncthreads();
    float nrm = sqrtf(red[0] + red[1] + red[2] + red[3] + red[4] + red[5] + red[6] + red[7]);
    g_sgn[tid] = sg / fmaxf(nrm, 1e-12f);
}

__global__ __launch_bounds__(256) void vr_kernel(
    const float* __restrict__ w_hh,
    const float* __restrict__ b_ih, const float* __restrict__ b_hh)
{
    int lane = threadIdx.x & 31, wid = threadIdx.x >> 5;
    int n = blockIdx.x * 8 + wid;
    int p = nperm_src(n);
    const float* w = w_hh + (size_t)p * HID + DM;
    float a = 0.f;
#pragma unroll
    for (int s = 0; s < 8; s++) a += w[lane + 32 * s] * g_sg[lane + 32 * s];
    a = wred(a);
    if (lane == 0) {
        g_vr[n] = a;
        g_pb[n] = b_ih[p] + b_hh[p];
    }
}

__global__ __launch_bounds__(256) void ln_kernel(const float* __restrict__ ln_g,
                                                 const float* __restrict__ ln_b) {
    __shared__ float red[8];
    __shared__ float srow[DM];
    int row = blockIdx.x, tid = threadIdx.x, lane = tid & 31, wid = tid >> 5;
    float z = g_qg[(size_t)row * DM + tid];
    float s1 = wred(z);
    if (lane == 0) red[wid] = s1;
    __syncthreads();
    float mu = (red[0] + red[1] + red[2] + red[3] + red[4] + red[5] + red[6] + red[7]) * (1.f / DM);
    __syncthreads();
    float dz = z - mu;
    float s2 = wred(dz * dz);
    if (lane == 0) red[wid] = s2;
    __syncthreads();
    float sig = sqrtf((red[0] + red[1] + red[2] + red[3] + red[4] + red[5] + red[6] + red[7]) * (1.f / (DM - 1)));
    float o = dz / (sig + 1e-3f) * ln_g[tid] + ln_b[tid];
    g_qg[(size_t)row * DM + tid] = o;
    srow[tid] = o;
    __syncthreads();
    if (tid < 128) {
        u32 hi, lo;
        splitpack(srow[2 * tid], srow[2 * tid + 1], hi, lo);
        g_qghi[(size_t)row * 128 + tid] = hi;
        g_qglo[(size_t)row * 128 + tid] = lo;
    }
}

__global__ __launch_bounds__(256) void final_kernel(float* __restrict__ out) {
    int lane = threadIdx.x & 31, wid = threadIdx.x >> 5;
    int row = blockIdx.x * 8 + wid;
    const float* h = g_hb + (size_t)row * DM;
    float ss = 0.f, dt = 0.f;
#pragma unroll
    for (int s = 0; s < 8; s++) {
        float v = h[lane + 32 * s];
        ss += v * v;
        dt += v * g_sgn[lane + 32 * s];
    }
    ss = wred(ss); dt = wred(dt);
    if (lane == 0) out[row] = dt / fmaxf(sqrtf(ss), 1e-12f);
}

// ================= host =================
extern "C" void kernel_launch(void* const* d_in, const int* in_sizes, int n_in,
                              void* d_out, int out_size) {
    const int*   query   = (const int*)d_in[0];
    const int*   support = (const int*)d_in[1];
    const int*   qlc     = (const int*)d_in[2];
    const int*   qrc     = (const int*)d_in[4];
    const int*   slc     = (const int*)d_in[6];
    const int*   src_    = (const int*)d_in[8];
    const int*   knn     = (const int*)d_in[10];
    const float* emb     = (const float*)d_in[11];
    const float* gcn_w   = (const float*)d_in[12];
    const float* gcn_w_b = (const float*)d_in[13];
    const float* gcn_b   = (const float*)d_in[14];
    const float* gate_w  = (const float*)d_in[15];
    const float* gate_b  = (const float*)d_in[16];
    const float* p1_w    = (const float*)d_in[17];
    const float* p1_b    = (const float*)d_in[18];
    const float* p2_w    = (const float*)d_in[19];
    const float* p2_b    = (const float*)d_in[20];
    const float* ln_g    = (const float*)d_in[21];
    const float* ln_b    = (const float*)d_in[22];
    const float* w_ih    = (const float*)d_in[23];
    const float* w_hh    = (const float*)d_in[24];
    const float* b_ih    = (const float*)d_in[25];
    const float* b_hh    = (const float*)d_in[26];
    float* out = (float*)d_out;

    float *c1, *c2, *qn, *qg, *vr, *pb, *qp, *cst, *hb;
    u32 *wihh, *wihl, *whhh, *whhl, *qghi, *qglo, *hahi, *halo, *hbhi, *hblo;
    u32 *hshi, *hslo, *hkhi, *hklo, *qnhi, *qnlo, *acthi, *actlo;
    u32 *gwh, *gwl, *gkh, *gkl, *p1h, *p1l, *p2h, *p2l;
    cudaGetSymbolAddress((void**)&c1, g_c1);
    cudaGetSymbolAddress((void**)&c2, g_c2);
    cudaGetSymbolAddress((void**)&qn, g_qn);
    cudaGetSymbolAddress((void**)&qg, g_qg);
    cudaGetSymbolAddress((void**)&vr, g_vr);
    cudaGetSymbolAddress((void**)&pb, g_pb);
    cudaGetSymbolAddress((void**)&qp, g_qp);
    cudaGetSymbolAddress((void**)&cst, g_cst);
    cudaGetSymbolAddress((void**)&hb, g_hb);
    cudaGetSymbolAddress((void**)&wihh, g_wihh);
    cudaGetSymbolAddress((void**)&wihl, g_wihl);
    cudaGetSymbolAddress((void**)&whhh, g_whhh);
    cudaGetSymbolAddress((void**)&whhl, g_whhl);
    cudaGetSymbolAddress((void**)&qghi, g_qghi);
    cudaGetSymbolAddress((void**)&qglo, g_qglo);
    cudaGetSymbolAddress((void**)&hahi, g_hahi);
    cudaGetSymbolAddress((void**)&halo, g_halo);
    cudaGetSymbolAddress((void**)&hbhi, g_hbhi);
    cudaGetSymbolAddress((void**)&hblo, g_hblo);
    cudaGetSymbolAddress((void**)&hshi, g_hshi);
    cudaGetSymbolAddress((void**)&hslo, g_hslo);
    cudaGetSymbolAddress((void**)&hkhi, g_hkhi);
    cudaGetSymbolAddress((void**)&hklo, g_hklo);
    cudaGetSymbolAddress((void**)&qnhi, g_qnhi);
    cudaGetSymbolAddress((void**)&qnlo, g_qnlo);
    cudaGetSymbolAddress((void**)&acthi, g_acthi);
    cudaGetSymbolAddress((void**)&actlo, g_actlo);
    cudaGetSymbolAddress((void**)&gwh, g_gwh);
    cudaGetSymbolAddress((void**)&gwl, g_gwl);
    cudaGetSymbolAddress((void**)&gkh, g_gkh);
    cudaGetSymbolAddress((void**)&gkl, g_gkl);
    cudaGetSymbolAddress((void**)&p1h, g_p1h);
    cudaGetSymbolAddress((void**)&p1l, g_p1l);
    cudaGetSymbolAddress((void**)&p2h, g_p2h);
    cudaGetSymbolAddress((void**)&p2l, g_p2l);

    prep_wmma<<<GATES * 128 / 256, 256>>>(w_ih, DM, wihh, wihl);
    prep_wmma<<<GATES * 128 / 256, 256>>>(w_hh, HID, whhh, whhl);
    split_w<<<64, 256>>>(gcn_w, 256, 0, 128, gwh, gwl);
    split_w<<<32, 256>>>(gcn_w, 256, 128, 64, gkh, gkl);
    split_w<<<256, 256>>>(p1_w, 256, 0, 128, p1h, p1l);
    split_w<<<256, 256>>>(p2_w, 512, 0, 256, p2h, p2l);

    neigh_gather<<<NTASK, 256>>>(query, support, qlc, qrc, slc, src_, knn, emb);
    mma_gemm<0><<<dim3(1, TPAD / 128, 2), 256>>>(
        hshi, hslo, gwh, gwl, 256, 128, c1, nullptr, nullptr, nullptr, nullptr,
        hkhi, hklo, gkh, gkl, 128, c2);
    combine_kernel<<<(NTASK + 7) / 8, 256>>>(gcn_w_b, gcn_b, gate_w, gate_b);
    sup1_kernel<<<FEW * HID / 8, 256>>>(p1_w, p1_b);
    sup2_kernel<<<FEW * DM / 8, 256>>>(p2_w, p2_b);
    sup3_kernel<<<1, 256>>>(ln_g, ln_b);
    vr_kernel<<<GATES / 8, 256>>>(w_hh, b_ih, b_hh);
    mma_gemm<1><<<dim3(4, Bq / 128), 256>>>(
        qnhi, qnlo, p1h, p1l, 256, 512, nullptr, acthi, actlo, p1_b, nullptr,
        nullptr, nullptr, nullptr, nullptr, 0, nullptr);
    mma_gemm<2><<<dim3(2, Bq / 128), 256>>>(
        acthi, actlo, p2h, p2l, 512, 256, qg, nullptr, nullptr, p2_b, qn,
        nullptr, nullptr, nullptr, nullptr, 0, nullptr);
    ln_kernel<<<Bq, 256>>>(ln_g, ln_b);
    lstm_mma<1, 0><<<dim3(16, 16), 256>>>(qghi, qglo, wihh, wihl, qp, pb, vr, cst, qg,
                                          hahi, halo, nullptr);
    lstm_mma<0, 0><<<dim3(16, 16), 256>>>(hahi, halo, whhh, whhl, qp, pb, vr, cst, qg,
                                          hbhi, hblo, nullptr);
    lstm_mma<0, 0><<<dim3(16, 16), 256>>>(hbhi, hblo, whhh, whhl, qp, pb, vr, cst, qg,
                                          hahi, halo, nullptr);
    lstm_mma<0, 1><<<dim3(16, 16), 256>>>(hahi, halo, whhh, whhl, qp, pb, vr, cst, qg,
                                          nullptr, nullptr, hb);
    final_kernel<<<Bq / 8, 256>>>(out);
}

// round 8
// speedup vs baseline: 1.3003x; 1.0383x over previous
#include <cuda_runtime.h>
#include <cuda_bf16.h>
#include <math.h>
#include <cstdint>

#define D     128
#define Mn    128
#define KTAB  64
#define KSEL  32
#define Bq    2048
#define FEW   5
#define DM    256
#define HID   512
#define GATES 2048
#define NTASK (2 * Bq + 2 * FEW)
#define TPAD  4224

typedef unsigned long long ull;
typedef unsigned int u32;

// ================= scratch =================
__device__ __align__(128) float g_qn[Bq * DM];
__device__ __align__(128) float g_sn[FEW * DM];
__device__ __align__(128) float g_shd[FEW * HID];
__device__ __align__(128) float g_sz[FEW * DM];
__device__ __align__(128) float g_qg[Bq * DM];
__device__ __align__(128) float g_sg[DM];
__device__ __align__(128) float g_sgn[DM];
__device__ __align__(128) float g_vr[GATES];
__device__ __align__(128) float g_pb[GATES];
__device__ __align__(128) float g_qp[(size_t)Bq * GATES];
__device__ __align__(128) float g_cst[Bq * HID];
__device__ __align__(128) float g_hb[Bq * DM];
__device__ __align__(128) u32 g_hshi[TPAD * 128];
__device__ __align__(128) u32 g_hslo[TPAD * 128];
__device__ __align__(128) u32 g_hkhi[TPAD * 64];
__device__ __align__(128) u32 g_hklo[TPAD * 64];
__device__ __align__(128) u32 g_qnhi[Bq * 128];
__device__ __align__(128) u32 g_qnlo[Bq * 128];
__device__ __align__(128) u32 g_acthi[Bq * 256];
__device__ __align__(128) u32 g_actlo[Bq * 256];
__device__ __align__(128) u32 g_qghi[Bq * 128];
__device__ __align__(128) u32 g_qglo[Bq * 128];
__device__ __align__(128) u32 g_hahi[Bq * 128];
__device__ __align__(128) u32 g_halo[Bq * 128];
__device__ __align__(128) u32 g_hbhi[Bq * 128];
__device__ __align__(128) u32 g_hblo[Bq * 128];
__device__ __align__(128) u32 g_wihh[GATES * 128];
__device__ __align__(128) u32 g_wihl[GATES * 128];
__device__ __align__(128) u32 g_whhh[GATES * 128];
__device__ __align__(128) u32 g_whhl[GATES * 128];
__device__ __align__(128) u32 g_gwh[128 * 128];
__device__ __align__(128) u32 g_gwl[128 * 128];
__device__ __align__(128) u32 g_gkh[128 * 64];
__device__ __align__(128) u32 g_gkl[128 * 64];
__device__ __align__(128) u32 g_p1h[512 * 128];
__device__ __align__(128) u32 g_p1l[512 * 128];
__device__ __align__(128) u32 g_p2h[256 * 256];
__device__ __align__(128) u32 g_p2l[256 * 256];

__device__ __forceinline__ float wred(float v) {
#pragma unroll
    for (int o = 16; o; o >>= 1) v += __shfl_xor_sync(0xffffffffu, v, o);
    return v;
}
__device__ __forceinline__ float sigmf(float x) { return 1.f / (1.f + expf(-x)); }
__device__ __forceinline__ void splitpack(float a, float b, u32& hi, u32& lo) {
    __nv_bfloat16 ha = __float2bfloat16(a), hb2 = __float2bfloat16(b);
    __nv_bfloat16 la = __float2bfloat16(a - __bfloat162float(ha));
    __nv_bfloat16 lb = __float2bfloat16(b - __bfloat162float(hb2));
    __nv_bfloat162 H; H.x = ha; H.y = hb2;
    __nv_bfloat162 L; L.x = la; L.y = lb;
    hi = *(u32*)&H; lo = *(u32*)&L;
}
__device__ __forceinline__ int nperm_src(int n) {
    int b = n >> 4, r = n & 15;
    int v = (r & 7) >> 1;
    int g = (r >> 3) * 2 + (r & 1);
    return g * 512 + b * 4 + v;
}
__device__ __forceinline__ u32 smem_u32(const void* p) {
    u32 a;
    asm("{ .reg .u64 t; cvta.to.shared.u64 t, %1; cvt.u32.u64 %0, t; }" : "=r"(a) : "l"(p));
    return a;
}
__device__ __forceinline__ void ldm4(u32* r, u32 addr) {
    asm volatile("ldmatrix.sync.aligned.m8n8.x4.shared.b16 {%0,%1,%2,%3}, [%4];"
                 : "=r"(r[0]), "=r"(r[1]), "=r"(r[2]), "=r"(r[3]) : "r"(addr));
}
__device__ __forceinline__ void mma16816(float* d, const u32* a, const u32* b) {
    asm volatile("mma.sync.aligned.m16n8k16.row.col.f32.bf16.bf16.f32 "
                 "{%0,%1,%2,%3},{%4,%5,%6,%7},{%8,%9},{%0,%1,%2,%3};"
                 : "+f"(d[0]), "+f"(d[1]), "+f"(d[2]), "+f"(d[3])
                 : "r"(a[0]), "r"(a[1]), "r"(a[2]), "r"(a[3]), "r"(b[0]), "r"(b[1]));
}

// ================= neighbor gather =================
__global__ __launch_bounds__(256) void neigh_gather(
    const int* __restrict__ query, const int* __restrict__ support,
    const int* __restrict__ qlc, const int* __restrict__ qrc,
    const int* __restrict__ slc, const int* __restrict__ src_,
    const int* __restrict__ knn, const float* __restrict__ emb)
{
    __shared__ float s_center[D];
    __shared__ int   s_rid[Mn], s_eid[Mn];
    __shared__ float s_sim[Mn];
    __shared__ int   s_kid[KTAB];
    __shared__ float s_ksim[KTAB];
    __shared__ int   s_selr[KSEL], s_sele[KSEL], s_kselv[KSEL];
    __shared__ int   s_cnt, s_kcnt;
    __shared__ float s_cn;
    __shared__ float e_hs[DM];
    __shared__ float e_hk[D];

    int task = blockIdx.x;
    const int* conn; int id;
    if (task < 2 * Bq) {
        int row = task & (Bq - 1);
        int br  = task >> 11;
        conn = (br ? qrc : qlc) + (size_t)row * Mn * 2;
        id   = query[row * 2 + br];
    } else {
        int t = task - 2 * Bq;
        int br = t / FEW, row = t % FEW;
        conn = (br ? src_ : slc) + (size_t)row * Mn * 2;
        id   = support[row * 2 + br];
    }
    int tid = threadIdx.x, lane = tid & 31, wid = tid >> 5;
    if (tid == 0) { s_cnt = 0; s_kcnt = 0; }
    if (tid < D)  s_center[tid] = emb[(size_t)id * D + tid];
    if (tid < Mn) { s_rid[tid] = conn[tid * 2]; s_eid[tid] = conn[tid * 2 + 1]; }
    if (tid >= 192) s_kid[tid - 192] = knn[(size_t)id * KTAB + (tid - 192)];
    __syncthreads();

    if (wid == 0) {
        float c0 = s_center[lane], c1 = s_center[lane + 32],
              c2 = s_center[lane + 64], c3 = s_center[lane + 96];
        float s = wred(c0 * c0 + c1 * c1 + c2 * c2 + c3 * c3);
        if (lane == 0) s_cn = sqrtf(s);
    }
    __syncthreads();
    float cn = s_cn;
    float4 cv = ((const float4*)s_center)[lane];

#pragma unroll
    for (int g = 0; g < 4; g++) {
        int m = wid * 16 + g * 4;
        float dt[4], nn[4];
#pragma unroll
        for (int t = 0; t < 4; t++) {
            float4 ev = ((const float4*)(emb + (size_t)s_eid[m + t] * D))[lane];
            dt[t] = ev.x * cv.x + ev.y * cv.y + ev.z * cv.z + ev.w * cv.w;
            nn[t] = ev.x * ev.x + ev.y * ev.y + ev.z * ev.z + ev.w * ev.w;
        }
#pragma unroll
        for (int o = 16; o; o >>= 1) {
#pragma unroll
            for (int t = 0; t < 4; t++) {
                dt[t] += __shfl_xor_sync(0xffffffffu, dt[t], o);
                nn[t] += __shfl_xor_sync(0xffffffffu, nn[t], o);
            }
        }
        if (lane == 0) {
#pragma unroll
            for (int t = 0; t < 4; t++)
                s_sim[m + t] = dt[t] / fmaxf(cn * sqrtf(nn[t]), 1e-8f);
        }
    }
#pragma unroll
    for (int g = 0; g < 2; g++) {
        int m = wid * 8 + g * 4;
        float dt[4], nn[4];
#pragma unroll
        for (int t = 0; t < 4; t++) {
            float4 ev = ((const float4*)(emb + (size_t)s_kid[m + t] * D))[lane];
            dt[t] = ev.x * cv.x + ev.y * cv.y + ev.z * cv.z + ev.w * cv.w;
            nn[t] = ev.x * ev.x + ev.y * ev.y + ev.z * ev.z + ev.w * ev.w;
        }
#pragma unroll
        for (int o = 16; o; o >>= 1) {
#pragma unroll
            for (int t = 0; t < 4; t++) {
                dt[t] += __shfl_xor_sync(0xffffffffu, dt[t], o);
                nn[t] += __shfl_xor_sync(0xffffffffu, nn[t], o);
            }
        }
        if (lane == 0) {
#pragma unroll
            for (int t = 0; t < 4; t++)
                s_ksim[m + t] = dt[t] / fmaxf(cn * sqrtf(nn[t]), 1e-8f);
        }
    }
    __syncthreads();

    if (tid < Mn) {
        float v = s_sim[tid]; int r = 0;
        for (int j = 0; j < Mn; j++) {
            float u = s_sim[j];
            r += (u > v) || (u == v && j < tid);
        }
        if (r < KSEL) {
            int p = atomicAdd(&s_cnt, 1);
            s_selr[p] = s_rid[tid];
            s_sele[p] = s_eid[tid];
        }
    } else if (tid < Mn + KTAB) {
        int m = tid - Mn;
        float v = s_ksim[m]; int r = 0;
        for (int j = 0; j < KTAB; j++) {
            float u = s_ksim[j];
            r += (u > v) || (u == v && j < m);
        }
        if (r < KSEL) {
            int p = atomicAdd(&s_kcnt, 1);
            s_kselv[p] = s_kid[m];
        }
    }
    __syncthreads();

    int d = tid & (D - 1);
    float acc = 0.f;
    if (tid < D) {
#pragma unroll 8
        for (int i = 0; i < KSEL; i++) acc += emb[(size_t)s_selr[i] * D + d];
        e_hs[d] = acc * (1.f / KSEL);
        float ak = 0.f;
#pragma unroll 8
        for (int i = 0; i < KSEL; i++) ak += emb[(size_t)s_kselv[i] * D + d];
        e_hk[d] = ak * (1.f / KSEL);
    } else {
#pragma unroll 8
        for (int i = 0; i < KSEL; i++) acc += emb[(size_t)s_sele[i] * D + d];
        e_hs[D + d] = acc * (1.f / KSEL);
    }
    __syncthreads();
    if (tid < 128) {
        u32 hi, lo;
        splitpack(e_hs[2 * tid], e_hs[2 * tid + 1], hi, lo);
        g_hshi[(size_t)task * 128 + tid] = hi;
        g_hslo[(size_t)task * 128 + tid] = lo;
    } else if (tid < 192) {
        int t2 = tid - 128;
        u32 hi, lo;
        splitpack(e_hk[2 * t2], e_hk[2 * t2 + 1], hi, lo);
        g_hkhi[(size_t)task * 64 + t2] = hi;
        g_hklo[(size_t)task * 64 + t2] = lo;
    }
}

// ================= merged weight prep =================
__device__ __forceinline__ void prep_perm_body(int idx, const float* w, int ldw,
                                               u32* hi, u32* lo) {
    int n = idx >> 7, kp = idx & 127;
    int srow = nperm_src(n);
    float v0 = w[(size_t)srow * ldw + 2 * kp];
    float v1 = w[(size_t)srow * ldw + 2 * kp + 1];
    u32 h, l;
    splitpack(v0, v1, h, l);
    hi[idx] = h; lo[idx] = l;
}
__device__ __forceinline__ void split_body(int idx, const float* w, int ldw, int off,
                                           int khalf, u32* hi, u32* lo) {
    int n = idx / khalf, kp = idx % khalf;
    float v0 = w[(size_t)n * ldw + off + 2 * kp];
    float v1 = w[(size_t)n * ldw + off + 2 * kp + 1];
    u32 h, l;
    splitpack(v0, v1, h, l);
    hi[idx] = h; lo[idx] = l;
}
__global__ __launch_bounds__(256) void prep_all(
    const float* __restrict__ w_ih, const float* __restrict__ w_hh,
    const float* __restrict__ gcn_w, const float* __restrict__ p1_w,
    const float* __restrict__ p2_w)
{
    int b = blockIdx.x, tid = threadIdx.x;
    if (b < 1024)       prep_perm_body(b * 256 + tid, w_ih, DM, g_wihh, g_wihl);
    else if (b < 2048)  prep_perm_body((b - 1024) * 256 + tid, w_hh, HID, g_whhh, g_whhl);
    else if (b < 2112)  split_body((b - 2048) * 256 + tid, gcn_w, 256, 0, 128, g_gwh, g_gwl);
    else if (b < 2144)  split_body((b - 2112) * 256 + tid, gcn_w, 256, 128, 64, g_gkh, g_gkl);
    else if (b < 2400)  split_body((b - 2144) * 256 + tid, p1_w, 256, 0, 128, g_p1h, g_p1l);
    else                split_body((b - 2400) * 256 + tid, p2_w, 512, 0, 256, g_p2h, g_p2l);
}

// ================= pipelined mma mainloop macro =================
// Stages chunk kc's 4 uint4s (already in nah/nal/nwh/nwl), prefetches kc+1,
// then runs 3-pass bf16-split mma into ACC.
#define MMA_CHUNK(ACC, NCH) \
    for (int kc = 0; kc < (NCH); kc++) { \
        __syncthreads(); \
        *(uint4*)((char*)sAh + soff) = nah; \
        *(uint4*)((char*)sAl + soff) = nal; \
        *(uint4*)((char*)sWh + soff) = nwh; \
        *(uint4*)((char*)sWl + soff) = nwl; \
        __syncthreads(); \
        if (kc + 1 < (NCH)) { \
            nah = gAh[(kc + 1) * 2]; nal = gAl[(kc + 1) * 2]; \
            nwh = gWh[(kc + 1) * 2]; nwl = gWl[(kc + 1) * 2]; \
        } \
        u32 ah[2][4], al[2][4], wf[4][4]; \
        ldm4(ah[0], bAh + aoff[0]); ldm4(ah[1], bAh + aoff[1]); \
        ldm4(al[0], bAl + aoff[0]); ldm4(al[1], bAl + aoff[1]); \
        _Pragma("unroll") \
        for (int nf = 0; nf < 4; nf++) ldm4(wf[nf], bWh + boff[nf]); \
        _Pragma("unroll") \
        for (int mf = 0; mf < 2; mf++) \
            _Pragma("unroll") \
            for (int nf = 0; nf < 4; nf++) { \
                mma16816(ACC[mf][nf * 2],     ah[mf], wf[nf]); \
                mma16816(ACC[mf][nf * 2 + 1], ah[mf], wf[nf] + 2); \
                mma16816(ACC[mf][nf * 2],     al[mf], wf[nf]); \
                mma16816(ACC[mf][nf * 2 + 1], al[mf], wf[nf] + 2); \
            } \
        _Pragma("unroll") \
        for (int nf = 0; nf < 4; nf++) ldm4(wf[nf], bWl + boff[nf]); \
        _Pragma("unroll") \
        for (int mf = 0; mf < 2; mf++) \
            _Pragma("unroll") \
            for (int nf = 0; nf < 4; nf++) { \
                mma16816(ACC[mf][nf * 2],     ah[mf], wf[nf]); \
                mma16816(ACC[mf][nf * 2 + 1], ah[mf], wf[nf] + 2); \
            } \
    }

#define MMA_PROLOGUE() \
    int tid = threadIdx.x, lane = tid & 31, w = tid >> 5; \
    int wm = (w >> 1) * 32, wn = (w & 1) * 64; \
    int lrow = tid >> 1, lseg = tid & 1; \
    u32 soff = (u32)(lrow * 24 + lseg * 8) * 2; \
    u32 bAh = smem_u32(sAh), bAl = smem_u32(sAl), bWh = smem_u32(sWh), bWl = smem_u32(sWl); \
    u32 aoff[2]; \
    _Pragma("unroll") \
    for (int mf = 0; mf < 2; mf++) { \
        int row = wm + mf * 16 + (lane & 15); \
        int col = (lane >> 4) * 8; \
        aoff[mf] = (u32)(row * 24 + col) * 2; \
    } \
    u32 boff[4]; \
    _Pragma("unroll") \
    for (int nf = 0; nf < 4; nf++) { \
        int g = lane >> 3; \
        int row = wn + nf * 16 + (lane & 7) + (g >> 1) * 8; \
        int col = (g & 1) * 8; \
        boff[nf] = (u32)(row * 24 + col) * 2; \
    }

// ================= fused GCN dual GEMM + combine =================
__global__ __launch_bounds__(256) void gcn_fused(
    const float* __restrict__ gcn_w_b, const float* __restrict__ gcn_b,
    const float* __restrict__ gate_w, const float* __restrict__ gate_b)
{
    __shared__ __align__(16) __nv_bfloat16 sAh[128][24], sAl[128][24], sWh[128][24], sWl[128][24];
    __shared__ float s_part[16][32];
    MMA_PROLOGUE();
    int bm = blockIdx.x * 128;

    float acc1[2][8][4], acc2[2][8][4];
#pragma unroll
    for (int i = 0; i < 2; i++)
#pragma unroll
        for (int j = 0; j < 8; j++)
#pragma unroll
            for (int c = 0; c < 4; c++) { acc1[i][j][c] = 0.f; acc2[i][j][c] = 0.f; }

    // pass 1: c1 = hs @ gcn_w[:, :256]ᵀ   (K=256)
    {
        const uint4* gAh = (const uint4*)(g_hshi + (size_t)(bm + lrow) * 128) + lseg;
        const uint4* gAl = (const uint4*)(g_hslo + (size_t)(bm + lrow) * 128) + lseg;
        const uint4* gWh = (const uint4*)(g_gwh + (size_t)lrow * 128) + lseg;
        const uint4* gWl = (const uint4*)(g_gwl + (size_t)lrow * 128) + lseg;
        uint4 nah = gAh[0], nal = gAl[0], nwh = gWh[0], nwl = gWl[0];
        MMA_CHUNK(acc1, 16);
    }
    // pass 2: c2 = hk @ gcn_w[:, 128:256]ᵀ  (K=128)
    {
        const uint4* gAh = (const uint4*)(g_hkhi + (size_t)(bm + lrow) * 64) + lseg;
        const uint4* gAl = (const uint4*)(g_hklo + (size_t)(bm + lrow) * 64) + lseg;
        const uint4* gWh = (const uint4*)(g_gkh + (size_t)lrow * 64) + lseg;
        const uint4* gWl = (const uint4*)(g_gkl + (size_t)lrow * 64) + lseg;
        uint4 nah = gAh[0], nal = gAl[0], nwh = gWh[0], nwl = gWl[0];
        MMA_CHUNK(acc2, 8);
    }

    int q = lane & 3, r4 = lane >> 2;
    // tanh transform + per-thread gate-dot partials
    float part[2][2];
#pragma unroll
    for (int mf = 0; mf < 2; mf++)
#pragma unroll
        for (int rh = 0; rh < 2; rh++) part[mf][rh] = 0.f;
#pragma unroll
    for (int p = 0; p < 4; p++)
#pragma unroll
        for (int s = 0; s < 2; s++)
#pragma unroll
            for (int c = 0; c < 2; c++) {
                int col = wn + p * 16 + s * 8 + 2 * q + c;
                float wbgb = gcn_w_b[col] + gcn_b[col];
                float gws = gate_w[col], gwk = gate_w[D + col];
#pragma unroll
                for (int mf = 0; mf < 2; mf++)
#pragma unroll
                    for (int rh = 0; rh < 2; rh++) {
                        float sv = tanhf(acc1[mf][2 * p + s][rh * 2 + c] + wbgb);
                        float kv = tanhf(acc2[mf][2 * p + s][rh * 2 + c] + wbgb);
                        acc1[mf][2 * p + s][rh * 2 + c] = sv;
                        acc2[mf][2 * p + s][rh * 2 + c] = kv;
                        part[mf][rh] += gws * sv + gwk * kv;
                    }
            }
    // reduce over q lanes (deterministic)
#pragma unroll
    for (int mf = 0; mf < 2; mf++)
#pragma unroll
        for (int rh = 0; rh < 2; rh++) {
            float v = part[mf][rh];
            v += __shfl_xor_sync(0xffffffffu, v, 1);
            v += __shfl_xor_sync(0xffffffffu, v, 2);
            part[mf][rh] = v;
        }
    if (q == 0) {
#pragma unroll
        for (int mf = 0; mf < 2; mf++)
#pragma unroll
            for (int rh = 0; rh < 2; rh++)
                s_part[w][mf * 16 + rh * 8 + r4] = part[mf][rh];
    }
    __syncthreads();
    float gb0 = gate_b[0];
#pragma unroll
    for (int mf = 0; mf < 2; mf++)
#pragma unroll
        for (int rh = 0; rh < 2; rh++) {
            int rl = mf * 16 + rh * 8 + r4;
            float tot = s_part[(w >> 1) * 2][rl] + s_part[(w >> 1) * 2 + 1][rl];
            float al = sigmf(tot + gb0);
            int t = bm + wm + mf * 16 + r4 + rh * 8;
#pragma unroll
            for (int p = 0; p < 4; p++)
#pragma unroll
                for (int s = 0; s < 2; s++) {
                    int col = wn + p * 16 + s * 8 + 2 * q;
                    float o0 = (1.f - al) * acc1[mf][2 * p + s][rh * 2]
                             + al * acc2[mf][2 * p + s][rh * 2];
                    float o1 = (1.f - al) * acc1[mf][2 * p + s][rh * 2 + 1]
                             + al * acc2[mf][2 * p + s][rh * 2 + 1];
                    if (t < 2 * Bq) {
                        int rowq = t & (Bq - 1);
                        int colq = (t >> 11) * 128 + col;
                        *(float2*)(g_qn + (size_t)rowq * DM + colq) = make_float2(o0, o1);
                        u32 h, l;
                        splitpack(o0, o1, h, l);
                        g_qnhi[(size_t)rowq * 128 + (colq >> 1)] = h;
                        g_qnlo[(size_t)rowq * 128 + (colq >> 1)] = l;
                    } else if (t < NTASK) {
                        int t2 = t - 2 * Bq;
                        *(float2*)(g_sn + (size_t)(t2 % FEW) * DM + (t2 / FEW) * 128 + col) =
                            make_float2(o0, o1);
                    }
                }
        }
}

// ================= generic bf16-split mma GEMM (MODE 1: relu->split, 2: +resid f32) =================
template<int MODE>
__global__ __launch_bounds__(256) void mma_gemm(
    const u32* __restrict__ ahi, const u32* __restrict__ alo,
    const u32* __restrict__ whi, const u32* __restrict__ wlo,
    int K, int N,
    float* __restrict__ Cf, u32* __restrict__ Chi, u32* __restrict__ Clo,
    const float* __restrict__ bias, const float* __restrict__ resid)
{
    int khalf = K >> 1;
    int nchunks = K >> 4;
    __shared__ __align__(16) __nv_bfloat16 sAh[128][24], sAl[128][24], sWh[128][24], sWl[128][24];
    MMA_PROLOGUE();
    int bm = blockIdx.y * 128, bn = blockIdx.x * 128;

    float acc[2][8][4];
#pragma unroll
    for (int i = 0; i < 2; i++)
#pragma unroll
        for (int j = 0; j < 8; j++)
#pragma unroll
            for (int c = 0; c < 4; c++) acc[i][j][c] = 0.f;

    const uint4* gAh = (const uint4*)(ahi + (size_t)(bm + lrow) * khalf) + lseg;
    const uint4* gAl = (const uint4*)(alo + (size_t)(bm + lrow) * khalf) + lseg;
    const uint4* gWh = (const uint4*)(whi + (size_t)(bn + lrow) * khalf) + lseg;
    const uint4* gWl = (const uint4*)(wlo + (size_t)(bn + lrow) * khalf) + lseg;
    uint4 nah = gAh[0], nal = gAl[0], nwh = gWh[0], nwl = gWl[0];
    MMA_CHUNK(acc, nchunks);

    int q = lane & 3, r4 = lane >> 2;
#pragma unroll
    for (int mf = 0; mf < 2; mf++)
#pragma unroll
        for (int p = 0; p < 4; p++)
#pragma unroll
            for (int s = 0; s < 2; s++) {
                int cb = bn + wn + p * 16 + s * 8 + 2 * q;
                float* A = acc[mf][2 * p + s];
#pragma unroll
                for (int rh = 0; rh < 2; rh++) {
                    size_t m = (size_t)(bm + wm + mf * 16 + r4 + rh * 8);
                    float v0 = A[rh * 2], v1 = A[rh * 2 + 1];
                    if (MODE == 1) {
                        v0 = fmaxf(v0 + bias[cb], 0.f);
                        v1 = fmaxf(v1 + bias[cb + 1], 0.f);
                        u32 h, l;
                        splitpack(v0, v1, h, l);
                        Chi[m * (N >> 1) + (cb >> 1)] = h;
                        Clo[m * (N >> 1) + (cb >> 1)] = l;
                    } else {
                        float2 r = *(const float2*)(resid + m * N + cb);
                        v0 += bias[cb] + r.x;
                        v1 += bias[cb + 1] + r.y;
                        *(float2*)(Cf + m * N + cb) = make_float2(v0, v1);
                    }
                }
            }
}

// ================= LSTM step =================
template<int FIRST, int LAST>
__global__ __launch_bounds__(256) void lstm_mma(
    const u32* __restrict__ ahi, const u32* __restrict__ alo,
    const u32* __restrict__ whi, const u32* __restrict__ wlo,
    float* __restrict__ qp, const float* __restrict__ pbias, const float* __restrict__ vr,
    float* __restrict__ cst, const float* __restrict__ qg,
    u32* __restrict__ ohi, u32* __restrict__ olo, float* __restrict__ of32)
{
    __shared__ __align__(16) __nv_bfloat16 sAh[128][24], sAl[128][24], sWh[128][24], sWl[128][24];
    MMA_PROLOGUE();
    int bm = blockIdx.y * 128, bn = blockIdx.x * 128;

    float acc[2][8][4];
#pragma unroll
    for (int i = 0; i < 2; i++)
#pragma unroll
        for (int j = 0; j < 8; j++)
#pragma unroll
            for (int c = 0; c < 4; c++) acc[i][j][c] = 0.f;

    const uint4* gAh = (const uint4*)(ahi + (size_t)(bm + lrow) * 128) + lseg;
    const uint4* gAl = (const uint4*)(alo + (size_t)(bm + lrow) * 128) + lseg;
    const uint4* gWh = (const uint4*)(whi + (size_t)(bn + lrow) * 128) + lseg;
    const uint4* gWl = (const uint4*)(wlo + (size_t)(bn + lrow) * 128) + lseg;
    uint4 nah = gAh[0], nal = gAl[0], nwh = gWh[0], nwl = gWl[0];
    MMA_CHUNK(acc, 16);

    int q = lane & 3, r4 = lane >> 2;
#pragma unroll
    for (int mf = 0; mf < 2; mf++) {
#pragma unroll
        for (int p = 0; p < 4; p++) {
            int nblk = bn + wn + p * 16;
            int u = (nblk >> 4) * 4 + q;
            int n0 = nblk + 2 * q;
            float* A0 = acc[mf][2 * p];
            float* A1 = acc[mf][2 * p + 1];
#pragma unroll
            for (int rh = 0; rh < 2; rh++) {
                size_t m = (size_t)(bm + wm + mf * 16 + r4 + rh * 8);
                float iv = A0[rh * 2], fv = A0[rh * 2 + 1];
                float gv = A1[rh * 2], ov = A1[rh * 2 + 1];
                if (FIRST) {
                    iv += pbias[n0];     fv += pbias[n0 + 1];
                    gv += pbias[n0 + 8]; ov += pbias[n0 + 9];
                    *(float2*)(qp + m * GATES + n0)     = make_float2(iv, fv);
                    *(float2*)(qp + m * GATES + n0 + 8) = make_float2(gv, ov);
                } else {
                    float2 q1 = *(const float2*)(qp + m * GATES + n0);
                    float2 q2 = *(const float2*)(qp + m * GATES + n0 + 8);
                    iv += q1.x + vr[n0];     fv += q1.y + vr[n0 + 1];
                    gv += q2.x + vr[n0 + 8]; ov += q2.y + vr[n0 + 9];
                }
                float cc;
                if (FIRST) cc = sigmf(iv) * tanhf(gv);
                else       cc = sigmf(fv) * cst[m * HID + u] + sigmf(iv) * tanhf(gv);
                cst[m * HID + u] = cc;
                if (u < DM) {
                    float h = qg[m * DM + u] + sigmf(ov) * tanhf(cc);
                    if (LAST) {
                        of32[m * DM + u] = h;
                    } else {
                        __nv_bfloat16 hh = __float2bfloat16(h);
                        __nv_bfloat16 hl = __float2bfloat16(h - __bfloat162float(hh));
                        ((__nv_bfloat16*)ohi)[m * DM + u] = hh;
                        ((__nv_bfloat16*)olo)[m * DM + u] = hl;
                    }
                }
            }
        }
    }
}

// ================= support path =================
__global__ __launch_bounds__(256) void sup1_kernel(
    const float* __restrict__ p1_w, const float* __restrict__ p1_b)
{
    int lane = threadIdx.x & 31, wid = threadIdx.x >> 5;
    int w = blockIdx.x * 8 + wid;
    int r = w >> 9, u = w & (HID - 1);
    const float* wp = p1_w + (size_t)u * DM;
    const float* xp = g_sn + r * DM;
    float a = 0.f;
#pragma unroll
    for (int s = 0; s < 8; s++) a += wp[lane + 32 * s] * xp[lane + 32 * s];
    a = wred(a);
    if (lane == 0) g_shd[r * HID + u] = fmaxf(a + p1_b[u], 0.f);
}

__global__ __launch_bounds__(256) void sup2_kernel(
    const float* __restrict__ p2_w, const float* __restrict__ p2_b)
{
    int lane = threadIdx.x & 31, wid = threadIdx.x >> 5;
    int w = blockIdx.x * 8 + wid;
    int r = w >> 8, u = w & (DM - 1);
    const float* wp = p2_w + (size_t)u * HID;
    const float* xp = g_shd + r * HID;
    float a = 0.f;
#pragma unroll
    for (int s = 0; s < 16; s++) a += wp[lane + 32 * s] * xp[lane + 32 * s];
    a = wred(a);
    if (lane == 0) g_sz[r * DM + u] = a + p2_b[u] + g_sn[r * DM + u];
}

__global__ __launch_bounds__(256) void sup3_kernel(
    const float* __restrict__ ln_g, const float* __restrict__ ln_b)
{
    __shared__ float red[8];
    int tid = threadIdx.x, lane = tid & 31, wid = tid >> 5;
    float accg = 0.f;
    for (int r = 0; r < FEW; r++) {
        float z = g_sz[r * DM + tid];
        float s1 = wred(z);
        if (lane == 0) red[wid] = s1;
        __syncthreads();
        float mu = (red[0] + red[1] + red[2] + red[3] + red[4] + red[5] + red[6] + red[7]) * (1.f / DM);
        __syncthreads();
        float dz = z - mu;
        float s2 = wred(dz * dz);
        if (lane == 0) red[wid] = s2;
        __syncthreads();
        float sig = sqrtf((red[0] + red[1] + red[2] + red[3] + red[4] + red[5] + red[6] + red[7]) * (1.f / (DM - 1)));
        accg += dz / (sig + 1e-3f) * ln_g[tid] + ln_b[tid];
        __syncthreads();
    }
    float sg = accg * (1.f / FEW);
    g_sg[tid] = sg;
    float s3 = wred(sg * sg);
    if (lane == 0) red[wid] = s3;
    __syncthreads();
    float nrm = sqrtf(red[0] + red[1] + red[2] + red[3] + red[4] + red[5] + red[6] + red[7]);
    g_sgn[tid] = sg / fmaxf(nrm, 1e-12f);
}

__global__ __launch_bounds__(256) void vr_kernel(
    const float* __restrict__ w_hh,
    const float* __restrict__ b_ih, const float* __restrict__ b_hh)
{
    int lane = threadIdx.x & 31, wid = threadIdx.x >> 5;
    int n = blockIdx.x * 8 + wid;
    int p = nperm_src(n);
    const float* w = w_hh + (size_t)p * HID + DM;
    float a = 0.f;
#pragma unroll
    for (int s = 0; s < 8; s++) a += w[lane + 32 * s] * g_sg[lane + 32 * s];
    a = wred(a);
    if (lane == 0) {
        g_vr[n] = a;
        g_pb[n] = b_ih[p] + b_hh[p];
    }
}

__global__ __launch_bounds__(256) void ln_kernel(const float* __restrict__ ln_g,
                                                 const float* __restrict__ ln_b) {
    __shared__ float red[8];
    __shared__ float srow[DM];
    int row = blockIdx.x, tid = threadIdx.x, lane = tid & 31, wid = tid >> 5;
    float z = g_qg[(size_t)row * DM + tid];
    float s1 = wred(z);
    if (lane == 0) red[wid] = s1;
    __syncthreads();
    float mu = (red[0] + red[1] + red[2] + red[3] + red[4] + red[5] + red[6] + red[7]) * (1.f / DM);
    __syncthreads();
    float dz = z - mu;
    float s2 = wred(dz * dz);
    if (lane == 0) red[wid] = s2;
    __syncthreads();
    float sig = sqrtf((red[0] + red[1] + red[2] + red[3] + red[4] + red[5] + red[6] + red[7]) * (1.f / (DM - 1)));
    float o = dz / (sig + 1e-3f) * ln_g[tid] + ln_b[tid];
    g_qg[(size_t)row * DM + tid] = o;
    srow[tid] = o;
    __syncthreads();
    if (tid < 128) {
        u32 hi, lo;
        splitpack(srow[2 * tid], srow[2 * tid + 1], hi, lo);
        g_qghi[(size_t)row * 128 + tid] = hi;
        g_qglo[(size_t)row * 128 + tid] = lo;
    }
}

__global__ __launch_bounds__(256) void final_kernel(float* __restrict__ out) {
    int lane = threadIdx.x & 31, wid = threadIdx.x >> 5;
    int row = blockIdx.x * 8 + wid;
    const float* h = g_hb + (size_t)row * DM;
    float ss = 0.f, dt = 0.f;
#pragma unroll
    for (int s = 0; s < 8; s++) {
        float v = h[lane + 32 * s];
        ss += v * v;
        dt += v * g_sgn[lane + 32 * s];
    }
    ss = wred(ss); dt = wred(dt);
    if (lane == 0) out[row] = dt / fmaxf(sqrtf(ss), 1e-12f);
}

// ================= host =================
extern "C" void kernel_launch(void* const* d_in, const int* in_sizes, int n_in,
                              void* d_out, int out_size) {
    const int*   query   = (const int*)d_in[0];
    const int*   support = (const int*)d_in[1];
    const int*   qlc     = (const int*)d_in[2];
    const int*   qrc     = (const int*)d_in[4];
    const int*   slc     = (const int*)d_in[6];
    const int*   src_    = (const int*)d_in[8];
    const int*   knn     = (const int*)d_in[10];
    const float* emb     = (const float*)d_in[11];
    const float* gcn_w   = (const float*)d_in[12];
    const float* gcn_w_b = (const float*)d_in[13];
    const float* gcn_b   = (const float*)d_in[14];
    const float* gate_w  = (const float*)d_in[15];
    const float* gate_b  = (const float*)d_in[16];
    const float* p1_w    = (const float*)d_in[17];
    const float* p1_b    = (const float*)d_in[18];
    const float* p2_w    = (const float*)d_in[19];
    const float* p2_b    = (const float*)d_in[20];
    const float* ln_g    = (const float*)d_in[21];
    const float* ln_b    = (const float*)d_in[22];
    const float* w_ih    = (const float*)d_in[23];
    const float* w_hh    = (const float*)d_in[24];
    const float* b_ih    = (const float*)d_in[25];
    const float* b_hh    = (const float*)d_in[26];
    float* out = (float*)d_out;

    float *qn, *qg, *vr, *pb, *qp, *cst, *hb;
    u32 *wihh, *wihl, *whhh, *whhl, *qghi, *qglo, *hahi, *halo, *hbhi, *hblo;
    u32 *qnhi, *qnlo, *acthi, *actlo, *p1h, *p1l, *p2h, *p2l;
    cudaGetSymbolAddress((void**)&qn, g_qn);
    cudaGetSymbolAddress((void**)&qg, g_qg);
    cudaGetSymbolAddress((void**)&vr, g_vr);
    cudaGetSymbolAddress((void**)&pb, g_pb);
    cudaGetSymbolAddress((void**)&qp, g_qp);
    cudaGetSymbolAddress((void**)&cst, g_cst);
    cudaGetSymbolAddress((void**)&hb, g_hb);
    cudaGetSymbolAddress((void**)&wihh, g_wihh);
    cudaGetSymbolAddress((void**)&wihl, g_wihl);
    cudaGetSymbolAddress((void**)&whhh, g_whhh);
    cudaGetSymbolAddress((void**)&whhl, g_whhl);
    cudaGetSymbolAddress((void**)&qghi, g_qghi);
    cudaGetSymbolAddress((void**)&qglo, g_qglo);
    cudaGetSymbolAddress((void**)&hahi, g_hahi);
    cudaGetSymbolAddress((void**)&halo, g_halo);
    cudaGetSymbolAddress((void**)&hbhi, g_hbhi);
    cudaGetSymbolAddress((void**)&hblo, g_hblo);
    cudaGetSymbolAddress((void**)&qnhi, g_qnhi);
    cudaGetSymbolAddress((void**)&qnlo, g_qnlo);
    cudaGetSymbolAddress((void**)&acthi, g_acthi);
    cudaGetSymbolAddress((void**)&actlo, g_actlo);
    cudaGetSymbolAddress((void**)&p1h, g_p1h);
    cudaGetSymbolAddress((void**)&p1l, g_p1l);
    cudaGetSymbolAddress((void**)&p2h, g_p2h);
    cudaGetSymbolAddress((void**)&p2l, g_p2l);

    prep_all<<<2656, 256>>>(w_ih, w_hh, gcn_w, p1_w, p2_w);
    neigh_gather<<<NTASK, 256>>>(query, support, qlc, qrc, slc, src_, knn, emb);
    gcn_fused<<<TPAD / 128, 256>>>(gcn_w_b, gcn_b, gate_w, gate_b);
    sup1_kernel<<<FEW * HID / 8, 256>>>(p1_w, p1_b);
    sup2_kernel<<<FEW * DM / 8, 256>>>(p2_w, p2_b);
    sup3_kernel<<<1, 256>>>(ln_g, ln_b);
    vr_kernel<<<GATES / 8, 256>>>(w_hh, b_ih, b_hh);
    mma_gemm<1><<<dim3(4, Bq / 128), 256>>>(
        qnhi, qnlo, p1h, p1l, 256, 512, nullptr, acthi, actlo, p1_b, nullptr);
    mma_gemm<2><<<dim3(2, Bq / 128), 256>>>(
        acthi, actlo, p2h, p2l, 512, 256, qg, nullptr, nullptr, p2_b, qn);
    ln_kernel<<<Bq, 256>>>(ln_g, ln_b);
    lstm_mma<1, 0><<<dim3(16, 16), 256>>>(qghi, qglo, wihh, wihl, qp, pb, vr, cst, qg,
                                          hahi, halo, nullptr);
    lstm_mma<0, 0><<<dim3(16, 16), 256>>>(hahi, halo, whhh, whhl, qp, pb, vr, cst, qg,
                                          hbhi, hblo, nullptr);
    lstm_mma<0, 0><<<dim3(16, 16), 256>>>(hbhi, hblo, whhh, whhl, qp, pb, vr, cst, qg,
                                          hahi, halo, nullptr);
    lstm_mma<0, 1><<<dim3(16, 16), 256>>>(hahi, halo, whhh, whhl, qp, pb, vr, cst, qg,
                                          nullptr, nullptr, hb);
    final_kernel<<<Bq / 8, 256>>>(out);
}

// round 9
// speedup vs baseline: 1.7982x; 1.3829x over previous
#include <cuda_runtime.h>
#include <cuda_bf16.h>
#include <math.h>
#include <cstdint>

#define D     128
#define Mn    128
#define KTAB  64
#define KSEL  32
#define Bq    2048
#define FEW   5
#define DM    256
#define HID   512
#define NL    1024          // live LSTM gate columns (units 0..255 only)
#define NTASK (2 * Bq + 2 * FEW)
#define TPAD  4224
#define TQ    2176          // query rows + support rows padded to tile

typedef unsigned long long ull;
typedef unsigned int u32;

// ================= scratch =================
__device__ __align__(128) float g_qn[TQ * DM];
__device__ __align__(128) float g_qg[TQ * DM];
__device__ __align__(128) float g_sg[DM];
__device__ __align__(128) float g_sgn[DM];
__device__ __align__(128) float g_vr[NL];
__device__ __align__(128) float g_pb[NL];
__device__ __align__(128) float g_qp[(size_t)Bq * NL];
__device__ __align__(128) float g_cst[Bq * DM];
__device__ __align__(128) float g_hb[Bq * DM];
__device__ __align__(128) u32 g_hshi[TPAD * 128];
__device__ __align__(128) u32 g_hslo[TPAD * 128];
__device__ __align__(128) u32 g_hkhi[TPAD * 64];
__device__ __align__(128) u32 g_hklo[TPAD * 64];
__device__ __align__(128) u32 g_qnhi[TQ * 128];
__device__ __align__(128) u32 g_qnlo[TQ * 128];
__device__ __align__(128) u32 g_acthi[TQ * 256];
__device__ __align__(128) u32 g_actlo[TQ * 256];
__device__ __align__(128) u32 g_qghi[Bq * 128];
__device__ __align__(128) u32 g_qglo[Bq * 128];
__device__ __align__(128) u32 g_hahi[Bq * 128];
__device__ __align__(128) u32 g_halo[Bq * 128];
__device__ __align__(128) u32 g_hbhi[Bq * 128];
__device__ __align__(128) u32 g_hblo[Bq * 128];
__device__ __align__(128) u32 g_wihh[NL * 128];
__device__ __align__(128) u32 g_wihl[NL * 128];
__device__ __align__(128) u32 g_whhh[NL * 128];
__device__ __align__(128) u32 g_whhl[NL * 128];
__device__ __align__(128) u32 g_gwh[128 * 128];
__device__ __align__(128) u32 g_gwl[128 * 128];
__device__ __align__(128) u32 g_gkh[128 * 64];
__device__ __align__(128) u32 g_gkl[128 * 64];
__device__ __align__(128) u32 g_p1h[512 * 128];
__device__ __align__(128) u32 g_p1l[512 * 128];
__device__ __align__(128) u32 g_p2h[256 * 256];
__device__ __align__(128) u32 g_p2l[256 * 256];

__device__ __forceinline__ float wred(float v) {
#pragma unroll
    for (int o = 16; o; o >>= 1) v += __shfl_xor_sync(0xffffffffu, v, o);
    return v;
}
__device__ __forceinline__ float sigmf(float x) { return 1.f / (1.f + expf(-x)); }
__device__ __forceinline__ void splitpack(float a, float b, u32& hi, u32& lo) {
    __nv_bfloat16 ha = __float2bfloat16(a), hb2 = __float2bfloat16(b);
    __nv_bfloat16 la = __float2bfloat16(a - __bfloat162float(ha));
    __nv_bfloat16 lb = __float2bfloat16(b - __bfloat162float(hb2));
    __nv_bfloat162 H; H.x = ha; H.y = hb2;
    __nv_bfloat162 L; L.x = la; L.y = lb;
    hi = *(u32*)&H; lo = *(u32*)&L;
}
__device__ __forceinline__ int nperm_src(int n) {
    int b = n >> 4, r = n & 15;
    int v = (r & 7) >> 1;
    int g = (r >> 3) * 2 + (r & 1);
    return g * 512 + b * 4 + v;
}
__device__ __forceinline__ u32 smem_u32(const void* p) {
    u32 a;
    asm("{ .reg .u64 t; cvta.to.shared.u64 t, %1; cvt.u32.u64 %0, t; }" : "=r"(a) : "l"(p));
    return a;
}
__device__ __forceinline__ void ldm4(u32* r, u32 addr) {
    asm volatile("ldmatrix.sync.aligned.m8n8.x4.shared.b16 {%0,%1,%2,%3}, [%4];"
                 : "=r"(r[0]), "=r"(r[1]), "=r"(r[2]), "=r"(r[3]) : "r"(addr));
}
__device__ __forceinline__ void mma16816(float* d, const u32* a, const u32* b) {
    asm volatile("mma.sync.aligned.m16n8k16.row.col.f32.bf16.bf16.f32 "
                 "{%0,%1,%2,%3},{%4,%5,%6,%7},{%8,%9},{%0,%1,%2,%3};"
                 : "+f"(d[0]), "+f"(d[1]), "+f"(d[2]), "+f"(d[3])
                 : "r"(a[0]), "r"(a[1]), "r"(a[2]), "r"(a[3]), "r"(b[0]), "r"(b[1]));
}

// ================= neighbor gather =================
__global__ __launch_bounds__(256) void neigh_gather(
    const int* __restrict__ query, const int* __restrict__ support,
    const int* __restrict__ qlc, const int* __restrict__ qrc,
    const int* __restrict__ slc, const int* __restrict__ src_,
    const int* __restrict__ knn, const float* __restrict__ emb)
{
    __shared__ float s_center[D];
    __shared__ int   s_rid[Mn], s_eid[Mn];
    __shared__ float s_sim[Mn];
    __shared__ int   s_kid[KTAB];
    __shared__ float s_ksim[KTAB];
    __shared__ int   s_selr[KSEL], s_sele[KSEL], s_kselv[KSEL];
    __shared__ int   s_cnt, s_kcnt;
    __shared__ float s_cn;
    __shared__ float e_hs[DM];
    __shared__ float e_hk[D];

    int task = blockIdx.x;
    const int* conn; int id;
    if (task < 2 * Bq) {
        int row = task & (Bq - 1);
        int br  = task >> 11;
        conn = (br ? qrc : qlc) + (size_t)row * Mn * 2;
        id   = query[row * 2 + br];
    } else {
        int t = task - 2 * Bq;
        int br = t / FEW, row = t % FEW;
        conn = (br ? src_ : slc) + (size_t)row * Mn * 2;
        id   = support[row * 2 + br];
    }
    int tid = threadIdx.x, lane = tid & 31, wid = tid >> 5;
    if (tid == 0) { s_cnt = 0; s_kcnt = 0; }
    if (tid < D)  s_center[tid] = emb[(size_t)id * D + tid];
    if (tid < Mn) { s_rid[tid] = conn[tid * 2]; s_eid[tid] = conn[tid * 2 + 1]; }
    if (tid >= 192) s_kid[tid - 192] = knn[(size_t)id * KTAB + (tid - 192)];
    __syncthreads();

    if (wid == 0) {
        float c0 = s_center[lane], c1 = s_center[lane + 32],
              c2 = s_center[lane + 64], c3 = s_center[lane + 96];
        float s = wred(c0 * c0 + c1 * c1 + c2 * c2 + c3 * c3);
        if (lane == 0) s_cn = sqrtf(s);
    }
    __syncthreads();
    float cn = s_cn;
    float4 cv = ((const float4*)s_center)[lane];

#pragma unroll
    for (int g = 0; g < 4; g++) {
        int m = wid * 16 + g * 4;
        float dt[4], nn[4];
#pragma unroll
        for (int t = 0; t < 4; t++) {
            float4 ev = ((const float4*)(emb + (size_t)s_eid[m + t] * D))[lane];
            dt[t] = ev.x * cv.x + ev.y * cv.y + ev.z * cv.z + ev.w * cv.w;
            nn[t] = ev.x * ev.x + ev.y * ev.y + ev.z * ev.z + ev.w * ev.w;
        }
#pragma unroll
        for (int o = 16; o; o >>= 1) {
#pragma unroll
            for (int t = 0; t < 4; t++) {
                dt[t] += __shfl_xor_sync(0xffffffffu, dt[t], o);
                nn[t] += __shfl_xor_sync(0xffffffffu, nn[t], o);
            }
        }
        if (lane == 0) {
#pragma unroll
            for (int t = 0; t < 4; t++)
                s_sim[m + t] = dt[t] / fmaxf(cn * sqrtf(nn[t]), 1e-8f);
        }
    }
#pragma unroll
    for (int g = 0; g < 2; g++) {
        int m = wid * 8 + g * 4;
        float dt[4], nn[4];
#pragma unroll
        for (int t = 0; t < 4; t++) {
            float4 ev = ((const float4*)(emb + (size_t)s_kid[m + t] * D))[lane];
            dt[t] = ev.x * cv.x + ev.y * cv.y + ev.z * cv.z + ev.w * cv.w;
            nn[t] = ev.x * ev.x + ev.y * ev.y + ev.z * ev.z + ev.w * ev.w;
        }
#pragma unroll
        for (int o = 16; o; o >>= 1) {
#pragma unroll
            for (int t = 0; t < 4; t++) {
                dt[t] += __shfl_xor_sync(0xffffffffu, dt[t], o);
                nn[t] += __shfl_xor_sync(0xffffffffu, nn[t], o);
            }
        }
        if (lane == 0) {
#pragma unroll
            for (int t = 0; t < 4; t++)
                s_ksim[m + t] = dt[t] / fmaxf(cn * sqrtf(nn[t]), 1e-8f);
        }
    }
    __syncthreads();

    if (tid < Mn) {
        float v = s_sim[tid]; int r = 0;
        for (int j = 0; j < Mn; j++) {
            float u = s_sim[j];
            r += (u > v) || (u == v && j < tid);
        }
        if (r < KSEL) {
            int p = atomicAdd(&s_cnt, 1);
            s_selr[p] = s_rid[tid];
            s_sele[p] = s_eid[tid];
        }
    } else if (tid < Mn + KTAB) {
        int m = tid - Mn;
        float v = s_ksim[m]; int r = 0;
        for (int j = 0; j < KTAB; j++) {
            float u = s_ksim[j];
            r += (u > v) || (u == v && j < m);
        }
        if (r < KSEL) {
            int p = atomicAdd(&s_kcnt, 1);
            s_kselv[p] = s_kid[m];
        }
    }
    __syncthreads();

    int d = tid & (D - 1);
    float acc = 0.f;
    if (tid < D) {
#pragma unroll 8
        for (int i = 0; i < KSEL; i++) acc += emb[(size_t)s_selr[i] * D + d];
        e_hs[d] = acc * (1.f / KSEL);
        float ak = 0.f;
#pragma unroll 8
        for (int i = 0; i < KSEL; i++) ak += emb[(size_t)s_kselv[i] * D + d];
        e_hk[d] = ak * (1.f / KSEL);
    } else {
#pragma unroll 8
        for (int i = 0; i < KSEL; i++) acc += emb[(size_t)s_sele[i] * D + d];
        e_hs[D + d] = acc * (1.f / KSEL);
    }
    __syncthreads();
    if (tid < 128) {
        u32 hi, lo;
        splitpack(e_hs[2 * tid], e_hs[2 * tid + 1], hi, lo);
        g_hshi[(size_t)task * 128 + tid] = hi;
        g_hslo[(size_t)task * 128 + tid] = lo;
    } else if (tid < 192) {
        int t2 = tid - 128;
        u32 hi, lo;
        splitpack(e_hk[2 * t2], e_hk[2 * t2 + 1], hi, lo);
        g_hkhi[(size_t)task * 64 + t2] = hi;
        g_hklo[(size_t)task * 64 + t2] = lo;
    }
}

// ================= merged weight prep =================
__device__ __forceinline__ void prep_perm_body(int idx, const float* w, int ldw,
                                               u32* hi, u32* lo) {
    int n = idx >> 7, kp = idx & 127;
    int srow = nperm_src(n);
    float v0 = w[(size_t)srow * ldw + 2 * kp];
    float v1 = w[(size_t)srow * ldw + 2 * kp + 1];
    u32 h, l;
    splitpack(v0, v1, h, l);
    hi[idx] = h; lo[idx] = l;
}
__device__ __forceinline__ void split_body(int idx, const float* w, int ldw, int off,
                                           int khalf, u32* hi, u32* lo) {
    int n = idx / khalf, kp = idx % khalf;
    float v0 = w[(size_t)n * ldw + off + 2 * kp];
    float v1 = w[(size_t)n * ldw + off + 2 * kp + 1];
    u32 h, l;
    splitpack(v0, v1, h, l);
    hi[idx] = h; lo[idx] = l;
}
__global__ __launch_bounds__(256) void prep_all(
    const float* __restrict__ w_ih, const float* __restrict__ w_hh,
    const float* __restrict__ gcn_w, const float* __restrict__ p1_w,
    const float* __restrict__ p2_w)
{
    int b = blockIdx.x, tid = threadIdx.x;
    if (b < 512)        prep_perm_body(b * 256 + tid, w_ih, DM, g_wihh, g_wihl);
    else if (b < 1024)  prep_perm_body((b - 512) * 256 + tid, w_hh, HID, g_whhh, g_whhl);
    else if (b < 1088)  split_body((b - 1024) * 256 + tid, gcn_w, 256, 0, 128, g_gwh, g_gwl);
    else if (b < 1120)  split_body((b - 1088) * 256 + tid, gcn_w, 256, 128, 64, g_gkh, g_gkl);
    else if (b < 1376)  split_body((b - 1120) * 256 + tid, p1_w, 256, 0, 128, g_p1h, g_p1l);
    else                split_body((b - 1376) * 256 + tid, p2_w, 512, 0, 256, g_p2h, g_p2l);
}

// ================= pipelined mma mainloop =================
#define MMA_CHUNK(ACC, NCH) \
    for (int kc = 0; kc < (NCH); kc++) { \
        __syncthreads(); \
        *(uint4*)((char*)sAh + soff) = nah; \
        *(uint4*)((char*)sAl + soff) = nal; \
        *(uint4*)((char*)sWh + soff) = nwh; \
        *(uint4*)((char*)sWl + soff) = nwl; \
        __syncthreads(); \
        if (kc + 1 < (NCH)) { \
            nah = gAh[(kc + 1) * 2]; nal = gAl[(kc + 1) * 2]; \
            nwh = gWh[(kc + 1) * 2]; nwl = gWl[(kc + 1) * 2]; \
        } \
        u32 ah[2][4], al[2][4], wf[4][4]; \
        ldm4(ah[0], bAh + aoff[0]); ldm4(ah[1], bAh + aoff[1]); \
        ldm4(al[0], bAl + aoff[0]); ldm4(al[1], bAl + aoff[1]); \
        _Pragma("unroll") \
        for (int nf = 0; nf < 4; nf++) ldm4(wf[nf], bWh + boff[nf]); \
        _Pragma("unroll") \
        for (int mf = 0; mf < 2; mf++) \
            _Pragma("unroll") \
            for (int nf = 0; nf < 4; nf++) { \
                mma16816(ACC[mf][nf * 2],     ah[mf], wf[nf]); \
                mma16816(ACC[mf][nf * 2 + 1], ah[mf], wf[nf] + 2); \
                mma16816(ACC[mf][nf * 2],     al[mf], wf[nf]); \
                mma16816(ACC[mf][nf * 2 + 1], al[mf], wf[nf] + 2); \
            } \
        _Pragma("unroll") \
        for (int nf = 0; nf < 4; nf++) ldm4(wf[nf], bWl + boff[nf]); \
        _Pragma("unroll") \
        for (int mf = 0; mf < 2; mf++) \
            _Pragma("unroll") \
            for (int nf = 0; nf < 4; nf++) { \
                mma16816(ACC[mf][nf * 2],     ah[mf], wf[nf]); \
                mma16816(ACC[mf][nf * 2 + 1], ah[mf], wf[nf] + 2); \
            } \
    }

#define MMA_PROLOGUE() \
    int tid = threadIdx.x, lane = tid & 31, w = tid >> 5; \
    int wm = (w >> 1) * 32, wn = (w & 1) * 64; \
    int lrow = tid >> 1, lseg = tid & 1; \
    u32 soff = (u32)(lrow * 24 + lseg * 8) * 2; \
    u32 bAh = smem_u32(sAh), bAl = smem_u32(sAl), bWh = smem_u32(sWh), bWl = smem_u32(sWl); \
    u32 aoff[2]; \
    _Pragma("unroll") \
    for (int mf = 0; mf < 2; mf++) { \
        int row = wm + mf * 16 + (lane & 15); \
        int col = (lane >> 4) * 8; \
        aoff[mf] = (u32)(row * 24 + col) * 2; \
    } \
    u32 boff[4]; \
    _Pragma("unroll") \
    for (int nf = 0; nf < 4; nf++) { \
        int g = lane >> 3; \
        int row = wn + nf * 16 + (lane & 7) + (g >> 1) * 8; \
        int col = (g & 1) * 8; \
        boff[nf] = (u32)(row * 24 + col) * 2; \
    }

// ================= fused GCN dual GEMM + combine =================
__global__ __launch_bounds__(256) void gcn_fused(
    const float* __restrict__ gcn_w_b, const float* __restrict__ gcn_b,
    const float* __restrict__ gate_w, const float* __restrict__ gate_b)
{
    __shared__ __align__(16) __nv_bfloat16 sAh[128][24], sAl[128][24], sWh[128][24], sWl[128][24];
    __shared__ float s_part[16][32];
    MMA_PROLOGUE();
    int bm = blockIdx.x * 128;

    float acc1[2][8][4], acc2[2][8][4];
#pragma unroll
    for (int i = 0; i < 2; i++)
#pragma unroll
        for (int j = 0; j < 8; j++)
#pragma unroll
            for (int c = 0; c < 4; c++) { acc1[i][j][c] = 0.f; acc2[i][j][c] = 0.f; }

    {
        const uint4* gAh = (const uint4*)(g_hshi + (size_t)(bm + lrow) * 128) + lseg;
        const uint4* gAl = (const uint4*)(g_hslo + (size_t)(bm + lrow) * 128) + lseg;
        const uint4* gWh = (const uint4*)(g_gwh + (size_t)lrow * 128) + lseg;
        const uint4* gWl = (const uint4*)(g_gwl + (size_t)lrow * 128) + lseg;
        uint4 nah = gAh[0], nal = gAl[0], nwh = gWh[0], nwl = gWl[0];
        MMA_CHUNK(acc1, 16);
    }
    {
        const uint4* gAh = (const uint4*)(g_hkhi + (size_t)(bm + lrow) * 64) + lseg;
        const uint4* gAl = (const uint4*)(g_hklo + (size_t)(bm + lrow) * 64) + lseg;
        const uint4* gWh = (const uint4*)(g_gkh + (size_t)lrow * 64) + lseg;
        const uint4* gWl = (const uint4*)(g_gkl + (size_t)lrow * 64) + lseg;
        uint4 nah = gAh[0], nal = gAl[0], nwh = gWh[0], nwl = gWl[0];
        MMA_CHUNK(acc2, 8);
    }

    int q = lane & 3, r4 = lane >> 2;
    float part[2][2];
#pragma unroll
    for (int mf = 0; mf < 2; mf++)
#pragma unroll
        for (int rh = 0; rh < 2; rh++) part[mf][rh] = 0.f;
#pragma unroll
    for (int p = 0; p < 4; p++)
#pragma unroll
        for (int s = 0; s < 2; s++)
#pragma unroll
            for (int c = 0; c < 2; c++) {
                int col = wn + p * 16 + s * 8 + 2 * q + c;
                float wbgb = gcn_w_b[col] + gcn_b[col];
                float gws = gate_w[col], gwk = gate_w[D + col];
#pragma unroll
                for (int mf = 0; mf < 2; mf++)
#pragma unroll
                    for (int rh = 0; rh < 2; rh++) {
                        float sv = tanhf(acc1[mf][2 * p + s][rh * 2 + c] + wbgb);
                        float kv = tanhf(acc2[mf][2 * p + s][rh * 2 + c] + wbgb);
                        acc1[mf][2 * p + s][rh * 2 + c] = sv;
                        acc2[mf][2 * p + s][rh * 2 + c] = kv;
                        part[mf][rh] += gws * sv + gwk * kv;
                    }
            }
#pragma unroll
    for (int mf = 0; mf < 2; mf++)
#pragma unroll
        for (int rh = 0; rh < 2; rh++) {
            float v = part[mf][rh];
            v += __shfl_xor_sync(0xffffffffu, v, 1);
            v += __shfl_xor_sync(0xffffffffu, v, 2);
            part[mf][rh] = v;
        }
    if (q == 0) {
#pragma unroll
        for (int mf = 0; mf < 2; mf++)
#pragma unroll
            for (int rh = 0; rh < 2; rh++)
                s_part[w][mf * 16 + rh * 8 + r4] = part[mf][rh];
    }
    __syncthreads();
    float gb0 = gate_b[0];
#pragma unroll
    for (int mf = 0; mf < 2; mf++)
#pragma unroll
        for (int rh = 0; rh < 2; rh++) {
            int rl = mf * 16 + rh * 8 + r4;
            float tot = s_part[(w >> 1) * 2][rl] + s_part[(w >> 1) * 2 + 1][rl];
            float al = sigmf(tot + gb0);
            int t = bm + wm + mf * 16 + r4 + rh * 8;
            int rowq, half;
            if (t < 2 * Bq) { rowq = t & (Bq - 1); half = t >> 11; }
            else if (t < NTASK) { int t2 = t - 2 * Bq; rowq = Bq + t2 % FEW; half = t2 / FEW; }
            else continue;
#pragma unroll
            for (int p = 0; p < 4; p++)
#pragma unroll
                for (int s = 0; s < 2; s++) {
                    int col = wn + p * 16 + s * 8 + 2 * q;
                    float o0 = (1.f - al) * acc1[mf][2 * p + s][rh * 2]
                             + al * acc2[mf][2 * p + s][rh * 2];
                    float o1 = (1.f - al) * acc1[mf][2 * p + s][rh * 2 + 1]
                             + al * acc2[mf][2 * p + s][rh * 2 + 1];
                    int colq = half * 128 + col;
                    *(float2*)(g_qn + (size_t)rowq * DM + colq) = make_float2(o0, o1);
                    u32 h, l;
                    splitpack(o0, o1, h, l);
                    g_qnhi[(size_t)rowq * 128 + (colq >> 1)] = h;
                    g_qnlo[(size_t)rowq * 128 + (colq >> 1)] = l;
                }
        }
}

// ================= generic bf16-split mma GEMM =================
template<int MODE>
__global__ __launch_bounds__(256) void mma_gemm(
    const u32* __restrict__ ahi, const u32* __restrict__ alo,
    const u32* __restrict__ whi, const u32* __restrict__ wlo,
    int K, int N,
    float* __restrict__ Cf, u32* __restrict__ Chi, u32* __restrict__ Clo,
    const float* __restrict__ bias, const float* __restrict__ resid)
{
    int khalf = K >> 1;
    int nchunks = K >> 4;
    __shared__ __align__(16) __nv_bfloat16 sAh[128][24], sAl[128][24], sWh[128][24], sWl[128][24];
    MMA_PROLOGUE();
    int bm = blockIdx.y * 128, bn = blockIdx.x * 128;

    float acc[2][8][4];
#pragma unroll
    for (int i = 0; i < 2; i++)
#pragma unroll
        for (int j = 0; j < 8; j++)
#pragma unroll
            for (int c = 0; c < 4; c++) acc[i][j][c] = 0.f;

    const uint4* gAh = (const uint4*)(ahi + (size_t)(bm + lrow) * khalf) + lseg;
    const uint4* gAl = (const uint4*)(alo + (size_t)(bm + lrow) * khalf) + lseg;
    const uint4* gWh = (const uint4*)(whi + (size_t)(bn + lrow) * khalf) + lseg;
    const uint4* gWl = (const uint4*)(wlo + (size_t)(bn + lrow) * khalf) + lseg;
    uint4 nah = gAh[0], nal = gAl[0], nwh = gWh[0], nwl = gWl[0];
    MMA_CHUNK(acc, nchunks);

    int q = lane & 3, r4 = lane >> 2;
#pragma unroll
    for (int mf = 0; mf < 2; mf++)
#pragma unroll
        for (int p = 0; p < 4; p++)
#pragma unroll
            for (int s = 0; s < 2; s++) {
                int cb = bn + wn + p * 16 + s * 8 + 2 * q;
                float* A = acc[mf][2 * p + s];
#pragma unroll
                for (int rh = 0; rh < 2; rh++) {
                    size_t m = (size_t)(bm + wm + mf * 16 + r4 + rh * 8);
                    float v0 = A[rh * 2], v1 = A[rh * 2 + 1];
                    if (MODE == 1) {
                        v0 = fmaxf(v0 + bias[cb], 0.f);
                        v1 = fmaxf(v1 + bias[cb + 1], 0.f);
                        u32 h, l;
                        splitpack(v0, v1, h, l);
                        Chi[m * (N >> 1) + (cb >> 1)] = h;
                        Clo[m * (N >> 1) + (cb >> 1)] = l;
                    } else {
                        float2 r = *(const float2*)(resid + m * N + cb);
                        v0 += bias[cb] + r.x;
                        v1 += bias[cb + 1] + r.y;
                        *(float2*)(Cf + m * N + cb) = make_float2(v0, v1);
                    }
                }
            }
}

// ================= LSTM step (N=1024 live cols) =================
template<int FIRST, int LAST>
__global__ __launch_bounds__(256) void lstm_mma(
    const u32* __restrict__ ahi, const u32* __restrict__ alo,
    const u32* __restrict__ whi, const u32* __restrict__ wlo,
    float* __restrict__ qp, const float* __restrict__ pbias, const float* __restrict__ vr,
    float* __restrict__ cst, const float* __restrict__ qg,
    u32* __restrict__ ohi, u32* __restrict__ olo, float* __restrict__ of32)
{
    __shared__ __align__(16) __nv_bfloat16 sAh[128][24], sAl[128][24], sWh[128][24], sWl[128][24];
    MMA_PROLOGUE();
    int bm = blockIdx.y * 128, bn = blockIdx.x * 128;

    float acc[2][8][4];
#pragma unroll
    for (int i = 0; i < 2; i++)
#pragma unroll
        for (int j = 0; j < 8; j++)
#pragma unroll
            for (int c = 0; c < 4; c++) acc[i][j][c] = 0.f;

    const uint4* gAh = (const uint4*)(ahi + (size_t)(bm + lrow) * 128) + lseg;
    const uint4* gAl = (const uint4*)(alo + (size_t)(bm + lrow) * 128) + lseg;
    const uint4* gWh = (const uint4*)(whi + (size_t)(bn + lrow) * 128) + lseg;
    const uint4* gWl = (const uint4*)(wlo + (size_t)(bn + lrow) * 128) + lseg;
    uint4 nah = gAh[0], nal = gAl[0], nwh = gWh[0], nwl = gWl[0];
    MMA_CHUNK(acc, 16);

    int q = lane & 3, r4 = lane >> 2;
#pragma unroll
    for (int mf = 0; mf < 2; mf++) {
#pragma unroll
        for (int p = 0; p < 4; p++) {
            int nblk = bn + wn + p * 16;
            int u = (nblk >> 4) * 4 + q;
            int n0 = nblk + 2 * q;
            float* A0 = acc[mf][2 * p];
            float* A1 = acc[mf][2 * p + 1];
#pragma unroll
            for (int rh = 0; rh < 2; rh++) {
                size_t m = (size_t)(bm + wm + mf * 16 + r4 + rh * 8);
                float iv = A0[rh * 2], fv = A0[rh * 2 + 1];
                float gv = A1[rh * 2], ov = A1[rh * 2 + 1];
                if (FIRST) {
                    iv += pbias[n0];     fv += pbias[n0 + 1];
                    gv += pbias[n0 + 8]; ov += pbias[n0 + 9];
                    *(float2*)(qp + m * NL + n0)     = make_float2(iv, fv);
                    *(float2*)(qp + m * NL + n0 + 8) = make_float2(gv, ov);
                } else {
                    float2 q1 = *(const float2*)(qp + m * NL + n0);
                    float2 q2 = *(const float2*)(qp + m * NL + n0 + 8);
                    iv += q1.x + vr[n0];     fv += q1.y + vr[n0 + 1];
                    gv += q2.x + vr[n0 + 8]; ov += q2.y + vr[n0 + 9];
                }
                float cc;
                if (FIRST) cc = sigmf(iv) * tanhf(gv);
                else       cc = sigmf(fv) * cst[m * DM + u] + sigmf(iv) * tanhf(gv);
                cst[m * DM + u] = cc;
                float h = qg[m * DM + u] + sigmf(ov) * tanhf(cc);
                if (LAST) {
                    of32[m * DM + u] = h;
                } else {
                    __nv_bfloat16 hh = __float2bfloat16(h);
                    __nv_bfloat16 hl = __float2bfloat16(h - __bfloat162float(hh));
                    ((__nv_bfloat16*)ohi)[m * DM + u] = hh;
                    ((__nv_bfloat16*)olo)[m * DM + u] = hl;
                }
            }
        }
    }
}

// ================= support LN + mean + normalize (rows Bq..Bq+4 of qg) =================
__global__ __launch_bounds__(256) void sup3_kernel(
    const float* __restrict__ ln_g, const float* __restrict__ ln_b)
{
    __shared__ float red[8];
    int tid = threadIdx.x, lane = tid & 31, wid = tid >> 5;
    float accg = 0.f;
    for (int r = 0; r < FEW; r++) {
        float z = g_qg[(size_t)(Bq + r) * DM + tid];
        float s1 = wred(z);
        if (lane == 0) red[wid] = s1;
        __syncthreads();
        float mu = (red[0] + red[1] + red[2] + red[3] + red[4] + red[5] + red[6] + red[7]) * (1.f / DM);
        __syncthreads();
        float dz = z - mu;
        float s2 = wred(dz * dz);
        if (lane == 0) red[wid] = s2;
        __syncthreads();
        float sig = sqrtf((red[0] + red[1] + red[2] + red[3] + red[4] + red[5] + red[6] + red[7]) * (1.f / (DM - 1)));
        accg += dz / (sig + 1e-3f) * ln_g[tid] + ln_b[tid];
        __syncthreads();
    }
    float sg = accg * (1.f / FEW);
    g_sg[tid] = sg;
    float s3 = wred(sg * sg);
    if (lane == 0) red[wid] = s3;
    __syncthreads();
    float nrm = sqrtf(red[0] + red[1] + red[2] + red[3] + red[4] + red[5] + red[6] + red[7]);
    g_sgn[tid] = sg / fmaxf(nrm, 1e-12f);
}

// vr + bias (live cols only)
__global__ __launch_bounds__(256) void vr_kernel(
    const float* __restrict__ w_hh,
    const float* __restrict__ b_ih, const float* __restrict__ b_hh)
{
    int lane = threadIdx.x & 31, wid = threadIdx.x >> 5;
    int n = blockIdx.x * 8 + wid;
    int p = nperm_src(n);
    const float* w = w_hh + (size_t)p * HID + DM;
    float a = 0.f;
#pragma unroll
    for (int s = 0; s < 8; s++) a += w[lane + 32 * s] * g_sg[lane + 32 * s];
    a = wred(a);
    if (lane == 0) {
        g_vr[n] = a;
        g_pb[n] = b_ih[p] + b_hh[p];
    }
}

__global__ __launch_bounds__(256) void ln_kernel(const float* __restrict__ ln_g,
                                                 const float* __restrict__ ln_b) {
    __shared__ float red[8];
    __shared__ float srow[DM];
    int row = blockIdx.x, tid = threadIdx.x, lane = tid & 31, wid = tid >> 5;
    float z = g_qg[(size_t)row * DM + tid];
    float s1 = wred(z);
    if (lane == 0) red[wid] = s1;
    __syncthreads();
    float mu = (red[0] + red[1] + red[2] + red[3] + red[4] + red[5] + red[6] + red[7]) * (1.f / DM);
    __syncthreads();
    float dz = z - mu;
    float s2 = wred(dz * dz);
    if (lane == 0) red[wid] = s2;
    __syncthreads();
    float sig = sqrtf((red[0] + red[1] + red[2] + red[3] + red[4] + red[5] + red[6] + red[7]) * (1.f / (DM - 1)));
    float o = dz / (sig + 1e-3f) * ln_g[tid] + ln_b[tid];
    g_qg[(size_t)row * DM + tid] = o;
    srow[tid] = o;
    __syncthreads();
    if (tid < 128) {
        u32 hi, lo;
        splitpack(srow[2 * tid], srow[2 * tid + 1], hi, lo);
        g_qghi[(size_t)row * 128 + tid] = hi;
        g_qglo[(size_t)row * 128 + tid] = lo;
    }
}

__global__ __launch_bounds__(256) void final_kernel(float* __restrict__ out) {
    int lane = threadIdx.x & 31, wid = threadIdx.x >> 5;
    int row = blockIdx.x * 8 + wid;
    const float* h = g_hb + (size_t)row * DM;
    float ss = 0.f, dt = 0.f;
#pragma unroll
    for (int s = 0; s < 8; s++) {
        float v = h[lane + 32 * s];
        ss += v * v;
        dt += v * g_sgn[lane + 32 * s];
    }
    ss = wred(ss); dt = wred(dt);
    if (lane == 0) out[row] = dt / fmaxf(sqrtf(ss), 1e-12f);
}

// ================= host =================
extern "C" void kernel_launch(void* const* d_in, const int* in_sizes, int n_in,
                              void* d_out, int out_size) {
    const int*   query   = (const int*)d_in[0];
    const int*   support = (const int*)d_in[1];
    const int*   qlc     = (const int*)d_in[2];
    const int*   qrc     = (const int*)d_in[4];
    const int*   slc     = (const int*)d_in[6];
    const int*   src_    = (const int*)d_in[8];
    const int*   knn     = (const int*)d_in[10];
    const float* emb     = (const float*)d_in[11];
    const float* gcn_w   = (const float*)d_in[12];
    const float* gcn_w_b = (const float*)d_in[13];
    const float* gcn_b   = (const float*)d_in[14];
    const float* gate_w  = (const float*)d_in[15];
    const float* gate_b  = (const float*)d_in[16];
    const float* p1_w    = (const float*)d_in[17];
    const float* p1_b    = (const float*)d_in[18];
    const float* p2_w    = (const float*)d_in[19];
    const float* p2_b    = (const float*)d_in[20];
    const float* ln_g    = (const float*)d_in[21];
    const float* ln_b    = (const float*)d_in[22];
    const float* w_ih    = (const float*)d_in[23];
    const float* w_hh    = (const float*)d_in[24];
    const float* b_ih    = (const float*)d_in[25];
    const float* b_hh    = (const float*)d_in[26];
    float* out = (float*)d_out;

    float *qn, *qg, *vr, *pb, *qp, *cst, *hb;
    u32 *wihh, *wihl, *whhh, *whhl, *qghi, *qglo, *hahi, *halo, *hbhi, *hblo;
    u32 *qnhi, *qnlo, *acthi, *actlo, *p1h, *p1l, *p2h, *p2l;
    cudaGetSymbolAddress((void**)&qn, g_qn);
    cudaGetSymbolAddress((void**)&qg, g_qg);
    cudaGetSymbolAddress((void**)&vr, g_vr);
    cudaGetSymbolAddress((void**)&pb, g_pb);
    cudaGetSymbolAddress((void**)&qp, g_qp);
    cudaGetSymbolAddress((void**)&cst, g_cst);
    cudaGetSymbolAddress((void**)&hb, g_hb);
    cudaGetSymbolAddress((void**)&wihh, g_wihh);
    cudaGetSymbolAddress((void**)&wihl, g_wihl);
    cudaGetSymbolAddress((void**)&whhh, g_whhh);
    cudaGetSymbolAddress((void**)&whhl, g_whhl);
    cudaGetSymbolAddress((void**)&qghi, g_qghi);
    cudaGetSymbolAddress((void**)&qglo, g_qglo);
    cudaGetSymbolAddress((void**)&hahi, g_hahi);
    cudaGetSymbolAddress((void**)&halo, g_halo);
    cudaGetSymbolAddress((void**)&hbhi, g_hbhi);
    cudaGetSymbolAddress((void**)&hblo, g_hblo);
    cudaGetSymbolAddress((void**)&qnhi, g_qnhi);
    cudaGetSymbolAddress((void**)&qnlo, g_qnlo);
    cudaGetSymbolAddress((void**)&acthi, g_acthi);
    cudaGetSymbolAddress((void**)&actlo, g_actlo);
    cudaGetSymbolAddress((void**)&p1h, g_p1h);
    cudaGetSymbolAddress((void**)&p1l, g_p1l);
    cudaGetSymbolAddress((void**)&p2h, g_p2h);
    cudaGetSymbolAddress((void**)&p2l, g_p2l);

    prep_all<<<1632, 256>>>(w_ih, w_hh, gcn_w, p1_w, p2_w);
    neigh_gather<<<NTASK, 256>>>(query, support, qlc, qrc, slc, src_, knn, emb);
    gcn_fused<<<TPAD / 128, 256>>>(gcn_w_b, gcn_b, gate_w, gate_b);
    // query+support encoder: M=2176 batch
    mma_gemm<1><<<dim3(4, TQ / 128), 256>>>(
        qnhi, qnlo, p1h, p1l, 256, 512, nullptr, acthi, actlo, p1_b, nullptr);
    mma_gemm<2><<<dim3(2, TQ / 128), 256>>>(
        acthi, actlo, p2h, p2l, 512, 256, qg, nullptr, nullptr, p2_b, qn);
    sup3_kernel<<<1, 256>>>(ln_g, ln_b);
    vr_kernel<<<NL / 8, 256>>>(w_hh, b_ih, b_hh);
    ln_kernel<<<Bq, 256>>>(ln_g, ln_b);
    lstm_mma<1, 0><<<dim3(8, 16), 256>>>(qghi, qglo, wihh, wihl, qp, pb, vr, cst, qg,
                                         hahi, halo, nullptr);
    lstm_mma<0, 0><<<dim3(8, 16), 256>>>(hahi, halo, whhh, whhl, qp, pb, vr, cst, qg,
                                         hbhi, hblo, nullptr);
    lstm_mma<0, 0><<<dim3(8, 16), 256>>>(hbhi, hblo, whhh, whhl, qp, pb, vr, cst, qg,
                                         hahi, halo, nullptr);
    lstm_mma<0, 1><<<dim3(8, 16), 256>>>(hahi, halo, whhh, whhl, qp, pb, vr, cst, qg,
                                         nullptr, nullptr, hb);
    final_kernel<<<Bq / 8, 256>>>(out);
}

// round 10
// speedup vs baseline: 2.0288x; 1.1282x over previous
#include <cuda_runtime.h>
#include <cuda_bf16.h>
#include <math.h>
#include <cstdint>

#define D     128
#define Mn    128
#define KTAB  64
#define KSEL  32
#define Bq    2048
#define FEW   5
#define DM    256
#define HID   512
#define NL    1024
#define NTASK (2 * Bq + 2 * FEW)
#define TPAD  4224
#define TQ    2176

typedef unsigned long long ull;
typedef unsigned int u32;

// ================= scratch =================
__device__ __align__(128) float g_qn[TQ * DM];
__device__ __align__(128) float g_qg[TQ * DM];
__device__ __align__(128) float g_sg[DM];
__device__ __align__(128) float g_sgn[DM];
__device__ __align__(128) float g_vr[NL];
__device__ __align__(128) float g_pb[NL];
__device__ __align__(128) float g_qp[(size_t)Bq * NL];
__device__ __align__(128) float g_cst[Bq * DM];
__device__ __align__(128) float g_hb[Bq * DM];
__device__ __align__(128) u32 g_hshi[TPAD * 128];
__device__ __align__(128) u32 g_hslo[TPAD * 128];
__device__ __align__(128) u32 g_hkhi[TPAD * 64];
__device__ __align__(128) u32 g_hklo[TPAD * 64];
__device__ __align__(128) u32 g_qnhi[TQ * 128];
__device__ __align__(128) u32 g_qnlo[TQ * 128];
__device__ __align__(128) u32 g_acthi[TQ * 256];
__device__ __align__(128) u32 g_actlo[TQ * 256];
__device__ __align__(128) u32 g_qghi[Bq * 128];
__device__ __align__(128) u32 g_qglo[Bq * 128];
__device__ __align__(128) u32 g_hahi[Bq * 128];
__device__ __align__(128) u32 g_halo[Bq * 128];
__device__ __align__(128) u32 g_hbhi[Bq * 128];
__device__ __align__(128) u32 g_hblo[Bq * 128];
__device__ __align__(128) u32 g_wihh[NL * 128];
__device__ __align__(128) u32 g_wihl[NL * 128];
__device__ __align__(128) u32 g_whhh[NL * 128];
__device__ __align__(128) u32 g_whhl[NL * 128];
__device__ __align__(128) u32 g_gwh[128 * 128];
__device__ __align__(128) u32 g_gwl[128 * 128];
__device__ __align__(128) u32 g_gkh[128 * 64];
__device__ __align__(128) u32 g_gkl[128 * 64];
__device__ __align__(128) u32 g_p1h[512 * 128];
__device__ __align__(128) u32 g_p1l[512 * 128];
__device__ __align__(128) u32 g_p2h[256 * 256];
__device__ __align__(128) u32 g_p2l[256 * 256];

__device__ __forceinline__ float wred(float v) {
#pragma unroll
    for (int o = 16; o; o >>= 1) v += __shfl_xor_sync(0xffffffffu, v, o);
    return v;
}
__device__ __forceinline__ float sigmf(float x) { return 1.f / (1.f + expf(-x)); }
__device__ __forceinline__ void splitpack(float a, float b, u32& hi, u32& lo) {
    __nv_bfloat16 ha = __float2bfloat16(a), hb2 = __float2bfloat16(b);
    __nv_bfloat16 la = __float2bfloat16(a - __bfloat162float(ha));
    __nv_bfloat16 lb = __float2bfloat16(b - __bfloat162float(hb2));
    __nv_bfloat162 H; H.x = ha; H.y = hb2;
    __nv_bfloat162 L; L.x = la; L.y = lb;
    hi = *(u32*)&H; lo = *(u32*)&L;
}
__device__ __forceinline__ int nperm_src(int n) {
    int b = n >> 4, r = n & 15;
    int v = (r & 7) >> 1;
    int g = (r >> 3) * 2 + (r & 1);
    return g * 512 + b * 4 + v;
}
__device__ __forceinline__ u32 smem_u32(const void* p) {
    u32 a;
    asm("{ .reg .u64 t; cvta.to.shared.u64 t, %1; cvt.u32.u64 %0, t; }" : "=r"(a) : "l"(p));
    return a;
}
__device__ __forceinline__ void ldm4(u32* r, u32 addr) {
    asm volatile("ldmatrix.sync.aligned.m8n8.x4.shared.b16 {%0,%1,%2,%3}, [%4];"
                 : "=r"(r[0]), "=r"(r[1]), "=r"(r[2]), "=r"(r[3]) : "r"(addr));
}
__device__ __forceinline__ void mma16816(float* d, const u32* a, const u32* b) {
    asm volatile("mma.sync.aligned.m16n8k16.row.col.f32.bf16.bf16.f32 "
                 "{%0,%1,%2,%3},{%4,%5,%6,%7},{%8,%9},{%0,%1,%2,%3};"
                 : "+f"(d[0]), "+f"(d[1]), "+f"(d[2]), "+f"(d[3])
                 : "r"(a[0]), "r"(a[1]), "r"(a[2]), "r"(a[3]), "r"(b[0]), "r"(b[1]));
}

// ================= neighbor gather =================
__global__ __launch_bounds__(256) void neigh_gather(
    const int* __restrict__ query, const int* __restrict__ support,
    const int* __restrict__ qlc, const int* __restrict__ qrc,
    const int* __restrict__ slc, const int* __restrict__ src_,
    const int* __restrict__ knn, const float* __restrict__ emb)
{
    __shared__ float s_center[D];
    __shared__ int   s_rid[Mn], s_eid[Mn];
    __shared__ float s_sim[Mn];
    __shared__ int   s_kid[KTAB];
    __shared__ float s_ksim[KTAB];
    __shared__ int   s_selr[KSEL], s_sele[KSEL], s_kselv[KSEL];
    __shared__ int   s_cnt, s_kcnt;
    __shared__ float s_cn;
    __shared__ float e_hs[DM];
    __shared__ float e_hk[D];

    int task = blockIdx.x;
    const int* conn; int id;
    if (task < 2 * Bq) {
        int row = task & (Bq - 1);
        int br  = task >> 11;
        conn = (br ? qrc : qlc) + (size_t)row * Mn * 2;
        id   = query[row * 2 + br];
    } else {
        int t = task - 2 * Bq;
        int br = t / FEW, row = t % FEW;
        conn = (br ? src_ : slc) + (size_t)row * Mn * 2;
        id   = support[row * 2 + br];
    }
    int tid = threadIdx.x, lane = tid & 31, wid = tid >> 5;
    if (tid == 0) { s_cnt = 0; s_kcnt = 0; }
    if (tid < D)  s_center[tid] = emb[(size_t)id * D + tid];
    if (tid < Mn) { s_rid[tid] = conn[tid * 2]; s_eid[tid] = conn[tid * 2 + 1]; }
    if (tid >= 192) s_kid[tid - 192] = knn[(size_t)id * KTAB + (tid - 192)];
    __syncthreads();

    if (wid == 0) {
        float c0 = s_center[lane], c1 = s_center[lane + 32],
              c2 = s_center[lane + 64], c3 = s_center[lane + 96];
        float s = wred(c0 * c0 + c1 * c1 + c2 * c2 + c3 * c3);
        if (lane == 0) s_cn = sqrtf(s);
    }
    __syncthreads();
    float cn = s_cn;
    float4 cv = ((const float4*)s_center)[lane];

#pragma unroll
    for (int g = 0; g < 4; g++) {
        int m = wid * 16 + g * 4;
        float dt[4], nn[4];
#pragma unroll
        for (int t = 0; t < 4; t++) {
            float4 ev = ((const float4*)(emb + (size_t)s_eid[m + t] * D))[lane];
            dt[t] = ev.x * cv.x + ev.y * cv.y + ev.z * cv.z + ev.w * cv.w;
            nn[t] = ev.x * ev.x + ev.y * ev.y + ev.z * ev.z + ev.w * ev.w;
        }
#pragma unroll
        for (int o = 16; o; o >>= 1) {
#pragma unroll
            for (int t = 0; t < 4; t++) {
                dt[t] += __shfl_xor_sync(0xffffffffu, dt[t], o);
                nn[t] += __shfl_xor_sync(0xffffffffu, nn[t], o);
            }
        }
        if (lane == 0) {
#pragma unroll
            for (int t = 0; t < 4; t++)
                s_sim[m + t] = dt[t] / fmaxf(cn * sqrtf(nn[t]), 1e-8f);
        }
    }
#pragma unroll
    for (int g = 0; g < 2; g++) {
        int m = wid * 8 + g * 4;
        float dt[4], nn[4];
#pragma unroll
        for (int t = 0; t < 4; t++) {
            float4 ev = ((const float4*)(emb + (size_t)s_kid[m + t] * D))[lane];
            dt[t] = ev.x * cv.x + ev.y * cv.y + ev.z * cv.z + ev.w * cv.w;
            nn[t] = ev.x * ev.x + ev.y * ev.y + ev.z * ev.z + ev.w * ev.w;
        }
#pragma unroll
        for (int o = 16; o; o >>= 1) {
#pragma unroll
            for (int t = 0; t < 4; t++) {
                dt[t] += __shfl_xor_sync(0xffffffffu, dt[t], o);
                nn[t] += __shfl_xor_sync(0xffffffffu, nn[t], o);
            }
        }
        if (lane == 0) {
#pragma unroll
            for (int t = 0; t < 4; t++)
                s_ksim[m + t] = dt[t] / fmaxf(cn * sqrtf(nn[t]), 1e-8f);
        }
    }
    __syncthreads();

    if (tid < Mn) {
        float v = s_sim[tid]; int r = 0;
        for (int j = 0; j < Mn; j++) {
            float u = s_sim[j];
            r += (u > v) || (u == v && j < tid);
        }
        if (r < KSEL) {
            int p = atomicAdd(&s_cnt, 1);
            s_selr[p] = s_rid[tid];
            s_sele[p] = s_eid[tid];
        }
    } else if (tid < Mn + KTAB) {
        int m = tid - Mn;
        float v = s_ksim[m]; int r = 0;
        for (int j = 0; j < KTAB; j++) {
            float u = s_ksim[j];
            r += (u > v) || (u == v && j < m);
        }
        if (r < KSEL) {
            int p = atomicAdd(&s_kcnt, 1);
            s_kselv[p] = s_kid[m];
        }
    }
    __syncthreads();

    int d = tid & (D - 1);
    float acc = 0.f;
    if (tid < D) {
#pragma unroll 8
        for (int i = 0; i < KSEL; i++) acc += emb[(size_t)s_selr[i] * D + d];
        e_hs[d] = acc * (1.f / KSEL);
        float ak = 0.f;
#pragma unroll 8
        for (int i = 0; i < KSEL; i++) ak += emb[(size_t)s_kselv[i] * D + d];
        e_hk[d] = ak * (1.f / KSEL);
    } else {
#pragma unroll 8
        for (int i = 0; i < KSEL; i++) acc += emb[(size_t)s_sele[i] * D + d];
        e_hs[D + d] = acc * (1.f / KSEL);
    }
    __syncthreads();
    if (tid < 128) {
        u32 hi, lo;
        splitpack(e_hs[2 * tid], e_hs[2 * tid + 1], hi, lo);
        g_hshi[(size_t)task * 128 + tid] = hi;
        g_hslo[(size_t)task * 128 + tid] = lo;
    } else if (tid < 192) {
        int t2 = tid - 128;
        u32 hi, lo;
        splitpack(e_hk[2 * t2], e_hk[2 * t2 + 1], hi, lo);
        g_hkhi[(size_t)task * 64 + t2] = hi;
        g_hklo[(size_t)task * 64 + t2] = lo;
    }
}

// ================= merged weight prep =================
__device__ __forceinline__ void prep_perm_body(int idx, const float* w, int ldw,
                                               u32* hi, u32* lo) {
    int n = idx >> 7, kp = idx & 127;
    int srow = nperm_src(n);
    float v0 = w[(size_t)srow * ldw + 2 * kp];
    float v1 = w[(size_t)srow * ldw + 2 * kp + 1];
    u32 h, l;
    splitpack(v0, v1, h, l);
    hi[idx] = h; lo[idx] = l;
}
__device__ __forceinline__ void split_body(int idx, const float* w, int ldw, int off,
                                           int khalf, u32* hi, u32* lo) {
    int n = idx / khalf, kp = idx % khalf;
    float v0 = w[(size_t)n * ldw + off + 2 * kp];
    float v1 = w[(size_t)n * ldw + off + 2 * kp + 1];
    u32 h, l;
    splitpack(v0, v1, h, l);
    hi[idx] = h; lo[idx] = l;
}
__global__ __launch_bounds__(256) void prep_all(
    const float* __restrict__ w_ih, const float* __restrict__ w_hh,
    const float* __restrict__ gcn_w, const float* __restrict__ p1_w,
    const float* __restrict__ p2_w)
{
    int b = blockIdx.x, tid = threadIdx.x;
    if (b < 512)        prep_perm_body(b * 256 + tid, w_ih, DM, g_wihh, g_wihl);
    else if (b < 1024)  prep_perm_body((b - 512) * 256 + tid, w_hh, HID, g_whhh, g_whhl);
    else if (b < 1088)  split_body((b - 1024) * 256 + tid, gcn_w, 256, 0, 128, g_gwh, g_gwl);
    else if (b < 1120)  split_body((b - 1088) * 256 + tid, gcn_w, 256, 128, 64, g_gkh, g_gkl);
    else if (b < 1376)  split_body((b - 1120) * 256 + tid, p1_w, 256, 0, 128, g_p1h, g_p1l);
    else                split_body((b - 1376) * 256 + tid, p2_w, 512, 0, 256, g_p2h, g_p2l);
}

// ================= pipelined mma mainloop (MF = m-tiles of 16 per warp row-group) =================
// A tile = 64*MF rows; W tile = 128 rows. For MF=1 only threads <128 stage A.
#define MMA_CHUNK(ACC, NCH, MF) \
    for (int kc = 0; kc < (NCH); kc++) { \
        __syncthreads(); \
        if (MF == 2 || tid < 128) { \
            *(uint4*)((char*)sAh + soffA) = nah; \
            *(uint4*)((char*)sAl + soffA) = nal; \
        } \
        *(uint4*)((char*)sWh + soffW) = nwh; \
        *(uint4*)((char*)sWl + soffW) = nwl; \
        __syncthreads(); \
        if (kc + 1 < (NCH)) { \
            if (MF == 2 || tid < 128) { nah = gAh[(kc + 1) * 2]; nal = gAl[(kc + 1) * 2]; } \
            nwh = gWh[(kc + 1) * 2]; nwl = gWl[(kc + 1) * 2]; \
        } \
        u32 ah[MF][4], al[MF][4], wf[4][4]; \
        _Pragma("unroll") \
        for (int mf = 0; mf < MF; mf++) { ldm4(ah[mf], bAh + aoff[mf]); ldm4(al[mf], bAl + aoff[mf]); } \
        _Pragma("unroll") \
        for (int nf = 0; nf < 4; nf++) ldm4(wf[nf], bWh + boff[nf]); \
        _Pragma("unroll") \
        for (int mf = 0; mf < MF; mf++) \
            _Pragma("unroll") \
            for (int nf = 0; nf < 4; nf++) { \
                mma16816(ACC[mf][nf * 2],     ah[mf], wf[nf]); \
                mma16816(ACC[mf][nf * 2 + 1], ah[mf], wf[nf] + 2); \
                mma16816(ACC[mf][nf * 2],     al[mf], wf[nf]); \
                mma16816(ACC[mf][nf * 2 + 1], al[mf], wf[nf] + 2); \
            } \
        _Pragma("unroll") \
        for (int nf = 0; nf < 4; nf++) ldm4(wf[nf], bWl + boff[nf]); \
        _Pragma("unroll") \
        for (int mf = 0; mf < MF; mf++) \
            _Pragma("unroll") \
            for (int nf = 0; nf < 4; nf++) { \
                mma16816(ACC[mf][nf * 2],     ah[mf], wf[nf]); \
                mma16816(ACC[mf][nf * 2 + 1], ah[mf], wf[nf] + 2); \
            } \
    }

#define MMA_PROLOGUE(MF) \
    int tid = threadIdx.x, lane = tid & 31, w = tid >> 5; \
    int wm = (w >> 1) * 16 * MF, wn = (w & 1) * 64; \
    int lrowW = tid >> 1, lsegW = tid & 1; \
    int lrowA = (MF == 2) ? (tid >> 1) : ((tid & 127) >> 1); \
    int lsegA = tid & 1; \
    u32 soffW = (u32)(lrowW * 24 + lsegW * 8) * 2; \
    u32 soffA = (u32)(lrowA * 24 + lsegA * 8) * 2; \
    u32 bAh = smem_u32(sAh), bAl = smem_u32(sAl), bWh = smem_u32(sWh), bWl = smem_u32(sWl); \
    u32 aoff[MF]; \
    _Pragma("unroll") \
    for (int mf = 0; mf < MF; mf++) { \
        int row = wm + mf * 16 + (lane & 15); \
        int col = (lane >> 4) * 8; \
        aoff[mf] = (u32)(row * 24 + col) * 2; \
    } \
    u32 boff[4]; \
    _Pragma("unroll") \
    for (int nf = 0; nf < 4; nf++) { \
        int g = lane >> 3; \
        int row = wn + nf * 16 + (lane & 7) + (g >> 1) * 8; \
        int col = (g & 1) * 8; \
        boff[nf] = (u32)(row * 24 + col) * 2; \
    }

// ================= fused GCN dual GEMM + combine (MF=1, 64-row tiles) =================
__global__ __launch_bounds__(256) void gcn_fused(
    const float* __restrict__ gcn_w_b, const float* __restrict__ gcn_b,
    const float* __restrict__ gate_w, const float* __restrict__ gate_b)
{
    __shared__ __align__(16) __nv_bfloat16 sAh[64][24], sAl[64][24], sWh[128][24], sWl[128][24];
    __shared__ float s_part[16][16];
    MMA_PROLOGUE(1);
    int bm = blockIdx.x * 64;

    float acc1[1][8][4], acc2[1][8][4];
#pragma unroll
    for (int j = 0; j < 8; j++)
#pragma unroll
        for (int c = 0; c < 4; c++) { acc1[0][j][c] = 0.f; acc2[0][j][c] = 0.f; }

    {
        const uint4* gAh = (const uint4*)(g_hshi + (size_t)(bm + lrowA) * 128) + lsegA;
        const uint4* gAl = (const uint4*)(g_hslo + (size_t)(bm + lrowA) * 128) + lsegA;
        const uint4* gWh = (const uint4*)(g_gwh + (size_t)lrowW * 128) + lsegW;
        const uint4* gWl = (const uint4*)(g_gwl + (size_t)lrowW * 128) + lsegW;
        uint4 nah, nal;
        if (tid < 128) { nah = gAh[0]; nal = gAl[0]; }
        uint4 nwh = gWh[0], nwl = gWl[0];
        MMA_CHUNK(acc1, 16, 1);
    }
    {
        const uint4* gAh = (const uint4*)(g_hkhi + (size_t)(bm + lrowA) * 64) + lsegA;
        const uint4* gAl = (const uint4*)(g_hklo + (size_t)(bm + lrowA) * 64) + lsegA;
        const uint4* gWh = (const uint4*)(g_gkh + (size_t)lrowW * 64) + lsegW;
        const uint4* gWl = (const uint4*)(g_gkl + (size_t)lrowW * 64) + lsegW;
        uint4 nah, nal;
        if (tid < 128) { nah = gAh[0]; nal = gAl[0]; }
        uint4 nwh = gWh[0], nwl = gWl[0];
        MMA_CHUNK(acc2, 8, 1);
    }

    int q = lane & 3, r4 = lane >> 2;
    float part[2] = {0.f, 0.f};
#pragma unroll
    for (int p = 0; p < 4; p++)
#pragma unroll
        for (int s = 0; s < 2; s++)
#pragma unroll
            for (int c = 0; c < 2; c++) {
                int col = wn + p * 16 + s * 8 + 2 * q + c;
                float wbgb = gcn_w_b[col] + gcn_b[col];
                float gws = gate_w[col], gwk = gate_w[D + col];
#pragma unroll
                for (int rh = 0; rh < 2; rh++) {
                    float sv = tanhf(acc1[0][2 * p + s][rh * 2 + c] + wbgb);
                    float kv = tanhf(acc2[0][2 * p + s][rh * 2 + c] + wbgb);
                    acc1[0][2 * p + s][rh * 2 + c] = sv;
                    acc2[0][2 * p + s][rh * 2 + c] = kv;
                    part[rh] += gws * sv + gwk * kv;
                }
            }
#pragma unroll
    for (int rh = 0; rh < 2; rh++) {
        float v = part[rh];
        v += __shfl_xor_sync(0xffffffffu, v, 1);
        v += __shfl_xor_sync(0xffffffffu, v, 2);
        part[rh] = v;
    }
    if (q == 0) {
#pragma unroll
        for (int rh = 0; rh < 2; rh++)
            s_part[w][rh * 8 + r4] = part[rh];
    }
    __syncthreads();
    float gb0 = gate_b[0];
#pragma unroll
    for (int rh = 0; rh < 2; rh++) {
        int rl = rh * 8 + r4;
        float tot = s_part[(w >> 1) * 2][rl] + s_part[(w >> 1) * 2 + 1][rl];
        float al = sigmf(tot + gb0);
        int t = bm + wm + r4 + rh * 8;
        int rowq, half;
        if (t < 2 * Bq) { rowq = t & (Bq - 1); half = t >> 11; }
        else if (t < NTASK) { int t2 = t - 2 * Bq; rowq = Bq + t2 % FEW; half = t2 / FEW; }
        else continue;
#pragma unroll
        for (int p = 0; p < 4; p++)
#pragma unroll
            for (int s = 0; s < 2; s++) {
                int col = wn + p * 16 + s * 8 + 2 * q;
                float o0 = (1.f - al) * acc1[0][2 * p + s][rh * 2]
                         + al * acc2[0][2 * p + s][rh * 2];
                float o1 = (1.f - al) * acc1[0][2 * p + s][rh * 2 + 1]
                         + al * acc2[0][2 * p + s][rh * 2 + 1];
                int colq = half * 128 + col;
                *(float2*)(g_qn + (size_t)rowq * DM + colq) = make_float2(o0, o1);
                u32 h, l;
                splitpack(o0, o1, h, l);
                g_qnhi[(size_t)rowq * 128 + (colq >> 1)] = h;
                g_qnlo[(size_t)rowq * 128 + (colq >> 1)] = l;
            }
    }
}

// ================= generic bf16-split mma GEMM (MF=1, 64-row tiles) =================
template<int MODE>
__global__ __launch_bounds__(256) void mma_gemm(
    const u32* __restrict__ ahi, const u32* __restrict__ alo,
    const u32* __restrict__ whi, const u32* __restrict__ wlo,
    int K, int N,
    float* __restrict__ Cf, u32* __restrict__ Chi, u32* __restrict__ Clo,
    const float* __restrict__ bias, const float* __restrict__ resid)
{
    int khalf = K >> 1;
    int nchunks = K >> 4;
    __shared__ __align__(16) __nv_bfloat16 sAh[64][24], sAl[64][24], sWh[128][24], sWl[128][24];
    MMA_PROLOGUE(1);
    int bm = blockIdx.y * 64, bn = blockIdx.x * 128;

    float acc[1][8][4];
#pragma unroll
    for (int j = 0; j < 8; j++)
#pragma unroll
        for (int c = 0; c < 4; c++) acc[0][j][c] = 0.f;

    const uint4* gAh = (const uint4*)(ahi + (size_t)(bm + lrowA) * khalf) + lsegA;
    const uint4* gAl = (const uint4*)(alo + (size_t)(bm + lrowA) * khalf) + lsegA;
    const uint4* gWh = (const uint4*)(whi + (size_t)(bn + lrowW) * khalf) + lsegW;
    const uint4* gWl = (const uint4*)(wlo + (size_t)(bn + lrowW) * khalf) + lsegW;
    uint4 nah, nal;
    if (tid < 128) { nah = gAh[0]; nal = gAl[0]; }
    uint4 nwh = gWh[0], nwl = gWl[0];
    MMA_CHUNK(acc, nchunks, 1);

    int q = lane & 3, r4 = lane >> 2;
#pragma unroll
    for (int p = 0; p < 4; p++)
#pragma unroll
        for (int s = 0; s < 2; s++) {
            int cb = bn + wn + p * 16 + s * 8 + 2 * q;
            float* A = acc[0][2 * p + s];
#pragma unroll
            for (int rh = 0; rh < 2; rh++) {
                size_t m = (size_t)(bm + wm + r4 + rh * 8);
                float v0 = A[rh * 2], v1 = A[rh * 2 + 1];
                if (MODE == 1) {
                    v0 = fmaxf(v0 + bias[cb], 0.f);
                    v1 = fmaxf(v1 + bias[cb + 1], 0.f);
                    u32 h, l;
                    splitpack(v0, v1, h, l);
                    Chi[m * (N >> 1) + (cb >> 1)] = h;
                    Clo[m * (N >> 1) + (cb >> 1)] = l;
                } else {
                    float2 r = *(const float2*)(resid + m * N + cb);
                    v0 += bias[cb] + r.x;
                    v1 += bias[cb + 1] + r.y;
                    *(float2*)(Cf + m * N + cb) = make_float2(v0, v1);
                }
            }
        }
}

// ================= LSTM step (MF=2, 128-row tiles; N=1024 live cols) =================
template<int FIRST, int LAST>
__global__ __launch_bounds__(256) void lstm_mma(
    const u32* __restrict__ ahi, const u32* __restrict__ alo,
    const u32* __restrict__ whi, const u32* __restrict__ wlo,
    float* __restrict__ qp, const float* __restrict__ pbias, const float* __restrict__ vr,
    float* __restrict__ cst, const float* __restrict__ qg,
    u32* __restrict__ ohi, u32* __restrict__ olo, float* __restrict__ of32)
{
    __shared__ __align__(16) __nv_bfloat16 sAh[128][24], sAl[128][24], sWh[128][24], sWl[128][24];
    MMA_PROLOGUE(2);
    int bm = blockIdx.y * 128, bn = blockIdx.x * 128;

    float acc[2][8][4];
#pragma unroll
    for (int i = 0; i < 2; i++)
#pragma unroll
        for (int j = 0; j < 8; j++)
#pragma unroll
            for (int c = 0; c < 4; c++) acc[i][j][c] = 0.f;

    const uint4* gAh = (const uint4*)(ahi + (size_t)(bm + lrowA) * 128) + lsegA;
    const uint4* gAl = (const uint4*)(alo + (size_t)(bm + lrowA) * 128) + lsegA;
    const uint4* gWh = (const uint4*)(whi + (size_t)(bn + lrowW) * 128) + lsegW;
    const uint4* gWl = (const uint4*)(wlo + (size_t)(bn + lrowW) * 128) + lsegW;
    uint4 nah = gAh[0], nal = gAl[0], nwh = gWh[0], nwl = gWl[0];
    MMA_CHUNK(acc, 16, 2);

    int q = lane & 3, r4 = lane >> 2;
#pragma unroll
    for (int mf = 0; mf < 2; mf++) {
#pragma unroll
        for (int p = 0; p < 4; p++) {
            int nblk = bn + wn + p * 16;
            int u = (nblk >> 4) * 4 + q;
            int n0 = nblk + 2 * q;
            float* A0 = acc[mf][2 * p];
            float* A1 = acc[mf][2 * p + 1];
#pragma unroll
            for (int rh = 0; rh < 2; rh++) {
                size_t m = (size_t)(bm + wm + mf * 16 + r4 + rh * 8);
                float iv = A0[rh * 2], fv = A0[rh * 2 + 1];
                float gv = A1[rh * 2], ov = A1[rh * 2 + 1];
                if (FIRST) {
                    iv += pbias[n0];     fv += pbias[n0 + 1];
                    gv += pbias[n0 + 8]; ov += pbias[n0 + 9];
                    *(float2*)(qp + m * NL + n0)     = make_float2(iv, fv);
                    *(float2*)(qp + m * NL + n0 + 8) = make_float2(gv, ov);
                } else {
                    float2 q1 = *(const float2*)(qp + m * NL + n0);
                    float2 q2 = *(const float2*)(qp + m * NL + n0 + 8);
                    iv += q1.x + vr[n0];     fv += q1.y + vr[n0 + 1];
                    gv += q2.x + vr[n0 + 8]; ov += q2.y + vr[n0 + 9];
                }
                float cc;
                if (FIRST) cc = sigmf(iv) * tanhf(gv);
                else       cc = sigmf(fv) * cst[m * DM + u] + sigmf(iv) * tanhf(gv);
                cst[m * DM + u] = cc;
                float h = qg[m * DM + u] + sigmf(ov) * tanhf(cc);
                if (LAST) {
                    of32[m * DM + u] = h;
                } else {
                    __nv_bfloat16 hh = __float2bfloat16(h);
                    __nv_bfloat16 hl = __float2bfloat16(h - __bfloat162float(hh));
                    ((__nv_bfloat16*)ohi)[m * DM + u] = hh;
                    ((__nv_bfloat16*)olo)[m * DM + u] = hl;
                }
            }
        }
    }
}

// ================= support LN + mean + normalize =================
__global__ __launch_bounds__(256) void sup3_kernel(
    const float* __restrict__ ln_g, const float* __restrict__ ln_b)
{
    __shared__ float red[8];
    int tid = threadIdx.x, lane = tid & 31, wid = tid >> 5;
    float accg = 0.f;
    for (int r = 0; r < FEW; r++) {
        float z = g_qg[(size_t)(Bq + r) * DM + tid];
        float s1 = wred(z);
        if (lane == 0) red[wid] = s1;
        __syncthreads();
        float mu = (red[0] + red[1] + red[2] + red[3] + red[4] + red[5] + red[6] + red[7]) * (1.f / DM);
        __syncthreads();
        float dz = z - mu;
        float s2 = wred(dz * dz);
        if (lane == 0) red[wid] = s2;
        __syncthreads();
        float sig = sqrtf((red[0] + red[1] + red[2] + red[3] + red[4] + red[5] + red[6] + red[7]) * (1.f / (DM - 1)));
        accg += dz / (sig + 1e-3f) * ln_g[tid] + ln_b[tid];
        __syncthreads();
    }
    float sg = accg * (1.f / FEW);
    g_sg[tid] = sg;
    float s3 = wred(sg * sg);
    if (lane == 0) red[wid] = s3;
    __syncthreads();
    float nrm = sqrtf(red[0] + red[1] + red[2] + red[3] + red[4] + red[5] + red[6] + red[7]);
    g_sgn[tid] = sg / fmaxf(nrm, 1e-12f);
}

__global__ __launch_bounds__(256) void vr_kernel(
    const float* __restrict__ w_hh,
    const float* __restrict__ b_ih, const float* __restrict__ b_hh)
{
    int lane = threadIdx.x & 31, wid = threadIdx.x >> 5;
    int n = blockIdx.x * 8 + wid;
    int p = nperm_src(n);
    const float* w = w_hh + (size_t)p * HID + DM;
    float a = 0.f;
#pragma unroll
    for (int s = 0; s < 8; s++) a += w[lane + 32 * s] * g_sg[lane + 32 * s];
    a = wred(a);
    if (lane == 0) {
        g_vr[n] = a;
        g_pb[n] = b_ih[p] + b_hh[p];
    }
}

__global__ __launch_bounds__(256) void ln_kernel(const float* __restrict__ ln_g,
                                                 const float* __restrict__ ln_b) {
    __shared__ float red[8];
    __shared__ float srow[DM];
    int row = blockIdx.x, tid = threadIdx.x, lane = tid & 31, wid = tid >> 5;
    float z = g_qg[(size_t)row * DM + tid];
    float s1 = wred(z);
    if (lane == 0) red[wid] = s1;
    __syncthreads();
    float mu = (red[0] + red[1] + red[2] + red[3] + red[4] + red[5] + red[6] + red[7]) * (1.f / DM);
    __syncthreads();
    float dz = z - mu;
    float s2 = wred(dz * dz);
    if (lane == 0) red[wid] = s2;
    __syncthreads();
    float sig = sqrtf((red[0] + red[1] + red[2] + red[3] + red[4] + red[5] + red[6] + red[7]) * (1.f / (DM - 1)));
    float o = dz / (sig + 1e-3f) * ln_g[tid] + ln_b[tid];
    g_qg[(size_t)row * DM + tid] = o;
    srow[tid] = o;
    __syncthreads();
    if (tid < 128) {
        u32 hi, lo;
        splitpack(srow[2 * tid], srow[2 * tid + 1], hi, lo);
        g_qghi[(size_t)row * 128 + tid] = hi;
        g_qglo[(size_t)row * 128 + tid] = lo;
    }
}

__global__ __launch_bounds__(256) void final_kernel(float* __restrict__ out) {
    int lane = threadIdx.x & 31, wid = threadIdx.x >> 5;
    int row = blockIdx.x * 8 + wid;
    const float* h = g_hb + (size_t)row * DM;
    float ss = 0.f, dt = 0.f;
#pragma unroll
    for (int s = 0; s < 8; s++) {
        float v = h[lane + 32 * s];
        ss += v * v;
        dt += v * g_sgn[lane + 32 * s];
    }
    ss = wred(ss); dt = wred(dt);
    if (lane == 0) out[row] = dt / fmaxf(sqrtf(ss), 1e-12f);
}

// ================= host =================
extern "C" void kernel_launch(void* const* d_in, const int* in_sizes, int n_in,
                              void* d_out, int out_size) {
    const int*   query   = (const int*)d_in[0];
    const int*   support = (const int*)d_in[1];
    const int*   qlc     = (const int*)d_in[2];
    const int*   qrc     = (const int*)d_in[4];
    const int*   slc     = (const int*)d_in[6];
    const int*   src_    = (const int*)d_in[8];
    const int*   knn     = (const int*)d_in[10];
    const float* emb     = (const float*)d_in[11];
    const float* gcn_w   = (const float*)d_in[12];
    const float* gcn_w_b = (const float*)d_in[13];
    const float* gcn_b   = (const float*)d_in[14];
    const float* gate_w  = (const float*)d_in[15];
    const float* gate_b  = (const float*)d_in[16];
    const float* p1_w    = (const float*)d_in[17];
    const float* p1_b    = (const float*)d_in[18];
    const float* p2_w    = (const float*)d_in[19];
    const float* p2_b    = (const float*)d_in[20];
    const float* ln_g    = (const float*)d_in[21];
    const float* ln_b    = (const float*)d_in[22];
    const float* w_ih    = (const float*)d_in[23];
    const float* w_hh    = (const float*)d_in[24];
    const float* b_ih    = (const float*)d_in[25];
    const float* b_hh    = (const float*)d_in[26];
    float* out = (float*)d_out;

    float *qg, *vr, *pb, *qp, *cst, *hb, *qn;
    u32 *wihh, *wihl, *whhh, *whhl, *qghi, *qglo, *hahi, *halo, *hbhi, *hblo;
    u32 *qnhi, *qnlo, *acthi, *actlo, *p1h, *p1l, *p2h, *p2l;
    cudaGetSymbolAddress((void**)&qn, g_qn);
    cudaGetSymbolAddress((void**)&qg, g_qg);
    cudaGetSymbolAddress((void**)&vr, g_vr);
    cudaGetSymbolAddress((void**)&pb, g_pb);
    cudaGetSymbolAddress((void**)&qp, g_qp);
    cudaGetSymbolAddress((void**)&cst, g_cst);
    cudaGetSymbolAddress((void**)&hb, g_hb);
    cudaGetSymbolAddress((void**)&wihh, g_wihh);
    cudaGetSymbolAddress((void**)&wihl, g_wihl);
    cudaGetSymbolAddress((void**)&whhh, g_whhh);
    cudaGetSymbolAddress((void**)&whhl, g_whhl);
    cudaGetSymbolAddress((void**)&qghi, g_qghi);
    cudaGetSymbolAddress((void**)&qglo, g_qglo);
    cudaGetSymbolAddress((void**)&hahi, g_hahi);
    cudaGetSymbolAddress((void**)&halo, g_halo);
    cudaGetSymbolAddress((void**)&hbhi, g_hbhi);
    cudaGetSymbolAddress((void**)&hblo, g_hblo);
    cudaGetSymbolAddress((void**)&qnhi, g_qnhi);
    cudaGetSymbolAddress((void**)&qnlo, g_qnlo);
    cudaGetSymbolAddress((void**)&acthi, g_acthi);
    cudaGetSymbolAddress((void**)&actlo, g_actlo);
    cudaGetSymbolAddress((void**)&p1h, g_p1h);
    cudaGetSymbolAddress((void**)&p1l, g_p1l);
    cudaGetSymbolAddress((void**)&p2h, g_p2h);
    cudaGetSymbolAddress((void**)&p2l, g_p2l);

    prep_all<<<1632, 256>>>(w_ih, w_hh, gcn_w, p1_w, p2_w);
    neigh_gather<<<NTASK, 256>>>(query, support, qlc, qrc, slc, src_, knn, emb);
    gcn_fused<<<TPAD / 64, 256>>>(gcn_w_b, gcn_b, gate_w, gate_b);
    mma_gemm<1><<<dim3(4, TQ / 64), 256>>>(
        qnhi, qnlo, p1h, p1l, 256, 512, nullptr, acthi, actlo, p1_b, nullptr);
    mma_gemm<2><<<dim3(2, TQ / 64), 256>>>(
        acthi, actlo, p2h, p2l, 512, 256, qg, nullptr, nullptr, p2_b, qn);
    sup3_kernel<<<1, 256>>>(ln_g, ln_b);
    vr_kernel<<<NL / 8, 256>>>(w_hh, b_ih, b_hh);
    ln_kernel<<<Bq, 256>>>(ln_g, ln_b);
    lstm_mma<1, 0><<<dim3(8, 16), 256>>>(qghi, qglo, wihh, wihl, qp, pb, vr, cst, qg,
                                         hahi, halo, nullptr);
    lstm_mma<0, 0><<<dim3(8, 16), 256>>>(hahi, halo, whhh, whhl, qp, pb, vr, cst, qg,
                                         hbhi, hblo, nullptr);
    lstm_mma<0, 0><<<dim3(8, 16), 256>>>(hbhi, hblo, whhh, whhl, qp, pb, vr, cst, qg,
                                         hahi, halo, nullptr);
    lstm_mma<0, 1><<<dim3(8, 16), 256>>>(hahi, halo, whhh, whhl, qp, pb, vr, cst, qg,
                                         nullptr, nullptr, hb);
    final_kernel<<<Bq / 8, 256>>>(out);
}